// round 3
// baseline (speedup 1.0000x reference)
#include <cuda_runtime.h>
#include <cstddef>

// Problem constants
#define Bn   256
#define Tn   512
#define Dn   64
#define Hn   512
#define G4H  2048   // 4*H
#define FCn  512
#define OUTn 8

#define STEP_BLOCKS 128   // (16 h-tiles) x (8 m-tiles); <= 148 SMs -> co-resident

// ---------------- scratch (device globals; no runtime allocation) ----------
__device__ float g_xg[(size_t)Bn * Tn * G4H];   // gate pre-activations (reused by both layers)
__device__ float g_h0all[(size_t)Bn * Tn * Hn]; // layer-0 hidden states for all t
__device__ float g_hA[Bn * Hn];
__device__ float g_hB[Bn * Hn];
__device__ float g_z[Bn * FCn];

// ---------------- software grid barrier (generation based, replay-safe) ----
__device__ unsigned g_bar_count = 0;
__device__ unsigned g_bar_gen   = 0;

__device__ __forceinline__ void grid_barrier(unsigned nblocks) {
    __syncthreads();
    __threadfence();
    if (threadIdx.x == 0) {
        unsigned gen = atomicAdd(&g_bar_gen, 0u);          // read current generation
        unsigned arrived = atomicAdd(&g_bar_count, 1u);
        if (arrived == nblocks - 1u) {
            atomicExch(&g_bar_count, 0u);
            __threadfence();
            atomicExch(&g_bar_gen, gen + 1u);
        } else {
            while (atomicAdd(&g_bar_gen, 0u) == gen) { __nanosleep(64); }
        }
    }
    __syncthreads();
}

// ---------------- generic tiled GEMM: C = A @ W^T + b1 (+ b2) (+relu) ------
// A: [M,K] row-major, W: [N,K] row-major, C: [M,N]. 64|M, 64|N, 16|K.
__global__ void gemm_bias_kernel(const float* __restrict__ A,
                                 const float* __restrict__ W,
                                 const float* __restrict__ b1,
                                 const float* __restrict__ b2,
                                 float* __restrict__ C,
                                 int M, int N, int K, int relu)
{
    __shared__ float As[64][17];
    __shared__ float Bs[64][17];
    const int m0 = blockIdx.y * 64;
    const int n0 = blockIdx.x * 64;
    const int tid = threadIdx.x;
    const int tx = tid & 15;
    const int ty = tid >> 4;

    float acc[4][4];
#pragma unroll
    for (int i = 0; i < 4; i++)
#pragma unroll
        for (int j = 0; j < 4; j++) acc[i][j] = 0.f;

    // 64x16 tile = 256 float4s = exactly one per thread
    const int lr = tid >> 2;          // 0..63 row
    const int lq = tid & 3;           // 0..3 float4-chunk (16 cols)

    for (int k0 = 0; k0 < K; k0 += 16) {
        float4 va = *(const float4*)(A + (size_t)(m0 + lr) * K + k0 + lq * 4);
        As[lr][lq*4+0] = va.x; As[lr][lq*4+1] = va.y; As[lr][lq*4+2] = va.z; As[lr][lq*4+3] = va.w;
        float4 vw = *(const float4*)(W + (size_t)(n0 + lr) * K + k0 + lq * 4);
        Bs[lr][lq*4+0] = vw.x; Bs[lr][lq*4+1] = vw.y; Bs[lr][lq*4+2] = vw.z; Bs[lr][lq*4+3] = vw.w;
        __syncthreads();
#pragma unroll
        for (int k = 0; k < 16; k++) {
            float a[4], w[4];
#pragma unroll
            for (int i = 0; i < 4; i++) a[i] = As[ty + 16 * i][k];
#pragma unroll
            for (int j = 0; j < 4; j++) w[j] = Bs[tx + 16 * j][k];
#pragma unroll
            for (int i = 0; i < 4; i++)
#pragma unroll
                for (int j = 0; j < 4; j++) acc[i][j] += a[i] * w[j];
        }
        __syncthreads();
    }

#pragma unroll
    for (int i = 0; i < 4; i++) {
        int row = m0 + ty + 16 * i;
#pragma unroll
        for (int j = 0; j < 4; j++) {
            int col = n0 + tx + 16 * j;
            float v = acc[i][j] + b1[col];
            if (b2) v += b2[col];
            if (relu) v = fmaxf(v, 0.f);
            C[(size_t)row * N + col] = v;
        }
    }
}

// ---------------- persistent LSTM layer kernel ------------------------------
// Runs all Tn timesteps. Grid (16, 8): 32 hidden units x 32 batch rows per
// block, all 4 gates. Cell state lives in registers (block owns its cells).
// Cross-step h exchange: write plain STG, read __ldcg (L1 is not coherent).
__global__ void lstm_layer_kernel(const float* __restrict__ xg,   // [B, T, 4H]
                                  const float* __restrict__ Whh,  // [4H, H]
                                  float* __restrict__ hA,
                                  float* __restrict__ hB,
                                  float* __restrict__ h_all)      // [B, T, H] or null
{
    __shared__ float As[32][17];
    __shared__ float Ws[128][17];
    const int h0 = blockIdx.x * 32;
    const int m0 = blockIdx.y * 32;
    const int tid = threadIdx.x;
    const int tx = tid & 31;          // hidden unit within tile
    const int ty = tid >> 5;          // 0..7 row group
    const int u = h0 + tx;

    float creg[4];
#pragma unroll
    for (int i = 0; i < 4; i++) creg[i] = 0.f;

    for (int t = 0; t < Tn; t++) {
        const float* h_in = (t & 1) ? hB : hA;
        float* h_out      = (t & 1) ? hA : hB;

        float acc[4][4];
#pragma unroll
        for (int i = 0; i < 4; i++)
#pragma unroll
            for (int g = 0; g < 4; g++) acc[i][g] = 0.f;

        if (t > 0) {
            for (int k0 = 0; k0 < Hn; k0 += 16) {
                // As: 32x16 tile of h_in = 128 float4s (L2 path: written by
                // other SMs last step)
                if (tid < 128) {
                    int r = tid >> 2, q = tid & 3;
                    float4 v = __ldcg((const float4*)(h_in + (m0 + r) * Hn + k0 + q * 4));
                    As[r][q*4+0] = v.x; As[r][q*4+1] = v.y; As[r][q*4+2] = v.z; As[r][q*4+3] = v.w;
                }
                // Ws: 128x16 tile of Whh = 512 float4s (2 per thread);
                // read-only -> default L1 path, hot across steps
#pragma unroll
                for (int i = 0; i < 2; i++) {
                    int idx = tid + i * 256;
                    int r = idx >> 2, q = idx & 3;
                    int g = r >> 5, hh = r & 31;
                    float4 v = *(const float4*)(Whh + (size_t)((g << 9) + h0 + hh) * Hn + k0 + q * 4);
                    Ws[r][q*4+0] = v.x; Ws[r][q*4+1] = v.y; Ws[r][q*4+2] = v.z; Ws[r][q*4+3] = v.w;
                }
                __syncthreads();
#pragma unroll
                for (int k = 0; k < 16; k++) {
                    float a[4], w[4];
#pragma unroll
                    for (int i = 0; i < 4; i++) a[i] = As[ty + 8 * i][k];
#pragma unroll
                    for (int g = 0; g < 4; g++) w[g] = Ws[g * 32 + tx][k];
#pragma unroll
                    for (int i = 0; i < 4; i++)
#pragma unroll
                        for (int g = 0; g < 4; g++) acc[i][g] += a[i] * w[g];
                }
                __syncthreads();
            }
        }

#pragma unroll
        for (int i = 0; i < 4; i++) {
            int row = m0 + ty + 8 * i;                       // batch index
            const float* xr = xg + ((size_t)row * Tn + t) * G4H;
            float gi = acc[i][0] + __ldcg(xr + u);
            float gf = acc[i][1] + __ldcg(xr + 512 + u);
            float gg = acc[i][2] + __ldcg(xr + 1024 + u);
            float go = acc[i][3] + __ldcg(xr + 1536 + u);
            float si = 1.f / (1.f + expf(-gi));
            float sf = 1.f / (1.f + expf(-gf));
            float so = 1.f / (1.f + expf(-go));
            float tg = tanhf(gg);
            float cn = sf * creg[i] + si * tg;               // t==0: creg==0
            creg[i] = cn;
            float hn = so * tanhf(cn);
            h_out[row * Hn + u] = hn;
            if (h_all) h_all[((size_t)row * Tn + t) * Hn + u] = hn;
        }

        if (t < Tn - 1) grid_barrier(STEP_BLOCKS);
    }
}

// ---------------- FC2: out[256,8] = z @ W_fc2^T + b ------------------------
__global__ void fc2_kernel(const float* __restrict__ z,
                           const float* __restrict__ W,
                           const float* __restrict__ b,
                           float* __restrict__ out)
{
    int row = blockIdx.x;       // 0..255
    int o = threadIdx.y;        // 0..7
    int lane = threadIdx.x;     // 0..31
    float s = 0.f;
    const float* zr = z + (size_t)row * FCn;
    const float* wr = W + (size_t)o * FCn;
    for (int k = lane; k < FCn; k += 32) s += zr[k] * wr[k];
#pragma unroll
    for (int off = 16; off; off >>= 1) s += __shfl_down_sync(0xffffffffu, s, off);
    if (lane == 0) out[row * OUTn + o] = s + b[o];
}

// ---------------- host orchestration ---------------------------------------
extern "C" void kernel_launch(void* const* d_in, const int* in_sizes, int n_in,
                              void* d_out, int out_size)
{
    const float* x      = (const float*)d_in[0];
    const float* W_ih0  = (const float*)d_in[1];
    const float* W_hh0  = (const float*)d_in[2];
    const float* b_ih0  = (const float*)d_in[3];
    const float* b_hh0  = (const float*)d_in[4];
    const float* W_ih1  = (const float*)d_in[5];
    const float* W_hh1  = (const float*)d_in[6];
    const float* b_ih1  = (const float*)d_in[7];
    const float* b_hh1  = (const float*)d_in[8];
    const float* W_fc1  = (const float*)d_in[9];
    const float* b_fc1  = (const float*)d_in[10];
    const float* W_fc2  = (const float*)d_in[11];
    const float* b_fc2  = (const float*)d_in[12];
    float* out = (float*)d_out;

    float *xg, *h0all, *hA, *hB, *z;
    cudaGetSymbolAddress((void**)&xg,    g_xg);
    cudaGetSymbolAddress((void**)&h0all, g_h0all);
    cudaGetSymbolAddress((void**)&hA,    g_hA);
    cudaGetSymbolAddress((void**)&hB,    g_hB);
    cudaGetSymbolAddress((void**)&z,     g_z);

    const int MT = Bn * Tn;               // 131072
    dim3 gemmGrid(G4H / 64, MT / 64);     // (32, 2048)
    dim3 stepGrid(Hn / 32, Bn / 32);      // (16, 8) = 128 blocks, all co-resident

    // ---- Layer 0 ----
    // xg = x @ W_ih0^T + b_ih0 + b_hh0   (M=131072, N=2048, K=64)
    gemm_bias_kernel<<<gemmGrid, 256>>>(x, W_ih0, b_ih0, b_hh0, xg, MT, G4H, Dn, 0);
    lstm_layer_kernel<<<stepGrid, 256>>>(xg, W_hh0, hA, hB, h0all);

    // ---- Layer 1 ----
    // xg = h0all @ W_ih1^T + b_ih1 + b_hh1   (M=131072, N=2048, K=512)
    gemm_bias_kernel<<<gemmGrid, 256>>>(h0all, W_ih1, b_ih1, b_hh1, xg, MT, G4H, Hn, 0);
    lstm_layer_kernel<<<stepGrid, 256>>>(xg, W_hh1, hA, hB, (float*)0);
    // T=512 even -> final h lives in hA

    // ---- FC head ----
    dim3 fc1Grid(FCn / 64, Bn / 64);      // (8, 4)
    gemm_bias_kernel<<<fc1Grid, 256>>>(hA, W_fc1, b_fc1, (const float*)0, z, Bn, FCn, Hn, 1);
    fc2_kernel<<<Bn, dim3(32, 8)>>>(z, W_fc2, b_fc2, out);
}

// round 4
// speedup vs baseline: 1.5625x; 1.5625x over previous
#include <cuda_runtime.h>
#include <cstddef>

// Problem constants
#define Bn   256
#define Tn   512
#define Dn   64
#define Hn   512
#define G4H  2048   // 4*H
#define FCn  512
#define OUTn 8

#define STEP_BLOCKS 128   // (16 u-tiles) x (8 m-tiles); <= 148 SMs -> co-resident
#define KC   32           // k-chunk in step kernel
#define GKC  32           // k-chunk in gemm kernel

typedef unsigned long long ull;

// ---------------- scratch (device globals; no runtime allocation) ----------
__device__ float g_xg[(size_t)Bn * Tn * G4H];   // gate pre-activations (reused by both layers)
__device__ float g_h0all[(size_t)Bn * Tn * Hn]; // layer-0 hidden states for all t
__device__ float g_hA[Bn * Hn];
__device__ float g_hB[Bn * Hn];
__device__ float g_z[Bn * FCn];
// packed recurrent weights: [layer][u_tile(16)][k(512)][u(32)] float4 = {Wi,Wf,Wg,Wo}
__device__ float4 g_Wq[2][16 * 512 * 32];

// ---------------- f32x2 packed helpers -------------------------------------
__device__ __forceinline__ void ffma2(ull& d, ull a, ull b) {
    asm("fma.rn.f32x2 %0, %1, %2, %0;" : "+l"(d) : "l"(a), "l"(b));
}
__device__ __forceinline__ ull pack2dup(float x) {
    ull r; asm("mov.b64 %0, {%1, %1};" : "=l"(r) : "f"(x)); return r;
}
__device__ __forceinline__ float2 unpack2(ull v) {
    float2 f; asm("mov.b64 {%0, %1}, %2;" : "=f"(f.x), "=f"(f.y) : "l"(v)); return f;
}

// ---------------- cp.async helpers -----------------------------------------
__device__ __forceinline__ void cp_async16(void* smem_dst, const void* gmem_src) {
    unsigned saddr = (unsigned)__cvta_generic_to_shared(smem_dst);
    asm volatile("cp.async.cg.shared.global [%0], [%1], 16;" :: "r"(saddr), "l"(gmem_src));
}
__device__ __forceinline__ void cp_commit() { asm volatile("cp.async.commit_group;"); }
__device__ __forceinline__ void cp_wait0()  { asm volatile("cp.async.wait_group 0;" ::: "memory"); }

// ---------------- software grid barrier (generation based, replay-safe) ----
__device__ unsigned g_bar_count = 0;
__device__ unsigned g_bar_gen   = 0;

__device__ __forceinline__ void grid_barrier(unsigned nblocks) {
    __syncthreads();
    __threadfence();
    if (threadIdx.x == 0) {
        unsigned gen = atomicAdd(&g_bar_gen, 0u);
        unsigned arrived = atomicAdd(&g_bar_count, 1u);
        if (arrived == nblocks - 1u) {
            atomicExch(&g_bar_count, 0u);
            __threadfence();
            atomicExch(&g_bar_gen, gen + 1u);
        } else {
            while (atomicAdd(&g_bar_gen, 0u) == gen) { __nanosleep(32); }
        }
    }
    __syncthreads();
}

// ---------------- weight pre-pack kernel ------------------------------------
// g_Wq[layer][bx][k][u] = {Whh[0*512+col][k], Whh[512+col][k], Whh[1024+col][k], Whh[1536+col][k]}
// with col = 32*bx + u.
__global__ void prepack_kernel(const float* __restrict__ Whh, float4* __restrict__ Wq) {
    int i = blockIdx.x * blockDim.x + threadIdx.x;        // 0 .. 16*512*32-1
    int uu = i & 31;
    int k  = (i >> 5) & 511;
    int bx = i >> 14;                                     // 0..15
    int col = bx * 32 + uu;
    float4 v;
    v.x = Whh[(size_t)(          col) * Hn + k];
    v.y = Whh[(size_t)( 512 +    col) * Hn + k];
    v.z = Whh[(size_t)(1024 +    col) * Hn + k];
    v.w = Whh[(size_t)(1536 +    col) * Hn + k];
    Wq[i] = v;
}

// ---------------- generic tiled GEMM: C = A @ W^T + b1 (+ b2) (+relu) ------
// A: [M,K] row-major, W: [N,K] row-major, C: [M,N]. 64|M, 64|N, 32|K.
// FFMA2 inner loop; Bs stored transposed [k][col] so 4 consecutive output
// columns read as one aligned float4 / two LDS.64 pairs.
__global__ void gemm_bias_kernel(const float* __restrict__ A,
                                 const float* __restrict__ W,
                                 const float* __restrict__ b1,
                                 const float* __restrict__ b2,
                                 float* __restrict__ C,
                                 int M, int N, int K, int relu)
{
    __shared__ __align__(16) float As[64][36];
    __shared__ __align__(16) float Bs[GKC][64];
    const int m0 = blockIdx.y * 64;
    const int n0 = blockIdx.x * 64;
    const int tid = threadIdx.x;
    const int cx = tid & 15;          // col group: cols 4*cx .. 4*cx+3
    const int ry = tid >> 4;          // row group: rows ry + 16*i

    ull acc01[4], acc23[4];
#pragma unroll
    for (int i = 0; i < 4; i++) { acc01[i] = 0ull; acc23[i] = 0ull; }

    const int nch = K / GKC;
    float4 pA[2], pW[2];
    // prologue: load chunk 0 into registers
#pragma unroll
    for (int i = 0; i < 2; i++) {
        int idx = tid + i * 256;
        pA[i] = *(const float4*)(A + (size_t)(m0 + (idx >> 3)) * K + (idx & 7) * 4);
        pW[i] = *(const float4*)(W + (size_t)(n0 + (idx & 63)) * K + (idx >> 6) * 4);
    }

    for (int c = 0; c < nch; c++) {
        __syncthreads();     // previous compute done before smem overwrite
#pragma unroll
        for (int i = 0; i < 2; i++) {
            int idx = tid + i * 256;
            *(float4*)&As[idx >> 3][(idx & 7) * 4] = pA[i];
            int cW = idx & 63, qW = idx >> 6;
            Bs[qW * 4 + 0][cW] = pW[i].x;
            Bs[qW * 4 + 1][cW] = pW[i].y;
            Bs[qW * 4 + 2][cW] = pW[i].z;
            Bs[qW * 4 + 3][cW] = pW[i].w;
        }
        __syncthreads();
        if (c + 1 < nch) {
            int k0 = (c + 1) * GKC;
#pragma unroll
            for (int i = 0; i < 2; i++) {
                int idx = tid + i * 256;
                pA[i] = *(const float4*)(A + (size_t)(m0 + (idx >> 3)) * K + k0 + (idx & 7) * 4);
                pW[i] = *(const float4*)(W + (size_t)(n0 + (idx & 63)) * K + k0 + (idx >> 6) * 4);
            }
        }
#pragma unroll
        for (int k4 = 0; k4 < GKC; k4 += 4) {
            float4 a4[4];
#pragma unroll
            for (int i = 0; i < 4; i++) a4[i] = *(const float4*)&As[ry + 16 * i][k4];
#pragma unroll
            for (int j = 0; j < 4; j++) {
                const float* wp = &Bs[k4 + j][4 * cx];
                ull w01 = *(const ull*)(wp);
                ull w23 = *(const ull*)(wp + 2);
#pragma unroll
                for (int i = 0; i < 4; i++) {
                    float av = (j == 0) ? a4[i].x : (j == 1) ? a4[i].y : (j == 2) ? a4[i].z : a4[i].w;
                    ull ad = pack2dup(av);
                    ffma2(acc01[i], ad, w01);
                    ffma2(acc23[i], ad, w23);
                }
            }
        }
    }

    const int col = n0 + 4 * cx;
    float bb0 = b1[col + 0], bb1 = b1[col + 1], bb2 = b1[col + 2], bb3 = b1[col + 3];
    if (b2) { bb0 += b2[col + 0]; bb1 += b2[col + 1]; bb2 += b2[col + 2]; bb3 += b2[col + 3]; }
#pragma unroll
    for (int i = 0; i < 4; i++) {
        int row = m0 + ry + 16 * i;
        float2 p01 = unpack2(acc01[i]);
        float2 p23 = unpack2(acc23[i]);
        float4 v;
        v.x = p01.x + bb0; v.y = p01.y + bb1; v.z = p23.x + bb2; v.w = p23.y + bb3;
        if (relu) { v.x = fmaxf(v.x, 0.f); v.y = fmaxf(v.y, 0.f); v.z = fmaxf(v.z, 0.f); v.w = fmaxf(v.w, 0.f); }
        *(float4*)&C[(size_t)row * N + col] = v;
    }
}

// ---------------- persistent LSTM layer kernel ------------------------------
// Grid (16, 8): block tile 32 batch rows x 32 hidden units x all 4 gates.
// Packed weights: Wq[k][u] float4 {Wi,Wf,Wg,Wo}; FFMA2 accumulators pack
// (i,f) and (g,o). Double-buffered cp.async staging of h-tile and W-slice.
__global__ void lstm_layer_kernel(const float* __restrict__ xg,     // [B, T, 4H]
                                  const float4* __restrict__ WqL,   // layer's packed W
                                  float* __restrict__ hA,
                                  float* __restrict__ hB,
                                  float* __restrict__ h_all)        // [B, T, H] or null
{
    __shared__ __align__(16) float  As[2][32][36];
    __shared__ __align__(16) float4 Wqs[2][KC][32];
    const int bx = blockIdx.x;         // unit tile
    const int m0 = blockIdx.y * 32;
    const int tid = threadIdx.x;
    const int tx = tid & 31;           // hidden unit within tile
    const int ty = tid >> 5;           // row group 0..7
    const int u  = bx * 32 + tx;

    const int s_r = tid >> 3, s_q = tid & 7;         // h-tile staging: 1 float4/thread
    const float4* WqT = WqL + (size_t)bx * 512 * 32; // [k][u] slice for this tile

    float creg[4] = {0.f, 0.f, 0.f, 0.f};

    for (int t = 0; t < Tn; t++) {
        const float* h_in = (t & 1) ? hB : hA;
        float* h_out      = (t & 1) ? hA : hB;

        ull acc01[4], acc23[4];
#pragma unroll
        for (int i = 0; i < 4; i++) { acc01[i] = 0ull; acc23[i] = 0ull; }

        if (t > 0) {
            // prologue: stage chunk 0 into buffer 0
            cp_async16(&As[0][s_r][4 * s_q], h_in + (m0 + s_r) * Hn + 4 * s_q);
#pragma unroll
            for (int i = 0; i < 4; i++) {
                int idx = tid + i * 256;
                cp_async16(&Wqs[0][idx >> 5][idx & 31], WqT + (size_t)(idx >> 5) * 32 + (idx & 31));
            }
            cp_commit();

            for (int c = 0; c < Hn / KC; c++) {
                cp_wait0();
                __syncthreads();
                const int buf = c & 1;
                if (c + 1 < Hn / KC) {
                    int k0n = (c + 1) * KC;
                    cp_async16(&As[buf ^ 1][s_r][4 * s_q], h_in + (m0 + s_r) * Hn + k0n + 4 * s_q);
#pragma unroll
                    for (int i = 0; i < 4; i++) {
                        int idx = tid + i * 256;
                        cp_async16(&Wqs[buf ^ 1][idx >> 5][idx & 31],
                                   WqT + (size_t)(k0n + (idx >> 5)) * 32 + (idx & 31));
                    }
                    cp_commit();
                }
#pragma unroll
                for (int k4 = 0; k4 < KC; k4 += 4) {
                    float4 a4[4];
#pragma unroll
                    for (int i = 0; i < 4; i++) a4[i] = *(const float4*)&As[buf][ty + 8 * i][k4];
#pragma unroll
                    for (int j = 0; j < 4; j++) {
                        const float* wp = (const float*)&Wqs[buf][k4 + j][tx];
                        ull w01 = *(const ull*)(wp);
                        ull w23 = *(const ull*)(wp + 2);
#pragma unroll
                        for (int i = 0; i < 4; i++) {
                            float av = (j == 0) ? a4[i].x : (j == 1) ? a4[i].y : (j == 2) ? a4[i].z : a4[i].w;
                            ull ad = pack2dup(av);
                            ffma2(acc01[i], ad, w01);
                            ffma2(acc23[i], ad, w23);
                        }
                    }
                }
            }
        }

#pragma unroll
        for (int i = 0; i < 4; i++) {
            int row = m0 + ty + 8 * i;                        // batch index
            const float* xr = xg + ((size_t)row * Tn + t) * G4H;
            float2 p01 = unpack2(acc01[i]);                   // (i, f)
            float2 p23 = unpack2(acc23[i]);                   // (g, o)
            float gi = p01.x + __ldcg(xr + u);
            float gf = p01.y + __ldcg(xr + 512 + u);
            float gg = p23.x + __ldcg(xr + 1024 + u);
            float go = p23.y + __ldcg(xr + 1536 + u);
            float si = 1.f / (1.f + expf(-gi));
            float sf = 1.f / (1.f + expf(-gf));
            float so = 1.f / (1.f + expf(-go));
            float tg = tanhf(gg);
            float cn = sf * creg[i] + si * tg;
            creg[i] = cn;
            float hn = so * tanhf(cn);
            h_out[row * Hn + u] = hn;
            if (h_all) h_all[((size_t)row * Tn + t) * Hn + u] = hn;
        }

        if (t < Tn - 1) grid_barrier(STEP_BLOCKS);
    }
}

// ---------------- FC2: out[256,8] = z @ W_fc2^T + b ------------------------
__global__ void fc2_kernel(const float* __restrict__ z,
                           const float* __restrict__ W,
                           const float* __restrict__ b,
                           float* __restrict__ out)
{
    int row = blockIdx.x;
    int o = threadIdx.y;
    int lane = threadIdx.x;
    float s = 0.f;
    const float* zr = z + (size_t)row * FCn;
    const float* wr = W + (size_t)o * FCn;
    for (int k = lane; k < FCn; k += 32) s += zr[k] * wr[k];
#pragma unroll
    for (int off = 16; off; off >>= 1) s += __shfl_down_sync(0xffffffffu, s, off);
    if (lane == 0) out[row * OUTn + o] = s + b[o];
}

// ---------------- host orchestration ---------------------------------------
extern "C" void kernel_launch(void* const* d_in, const int* in_sizes, int n_in,
                              void* d_out, int out_size)
{
    const float* x      = (const float*)d_in[0];
    const float* W_ih0  = (const float*)d_in[1];
    const float* W_hh0  = (const float*)d_in[2];
    const float* b_ih0  = (const float*)d_in[3];
    const float* b_hh0  = (const float*)d_in[4];
    const float* W_ih1  = (const float*)d_in[5];
    const float* W_hh1  = (const float*)d_in[6];
    const float* b_ih1  = (const float*)d_in[7];
    const float* b_hh1  = (const float*)d_in[8];
    const float* W_fc1  = (const float*)d_in[9];
    const float* b_fc1  = (const float*)d_in[10];
    const float* W_fc2  = (const float*)d_in[11];
    const float* b_fc2  = (const float*)d_in[12];
    float* out = (float*)d_out;

    float *xg, *h0all, *hA, *hB, *z;
    float4* Wq;
    cudaGetSymbolAddress((void**)&xg,    g_xg);
    cudaGetSymbolAddress((void**)&h0all, g_h0all);
    cudaGetSymbolAddress((void**)&hA,    g_hA);
    cudaGetSymbolAddress((void**)&hB,    g_hB);
    cudaGetSymbolAddress((void**)&z,     g_z);
    cudaGetSymbolAddress((void**)&Wq,    g_Wq);

    const int MT = Bn * Tn;               // 131072
    dim3 gemmGrid(G4H / 64, MT / 64);     // (32, 2048)
    dim3 stepGrid(Hn / 32, Bn / 32);      // (16, 8) = 128 blocks, co-resident

    const int NP = 16 * 512 * 32;         // packed elements per layer
    prepack_kernel<<<NP / 256, 256>>>(W_hh0, Wq);
    prepack_kernel<<<NP / 256, 256>>>(W_hh1, Wq + NP);

    // ---- Layer 0 ----
    gemm_bias_kernel<<<gemmGrid, 256>>>(x, W_ih0, b_ih0, b_hh0, xg, MT, G4H, Dn, 0);
    lstm_layer_kernel<<<stepGrid, 256>>>(xg, Wq, hA, hB, h0all);

    // ---- Layer 1 ----
    gemm_bias_kernel<<<gemmGrid, 256>>>(h0all, W_ih1, b_ih1, b_hh1, xg, MT, G4H, Hn, 0);
    lstm_layer_kernel<<<stepGrid, 256>>>(xg, Wq + NP, hA, hB, (float*)0);
    // T=512 even -> final h lives in hA

    // ---- FC head ----
    dim3 fc1Grid(FCn / 64, Bn / 64);      // (8, 4)
    gemm_bias_kernel<<<fc1Grid, 256>>>(hA, W_fc1, b_fc1, (const float*)0, z, Bn, FCn, Hn, 1);
    fc2_kernel<<<Bn, dim3(32, 8)>>>(z, W_fc2, b_fc2, out);
}

// round 5
// speedup vs baseline: 1.8269x; 1.1692x over previous
#include <cuda_runtime.h>
#include <cstddef>

// Problem constants
#define Bn   256
#define Tn   512
#define Dn   64
#define Hn   512
#define G4H  2048   // 4*H
#define FCn  512
#define OUTn 8

#define KC    32          // k-chunk in step kernel
#define GKC   16          // k-chunk in gemm kernel
#define MGRPS 8           // m-groups (Bn/32)
#define GRP_BLOCKS 16     // blocks per m-group (Hn/32)

typedef unsigned long long ull;

// ---------------- scratch (device globals; no runtime allocation) ----------
__device__ float g_xg[(size_t)Bn * Tn * G4H];
__device__ float g_h0all[(size_t)Bn * Tn * Hn];
__device__ float g_hA[Bn * Hn];
__device__ float g_hB[Bn * Hn];
__device__ float g_z[Bn * FCn];
// packed recurrent weights: [layer][u_tile(16)][k(512)][u(32)] float4 = {Wi,Wf,Wg,Wo}
__device__ float4 g_Wq[2][16 * 512 * 32];

// ---------------- f32x2 packed helpers -------------------------------------
__device__ __forceinline__ void ffma2(ull& d, ull a, ull b) {
    asm("fma.rn.f32x2 %0, %1, %2, %0;" : "+l"(d) : "l"(a), "l"(b));
}
__device__ __forceinline__ ull pack2dup(float x) {
    ull r; asm("mov.b64 %0, {%1, %1};" : "=l"(r) : "f"(x)); return r;
}
__device__ __forceinline__ float2 unpack2(ull v) {
    float2 f; asm("mov.b64 {%0, %1}, %2;" : "=f"(f.x), "=f"(f.y) : "l"(v)); return f;
}

// ---------------- fast activations ------------------------------------------
__device__ __forceinline__ float fsig(float x) {
    return __fdividef(1.f, 1.f + __expf(-x));
}
__device__ __forceinline__ float ftanh(float x) {
    // tanh(x) = 1 - 2/(1 + e^{2x}); stable at both infinities
    return 1.f - __fdividef(2.f, 1.f + __expf(2.f * x));
}

// ---------------- cp.async helpers -----------------------------------------
__device__ __forceinline__ void cp_async16(void* smem_dst, const void* gmem_src) {
    unsigned saddr = (unsigned)__cvta_generic_to_shared(smem_dst);
    asm volatile("cp.async.cg.shared.global [%0], [%1], 16;" :: "r"(saddr), "l"(gmem_src));
}
__device__ __forceinline__ void cp_commit() { asm volatile("cp.async.commit_group;"); }
__device__ __forceinline__ void cp_wait0()  { asm volatile("cp.async.wait_group 0;" ::: "memory"); }

// ---------------- per-m-group barrier (generation based, replay-safe) ------
struct __align__(128) BarSlot { unsigned count; unsigned gen; unsigned pad[30]; };
__device__ BarSlot g_bar[MGRPS];

__device__ __forceinline__ void group_barrier(int grp) {
    __syncthreads();
    __threadfence();
    if (threadIdx.x == 0) {
        unsigned gen = atomicAdd(&g_bar[grp].gen, 0u);
        unsigned arrived = atomicAdd(&g_bar[grp].count, 1u);
        if (arrived == GRP_BLOCKS - 1u) {
            atomicExch(&g_bar[grp].count, 0u);
            __threadfence();
            atomicExch(&g_bar[grp].gen, gen + 1u);
        } else {
            while (atomicAdd(&g_bar[grp].gen, 0u) == gen) { __nanosleep(20); }
        }
    }
    __syncthreads();
}

// ---------------- weight pre-pack kernel ------------------------------------
__global__ void prepack_kernel(const float* __restrict__ Whh, float4* __restrict__ Wq) {
    int i = blockIdx.x * blockDim.x + threadIdx.x;        // 0 .. 16*512*32-1
    int uu = i & 31;
    int k  = (i >> 5) & 511;
    int bx = i >> 14;                                     // 0..15
    int col = bx * 32 + uu;
    float4 v;
    v.x = Whh[(size_t)(          col) * Hn + k];
    v.y = Whh[(size_t)( 512 +    col) * Hn + k];
    v.z = Whh[(size_t)(1024 +    col) * Hn + k];
    v.w = Whh[(size_t)(1536 +    col) * Hn + k];
    Wq[i] = v;
}

// ---------------- tiled GEMM: C = A @ W^T + b1 (+ b2) (+relu) --------------
// A: [M,K] row-major, W: [N,K] row-major, C: [M,N]. 128|M, 64|N, 16|K.
// Tile 128x64 per 256 threads (32 outputs/thread), FFMA2 inner loop,
// cp.async double-buffered A, register-transposed B staging.
__global__ void __launch_bounds__(256, 2)
gemm_bias_kernel(const float* __restrict__ A,
                 const float* __restrict__ W,
                 const float* __restrict__ b1,
                 const float* __restrict__ b2,
                 float* __restrict__ C,
                 int M, int N, int K, int relu)
{
    __shared__ __align__(16) float As[2][128][GKC];
    __shared__ __align__(16) float Bs[2][GKC][64];
    const int m0 = blockIdx.y * 128;
    const int n0 = blockIdx.x * 64;
    const int tid = threadIdx.x;
    const int cx = tid & 15;          // col group: cols 4*cx .. 4*cx+3
    const int ry = tid >> 4;          // 0..15; rows ry + 16*i, i=0..7

    ull acc01[8], acc23[8];
#pragma unroll
    for (int i = 0; i < 8; i++) { acc01[i] = 0ull; acc23[i] = 0ull; }

    const int nch = K / GKC;
    const int ar = tid >> 2, aq = tid & 3;       // A staging (2 float4/thread with +256)
    const int bcol = tid & 63, bq = tid >> 6;    // B staging (1 float4/thread)

    // prologue: chunk 0
#pragma unroll
    for (int i = 0; i < 2; i++) {
        int idx = tid + i * 256;
        cp_async16(&As[0][idx >> 2][(idx & 3) * 4],
                   A + (size_t)(m0 + (idx >> 2)) * K + (idx & 3) * 4);
    }
    cp_commit();
    float4 pW = *(const float4*)(W + (size_t)(n0 + bcol) * K + bq * 4);
    Bs[0][bq * 4 + 0][bcol] = pW.x;
    Bs[0][bq * 4 + 1][bcol] = pW.y;
    Bs[0][bq * 4 + 2][bcol] = pW.z;
    Bs[0][bq * 4 + 3][bcol] = pW.w;

    for (int c = 0; c < nch; c++) {
        cp_wait0();
        __syncthreads();
        const int buf = c & 1;
        const bool more = (c + 1 < nch);
        if (more) {
            int k0 = (c + 1) * GKC;
#pragma unroll
            for (int i = 0; i < 2; i++) {
                int idx = tid + i * 256;
                cp_async16(&As[buf ^ 1][idx >> 2][(idx & 3) * 4],
                           A + (size_t)(m0 + (idx >> 2)) * K + k0 + (idx & 3) * 4);
            }
            cp_commit();
            pW = *(const float4*)(W + (size_t)(n0 + bcol) * K + k0 + bq * 4);
        }
#pragma unroll
        for (int k4 = 0; k4 < GKC; k4 += 4) {
            float4 a4[8];
#pragma unroll
            for (int i = 0; i < 8; i++) a4[i] = *(const float4*)&As[buf][ry + 16 * i][k4];
#pragma unroll
            for (int j = 0; j < 4; j++) {
                float4 w4 = *(const float4*)&Bs[buf][k4 + j][4 * cx];
                ull w01 = *reinterpret_cast<ull*>(&w4.x);
                ull w23 = *reinterpret_cast<ull*>(&w4.z);
#pragma unroll
                for (int i = 0; i < 8; i++) {
                    float av = (j == 0) ? a4[i].x : (j == 1) ? a4[i].y : (j == 2) ? a4[i].z : a4[i].w;
                    ull ad = pack2dup(av);
                    ffma2(acc01[i], ad, w01);
                    ffma2(acc23[i], ad, w23);
                }
            }
        }
        if (more) {
            Bs[buf ^ 1][bq * 4 + 0][bcol] = pW.x;
            Bs[buf ^ 1][bq * 4 + 1][bcol] = pW.y;
            Bs[buf ^ 1][bq * 4 + 2][bcol] = pW.z;
            Bs[buf ^ 1][bq * 4 + 3][bcol] = pW.w;
        }
    }

    const int col = n0 + 4 * cx;
    float bb0 = b1[col + 0], bb1 = b1[col + 1], bb2 = b1[col + 2], bb3 = b1[col + 3];
    if (b2) { bb0 += b2[col + 0]; bb1 += b2[col + 1]; bb2 += b2[col + 2]; bb3 += b2[col + 3]; }
#pragma unroll
    for (int i = 0; i < 8; i++) {
        int row = m0 + ry + 16 * i;
        float2 p01 = unpack2(acc01[i]);
        float2 p23 = unpack2(acc23[i]);
        float4 v;
        v.x = p01.x + bb0; v.y = p01.y + bb1; v.z = p23.x + bb2; v.w = p23.y + bb3;
        if (relu) { v.x = fmaxf(v.x, 0.f); v.y = fmaxf(v.y, 0.f); v.z = fmaxf(v.z, 0.f); v.w = fmaxf(v.w, 0.f); }
        *(float4*)&C[(size_t)row * N + col] = v;
    }
}

// ---------------- persistent LSTM layer kernel ------------------------------
// Grid (16, 8): block tile 32 batch rows x 32 hidden units x all 4 gates.
// Per-m-group barrier (16 blocks). xg + W chunk0 prefetched across barrier.
__global__ void __launch_bounds__(256)
lstm_layer_kernel(const float* __restrict__ xg,     // [B, T, 4H]
                  const float4* __restrict__ WqL,   // layer's packed W
                  float* __restrict__ hA,
                  float* __restrict__ hB,
                  float* __restrict__ h_all)        // [B, T, H] or null
{
    __shared__ __align__(16) float  As[2][32][36];
    __shared__ __align__(16) float4 Wqs[2][KC][32];
    const int bx = blockIdx.x;         // unit tile
    const int grp = blockIdx.y;        // m-group
    const int m0 = grp * 32;
    const int tid = threadIdx.x;
    const int tx = tid & 31;           // hidden unit within tile
    const int ty = tid >> 5;           // row group 0..7
    const int u  = bx * 32 + tx;

    const int s_r = tid >> 3, s_q = tid & 7;         // h-tile staging: 1 float4/thread
    const float4* WqT = WqL + (size_t)bx * 512 * 32; // [k][u] slice for this tile

    float creg[4] = {0.f, 0.f, 0.f, 0.f};
    float xv[4][4];                                  // prefetched xg for current t

    // prefetch xg for t=0
#pragma unroll
    for (int i = 0; i < 4; i++) {
        const float* xr = xg + ((size_t)(m0 + ty + 8 * i) * Tn + 0) * G4H;
        xv[i][0] = __ldcg(xr + u);
        xv[i][1] = __ldcg(xr + 512 + u);
        xv[i][2] = __ldcg(xr + 1024 + u);
        xv[i][3] = __ldcg(xr + 1536 + u);
    }

    for (int t = 0; t < Tn; t++) {
        const float* h_in = (t & 1) ? hB : hA;
        float* h_out      = (t & 1) ? hA : hB;

        ull acc01[4], acc23[4];
#pragma unroll
        for (int i = 0; i < 4; i++) { acc01[i] = 0ull; acc23[i] = 0ull; }

        if (t > 0) {
            // chunk0 As + W cp.async were issued around the barrier below
            for (int c = 0; c < Hn / KC; c++) {
                cp_wait0();
                __syncthreads();
                const int buf = c & 1;
                if (c + 1 < Hn / KC) {
                    int k0n = (c + 1) * KC;
                    cp_async16(&As[buf ^ 1][s_r][4 * s_q], h_in + (m0 + s_r) * Hn + k0n + 4 * s_q);
#pragma unroll
                    for (int i = 0; i < 4; i++) {
                        int idx = tid + i * 256;
                        cp_async16(&Wqs[buf ^ 1][idx >> 5][idx & 31],
                                   WqT + (size_t)(k0n + (idx >> 5)) * 32 + (idx & 31));
                    }
                    cp_commit();
                }
#pragma unroll
                for (int k4 = 0; k4 < KC; k4 += 4) {
                    float4 a4[4];
#pragma unroll
                    for (int i = 0; i < 4; i++) a4[i] = *(const float4*)&As[buf][ty + 8 * i][k4];
#pragma unroll
                    for (int j = 0; j < 4; j++) {
                        float4 w4 = Wqs[buf][k4 + j][tx];
                        ull w01 = *reinterpret_cast<ull*>(&w4.x);
                        ull w23 = *reinterpret_cast<ull*>(&w4.z);
#pragma unroll
                        for (int i = 0; i < 4; i++) {
                            float av = (j == 0) ? a4[i].x : (j == 1) ? a4[i].y : (j == 2) ? a4[i].z : a4[i].w;
                            ull ad = pack2dup(av);
                            ffma2(acc01[i], ad, w01);
                            ffma2(acc23[i], ad, w23);
                        }
                    }
                }
            }
        }

        // ---- epilogue: gate math + h/c update ----
#pragma unroll
        for (int i = 0; i < 4; i++) {
            int row = m0 + ty + 8 * i;
            float2 p01 = unpack2(acc01[i]);                   // (i, f)
            float2 p23 = unpack2(acc23[i]);                   // (g, o)
            float gi = p01.x + xv[i][0];
            float gf = p01.y + xv[i][1];
            float gg = p23.x + xv[i][2];
            float go = p23.y + xv[i][3];
            float si = fsig(gi);
            float sf = fsig(gf);
            float so = fsig(go);
            float tg = ftanh(gg);
            float cn = sf * creg[i] + si * tg;
            creg[i] = cn;
            float hn = so * ftanh(cn);
            h_out[row * Hn + u] = hn;
            if (h_all) h_all[((size_t)row * Tn + t) * Hn + u] = hn;
        }

        if (t < Tn - 1) {
            // prefetch xg for t+1 (independent of h; completes during barrier)
#pragma unroll
            for (int i = 0; i < 4; i++) {
                const float* xr = xg + ((size_t)(m0 + ty + 8 * i) * Tn + (t + 1)) * G4H;
                xv[i][0] = __ldcg(xr + u);
                xv[i][1] = __ldcg(xr + 512 + u);
                xv[i][2] = __ldcg(xr + 1024 + u);
                xv[i][3] = __ldcg(xr + 1536 + u);
            }
            // prefetch W chunk0 for next step (h-independent)
#pragma unroll
            for (int i = 0; i < 4; i++) {
                int idx = tid + i * 256;
                cp_async16(&Wqs[0][idx >> 5][idx & 31], WqT + (size_t)(idx >> 5) * 32 + (idx & 31));
            }
            cp_commit();

            group_barrier(grp);

            // now h for step t is visible: stage As chunk0
            const float* h_next_in = ((t + 1) & 1) ? hB : hA;
            cp_async16(&As[0][s_r][4 * s_q], h_next_in + (m0 + s_r) * Hn + 4 * s_q);
            cp_commit();
        }
    }
}

// ---------------- FC2: out[256,8] = z @ W_fc2^T + b ------------------------
__global__ void fc2_kernel(const float* __restrict__ z,
                           const float* __restrict__ W,
                           const float* __restrict__ b,
                           float* __restrict__ out)
{
    int row = blockIdx.x;
    int o = threadIdx.y;
    int lane = threadIdx.x;
    float s = 0.f;
    const float* zr = z + (size_t)row * FCn;
    const float* wr = W + (size_t)o * FCn;
    for (int k = lane; k < FCn; k += 32) s += zr[k] * wr[k];
#pragma unroll
    for (int off = 16; off; off >>= 1) s += __shfl_down_sync(0xffffffffu, s, off);
    if (lane == 0) out[row * OUTn + o] = s + b[o];
}

// ---------------- host orchestration ---------------------------------------
extern "C" void kernel_launch(void* const* d_in, const int* in_sizes, int n_in,
                              void* d_out, int out_size)
{
    const float* x      = (const float*)d_in[0];
    const float* W_ih0  = (const float*)d_in[1];
    const float* W_hh0  = (const float*)d_in[2];
    const float* b_ih0  = (const float*)d_in[3];
    const float* b_hh0  = (const float*)d_in[4];
    const float* W_ih1  = (const float*)d_in[5];
    const float* W_hh1  = (const float*)d_in[6];
    const float* b_ih1  = (const float*)d_in[7];
    const float* b_hh1  = (const float*)d_in[8];
    const float* W_fc1  = (const float*)d_in[9];
    const float* b_fc1  = (const float*)d_in[10];
    const float* W_fc2  = (const float*)d_in[11];
    const float* b_fc2  = (const float*)d_in[12];
    float* out = (float*)d_out;

    float *xg, *h0all, *hA, *hB, *z;
    float4* Wq;
    cudaGetSymbolAddress((void**)&xg,    g_xg);
    cudaGetSymbolAddress((void**)&h0all, g_h0all);
    cudaGetSymbolAddress((void**)&hA,    g_hA);
    cudaGetSymbolAddress((void**)&hB,    g_hB);
    cudaGetSymbolAddress((void**)&z,     g_z);
    cudaGetSymbolAddress((void**)&Wq,    g_Wq);

    const int MT = Bn * Tn;                 // 131072
    dim3 gemmGrid(G4H / 64, MT / 128);      // (32, 1024)
    dim3 stepGrid(Hn / 32, Bn / 32);        // (16, 8) = 128 blocks, co-resident

    const int NP = 16 * 512 * 32;
    prepack_kernel<<<NP / 256, 256>>>(W_hh0, Wq);
    prepack_kernel<<<NP / 256, 256>>>(W_hh1, Wq + NP);

    // ---- Layer 0 ----
    gemm_bias_kernel<<<gemmGrid, 256>>>(x, W_ih0, b_ih0, b_hh0, xg, MT, G4H, Dn, 0);
    lstm_layer_kernel<<<stepGrid, 256>>>(xg, Wq, hA, hB, h0all);

    // ---- Layer 1 ----
    gemm_bias_kernel<<<gemmGrid, 256>>>(h0all, W_ih1, b_ih1, b_hh1, xg, MT, G4H, Hn, 0);
    lstm_layer_kernel<<<stepGrid, 256>>>(xg, Wq + NP, hA, hB, (float*)0);
    // T=512 even -> final h lives in hA

    // ---- FC head ----
    dim3 fc1Grid(FCn / 64, Bn / 128);       // (8, 2)
    gemm_bias_kernel<<<fc1Grid, 256>>>(hA, W_fc1, b_fc1, (const float*)0, z, Bn, FCn, Hn, 1);
    fc2_kernel<<<Bn, dim3(32, 8)>>>(z, W_fc2, b_fc2, out);
}

// round 7
// speedup vs baseline: 2.1651x; 1.1851x over previous
#include <cuda_runtime.h>
#include <cuda_bf16.h>
#include <cstddef>
#include <cstdint>

// Problem constants
#define Bn   256
#define Tn   512
#define Dn   64
#define Hn   512
#define G4H  2048   // 4*H
#define FCn  512
#define OUTn 8

#define KC    32          // k-chunk in step kernel
#define GKC   16          // k-chunk in fp32 gemm kernel
#define MGRPS 8           // m-groups (Bn/32)
#define GRP_BLOCKS 16     // blocks per m-group (Hn/32)

typedef unsigned long long ull;

#define SWZ128(off) ((off) ^ (((off) >> 3) & 0x70))

// ---------------- scratch (device globals; no runtime allocation) ----------
__device__ float g_xg[(size_t)Bn * Tn * G4H];
__device__ float g_h0all[(size_t)Bn * Tn * Hn];
__device__ float g_hA[Bn * Hn];
__device__ float g_hB[Bn * Hn];
__device__ float g_z[Bn * FCn];
// packed recurrent weights: [layer][u_tile(16)][k(512)][u(32)] float4 = {Wi,Wf,Wg,Wo}
__device__ float4 g_Wq[2][16 * 512 * 32];
// bf16 hi/lo pre-swizzled W_ih for mma gemm (uint4 => 16B aligned for cp.async)
__device__ uint4 g_Wb0hi[G4H * Dn / 8],  g_Wb0lo[G4H * Dn / 8];   // layer0: 2048x64
__device__ uint4 g_Wb1hi[G4H * Hn / 8],  g_Wb1lo[G4H * Hn / 8];   // layer1: 2048x512

// ---------------- f32x2 packed helpers -------------------------------------
__device__ __forceinline__ void ffma2(ull& d, ull a, ull b) {
    asm("fma.rn.f32x2 %0, %1, %2, %0;" : "+l"(d) : "l"(a), "l"(b));
}
__device__ __forceinline__ ull pack2dup(float x) {
    ull r; asm("mov.b64 %0, {%1, %1};" : "=l"(r) : "f"(x)); return r;
}
__device__ __forceinline__ float2 unpack2(ull v) {
    float2 f; asm("mov.b64 {%0, %1}, %2;" : "=f"(f.x), "=f"(f.y) : "l"(v)); return f;
}

// ---------------- fast activations ------------------------------------------
__device__ __forceinline__ float fsig(float x) {
    return __fdividef(1.f, 1.f + __expf(-x));
}
__device__ __forceinline__ float ftanh(float x) {
    return 1.f - __fdividef(2.f, 1.f + __expf(2.f * x));
}

// ---------------- cp.async helpers -----------------------------------------
__device__ __forceinline__ void cp_async16(void* smem_dst, const void* gmem_src) {
    unsigned saddr = (unsigned)__cvta_generic_to_shared(smem_dst);
    asm volatile("cp.async.cg.shared.global [%0], [%1], 16;" :: "r"(saddr), "l"(gmem_src));
}
__device__ __forceinline__ void cp_async16u(unsigned saddr, const void* gmem_src) {
    asm volatile("cp.async.cg.shared.global [%0], [%1], 16;" :: "r"(saddr), "l"(gmem_src));
}
__device__ __forceinline__ void cp_commit() { asm volatile("cp.async.commit_group;"); }
__device__ __forceinline__ void cp_wait0()  { asm volatile("cp.async.wait_group 0;" ::: "memory"); }

__device__ __forceinline__ unsigned smem_u32(const void* p) {
    return (unsigned)__cvta_generic_to_shared(p);
}
__device__ __forceinline__ uint32_t cvt_bf16x2(float hi, float lo) {
    uint32_t r; asm("cvt.rn.bf16x2.f32 %0, %1, %2;" : "=r"(r) : "f"(hi), "f"(lo)); return r;
}

// ---------------- warp-level mma helpers ------------------------------------
__device__ __forceinline__ void ldsm_x4(uint32_t& r0, uint32_t& r1, uint32_t& r2, uint32_t& r3,
                                        uint32_t addr) {
    asm volatile("ldmatrix.sync.aligned.m8n8.x4.shared.b16 {%0,%1,%2,%3}, [%4];"
                 : "=r"(r0), "=r"(r1), "=r"(r2), "=r"(r3) : "r"(addr));
}
__device__ __forceinline__ void mma_bf16(float* d, const uint32_t* a, const uint32_t* b) {
    asm volatile("mma.sync.aligned.m16n8k16.row.col.f32.bf16.bf16.f32 "
                 "{%0,%1,%2,%3}, {%4,%5,%6,%7}, {%8,%9}, {%0,%1,%2,%3};"
                 : "+f"(d[0]), "+f"(d[1]), "+f"(d[2]), "+f"(d[3])
                 : "r"(a[0]), "r"(a[1]), "r"(a[2]), "r"(a[3]), "r"(b[0]), "r"(b[1]));
}

// ---------------- per-m-group barrier (generation based, replay-safe) ------
struct __align__(128) BarSlot { unsigned count; unsigned gen; unsigned pad[30]; };
__device__ BarSlot g_bar[MGRPS];

__device__ __forceinline__ void group_barrier(int grp) {
    __syncthreads();
    __threadfence();
    if (threadIdx.x == 0) {
        unsigned gen = atomicAdd(&g_bar[grp].gen, 0u);
        unsigned arrived = atomicAdd(&g_bar[grp].count, 1u);
        if (arrived == GRP_BLOCKS - 1u) {
            atomicExch(&g_bar[grp].count, 0u);
            __threadfence();
            atomicExch(&g_bar[grp].gen, gen + 1u);
        } else {
            while (atomicAdd(&g_bar[grp].gen, 0u) == gen) { __nanosleep(20); }
        }
    }
    __syncthreads();
}

// ---------------- weight pre-pack kernels -----------------------------------
__global__ void prepack_kernel(const float* __restrict__ Whh, float4* __restrict__ Wq) {
    int i = blockIdx.x * blockDim.x + threadIdx.x;        // 0 .. 16*512*32-1
    int uu = i & 31;
    int k  = (i >> 5) & 511;
    int bx = i >> 14;                                     // 0..15
    int col = bx * 32 + uu;
    float4 v;
    v.x = Whh[(size_t)(          col) * Hn + k];
    v.y = Whh[(size_t)( 512 +    col) * Hn + k];
    v.z = Whh[(size_t)(1024 +    col) * Hn + k];
    v.w = Whh[(size_t)(1536 +    col) * Hn + k];
    Wq[i] = v;
}

// Split W (N=2048 x K) into bf16 hi/lo, per (ntile, kchunk) 64x64 tile with
// SW128 swizzle so the GEMM can cp.async + ldmatrix directly.
__global__ void prepack_b_kernel(const float* __restrict__ W,
                                 __nv_bfloat16* __restrict__ hi,
                                 __nv_bfloat16* __restrict__ lo,
                                 int K)
{
    int i = blockIdx.x * blockDim.x + threadIdx.x;        // 0 .. 2048*K-1
    int k = i % K;
    int n = i / K;
    int ntile = n >> 6, ln = n & 63;
    int kc = k >> 6, lk = k & 63;
    int nch = K >> 6;
    size_t off = ((size_t)(ntile * nch + kc)) * 4096 + (SWZ128(ln * 128 + lk * 2) >> 1);
    float w = W[(size_t)n * K + k];
    __nv_bfloat16 h = __float2bfloat16(w);
    hi[off] = h;
    lo[off] = __float2bfloat16(w - __bfloat162float(h));
}

// ---------------- HMMA split-bf16 GEMM: C = A @ W^T + b1 (+b2) -------------
// A: [M,K] fp32 row-major (split to bf16 hi/lo in-kernel).
// W prepacked hi/lo swizzled 64x64 tiles. Block tile 128(M) x 64(N), K by 64.
// 8 warps: warp w -> m (w&3)*32, n (w>>2)*32; per warp 2x4 m16n8k16 tiles.
// 3 terms per tile: Ahi*Bhi + Ahi*Blo + Alo*Bhi, fp32 accumulate.
#define MMAG_SMEM (49152 + 1024)
__global__ void __launch_bounds__(256, 2)
mma_gemm_kernel(const float* __restrict__ A,
                const uint4* __restrict__ Wbhi,
                const uint4* __restrict__ Wblo,
                const float* __restrict__ b1,
                const float* __restrict__ b2,
                float* __restrict__ C,
                int K, int Ntot)
{
    extern __shared__ char dsm[];
    uint32_t usm = smem_u32(dsm);
    usm = (usm + 1023u) & ~1023u;
    const uint32_t uAhi = usm;              // 128 x 64 bf16 = 16KB
    const uint32_t uAlo = usm + 16384;      // 16KB
    const uint32_t uBhi = usm + 32768;      // 64 x 64 bf16 = 8KB
    const uint32_t uBlo = usm + 40960;      // 8KB

    const int bn = blockIdx.x;
    const int m0 = blockIdx.y * 128;
    const int n0 = bn * 64;
    const int tid = threadIdx.x;
    const int w = tid >> 5;
    const int lane = tid & 31;
    const int mw = (w & 3) * 32;
    const int nw = (w >> 2) * 32;
    const int nch = K >> 6;

    // per-lane ldmatrix addressing
    const uint32_t xorv  = (uint32_t)(lane & 7) << 4;
    const uint32_t aRow  = mw + (lane & 15);            // + mt in {0,16}
    const uint32_t aKsel = (uint32_t)(lane >> 4) << 4;  // k-half select
    const uint32_t bRow  = nw + (lane & 7) + ((lane >> 4) << 3);  // + ng in {0,16}
    const uint32_t bKsel = (uint32_t)((lane >> 3) & 1) << 4;

    float acc[2][4][4];
#pragma unroll
    for (int mt = 0; mt < 2; mt++)
#pragma unroll
        for (int nt = 0; nt < 4; nt++)
#pragma unroll
            for (int e = 0; e < 4; e++) acc[mt][nt][e] = 0.f;

    for (int c = 0; c < nch; c++) {
        if (c) __syncthreads();             // previous compute done before overwrite

        // ---- stage B (cp.async, pre-swizzled bf16 hi/lo tiles) ----
        const uint4* sbh = Wbhi + ((size_t)bn * nch + c) * 512;
        const uint4* sbl = Wblo + ((size_t)bn * nch + c) * 512;
        cp_async16u(uBhi + (uint32_t)tid * 16,         sbh + tid);
        cp_async16u(uBhi + (uint32_t)(tid + 256) * 16, sbh + tid + 256);
        cp_async16u(uBlo + (uint32_t)tid * 16,         sbl + tid);
        cp_async16u(uBlo + (uint32_t)(tid + 256) * 16, sbl + tid + 256);
        cp_commit();

        // ---- stage A: LDG fp32 -> split bf16 hi/lo -> swizzled STS ----
        const int k0 = c * 64;
#pragma unroll
        for (int it = 0; it < 8; it++) {
            int idx = tid + it * 256;                   // 0..2047
            int r = idx >> 4, f4 = idx & 15;
            float4 v = *(const float4*)(A + (size_t)(m0 + r) * K + k0 + f4 * 4);
            uint32_t h01 = cvt_bf16x2(v.y, v.x);
            uint32_t h23 = cvt_bf16x2(v.w, v.z);
            float f0 = __uint_as_float(h01 << 16);
            float f1 = __uint_as_float(h01 & 0xffff0000u);
            float f2 = __uint_as_float(h23 << 16);
            float f3 = __uint_as_float(h23 & 0xffff0000u);
            uint32_t l01 = cvt_bf16x2(v.y - f1, v.x - f0);
            uint32_t l23 = cvt_bf16x2(v.w - f3, v.z - f2);
            uint32_t sw = (uint32_t)r * 128 + (((uint32_t)f4 * 8) ^ (((uint32_t)r & 7) << 4));
            asm volatile("st.shared.v2.u32 [%0], {%1,%2};" :: "r"(uAhi + sw), "r"(h01), "r"(h23));
            asm volatile("st.shared.v2.u32 [%0], {%1,%2};" :: "r"(uAlo + sw), "r"(l01), "r"(l23));
        }
        cp_wait0();
        __syncthreads();

        // ---- compute: 4 k16 steps ----
#pragma unroll
        for (int ks = 0; ks < 4; ks++) {
            const uint32_t kbA = ((uint32_t)(32 * ks) + aKsel) ^ xorv;
            const uint32_t kbB = ((uint32_t)(32 * ks) + bKsel) ^ xorv;
            uint32_t ah0[4], ah1[4], al0[4], al1[4];
            ldsm_x4(ah0[0], ah0[1], ah0[2], ah0[3], uAhi + aRow * 128 + kbA);
            ldsm_x4(ah1[0], ah1[1], ah1[2], ah1[3], uAhi + (aRow + 16) * 128 + kbA);
            ldsm_x4(al0[0], al0[1], al0[2], al0[3], uAlo + aRow * 128 + kbA);
            ldsm_x4(al1[0], al1[1], al1[2], al1[3], uAlo + (aRow + 16) * 128 + kbA);
            uint32_t bh[8], bl[8];
            ldsm_x4(bh[0], bh[1], bh[2], bh[3], uBhi + bRow * 128 + kbB);
            ldsm_x4(bh[4], bh[5], bh[6], bh[7], uBhi + (bRow + 16) * 128 + kbB);
            ldsm_x4(bl[0], bl[1], bl[2], bl[3], uBlo + bRow * 128 + kbB);
            ldsm_x4(bl[4], bl[5], bl[6], bl[7], uBlo + (bRow + 16) * 128 + kbB);
#pragma unroll
            for (int mt = 0; mt < 2; mt++) {
                const uint32_t* Ah = mt ? ah1 : ah0;
                const uint32_t* Al = mt ? al1 : al0;
#pragma unroll
                for (int nt = 0; nt < 4; nt++) {
                    mma_bf16(acc[mt][nt], Ah, bh + nt * 2);
                    mma_bf16(acc[mt][nt], Ah, bl + nt * 2);
                    mma_bf16(acc[mt][nt], Al, bh + nt * 2);
                }
            }
        }
    }

    // ---- epilogue ----
    const int gid = lane >> 2, tig = lane & 3;
    float2 bias[4];
#pragma unroll
    for (int nt = 0; nt < 4; nt++) {
        int col = n0 + nw + nt * 8 + tig * 2;
        bias[nt].x = b1[col]     + (b2 ? b2[col]     : 0.f);
        bias[nt].y = b1[col + 1] + (b2 ? b2[col + 1] : 0.f);
    }
#pragma unroll
    for (int mt = 0; mt < 2; mt++) {
        int row0 = m0 + mw + mt * 16 + gid;
#pragma unroll
        for (int nt = 0; nt < 4; nt++) {
            int col = n0 + nw + nt * 8 + tig * 2;
            float2 v0, v1;
            v0.x = acc[mt][nt][0] + bias[nt].x;
            v0.y = acc[mt][nt][1] + bias[nt].y;
            v1.x = acc[mt][nt][2] + bias[nt].x;
            v1.y = acc[mt][nt][3] + bias[nt].y;
            *(float2*)&C[(size_t)row0 * Ntot + col]       = v0;
            *(float2*)&C[(size_t)(row0 + 8) * Ntot + col] = v1;
        }
    }
}

// ---------------- fp32 tiled GEMM (kept for FC1) ----------------------------
__global__ void __launch_bounds__(256, 2)
gemm_bias_kernel(const float* __restrict__ A,
                 const float* __restrict__ W,
                 const float* __restrict__ b1,
                 const float* __restrict__ b2,
                 float* __restrict__ C,
                 int M, int N, int K, int relu)
{
    __shared__ __align__(16) float As[2][128][GKC];
    __shared__ __align__(16) float Bs[2][GKC][64];
    const int m0 = blockIdx.y * 128;
    const int n0 = blockIdx.x * 64;
    const int tid = threadIdx.x;
    const int cx = tid & 15;
    const int ry = tid >> 4;

    ull acc01[8], acc23[8];
#pragma unroll
    for (int i = 0; i < 8; i++) { acc01[i] = 0ull; acc23[i] = 0ull; }

    const int nch = K / GKC;
    const int bcol = tid & 63, bq = tid >> 6;

#pragma unroll
    for (int i = 0; i < 2; i++) {
        int idx = tid + i * 256;
        cp_async16(&As[0][idx >> 2][(idx & 3) * 4],
                   A + (size_t)(m0 + (idx >> 2)) * K + (idx & 3) * 4);
    }
    cp_commit();
    float4 pW = *(const float4*)(W + (size_t)(n0 + bcol) * K + bq * 4);
    Bs[0][bq * 4 + 0][bcol] = pW.x;
    Bs[0][bq * 4 + 1][bcol] = pW.y;
    Bs[0][bq * 4 + 2][bcol] = pW.z;
    Bs[0][bq * 4 + 3][bcol] = pW.w;

    for (int c = 0; c < nch; c++) {
        cp_wait0();
        __syncthreads();
        const int buf = c & 1;
        const bool more = (c + 1 < nch);
        if (more) {
            int k0 = (c + 1) * GKC;
#pragma unroll
            for (int i = 0; i < 2; i++) {
                int idx = tid + i * 256;
                cp_async16(&As[buf ^ 1][idx >> 2][(idx & 3) * 4],
                           A + (size_t)(m0 + (idx >> 2)) * K + k0 + (idx & 3) * 4);
            }
            cp_commit();
            pW = *(const float4*)(W + (size_t)(n0 + bcol) * K + k0 + bq * 4);
        }
#pragma unroll
        for (int k4 = 0; k4 < GKC; k4 += 4) {
            float4 a4[8];
#pragma unroll
            for (int i = 0; i < 8; i++) a4[i] = *(const float4*)&As[buf][ry + 16 * i][k4];
#pragma unroll
            for (int j = 0; j < 4; j++) {
                float4 w4 = *(const float4*)&Bs[buf][k4 + j][4 * cx];
                ull w01 = *reinterpret_cast<ull*>(&w4.x);
                ull w23 = *reinterpret_cast<ull*>(&w4.z);
#pragma unroll
                for (int i = 0; i < 8; i++) {
                    float av = (j == 0) ? a4[i].x : (j == 1) ? a4[i].y : (j == 2) ? a4[i].z : a4[i].w;
                    ull ad = pack2dup(av);
                    ffma2(acc01[i], ad, w01);
                    ffma2(acc23[i], ad, w23);
                }
            }
        }
        if (more) {
            Bs[buf ^ 1][bq * 4 + 0][bcol] = pW.x;
            Bs[buf ^ 1][bq * 4 + 1][bcol] = pW.y;
            Bs[buf ^ 1][bq * 4 + 2][bcol] = pW.z;
            Bs[buf ^ 1][bq * 4 + 3][bcol] = pW.w;
        }
    }

    const int col = n0 + 4 * cx;
    float bb0 = b1[col + 0], bb1 = b1[col + 1], bb2 = b1[col + 2], bb3 = b1[col + 3];
    if (b2) { bb0 += b2[col + 0]; bb1 += b2[col + 1]; bb2 += b2[col + 2]; bb3 += b2[col + 3]; }
#pragma unroll
    for (int i = 0; i < 8; i++) {
        int row = m0 + ry + 16 * i;
        float2 p01 = unpack2(acc01[i]);
        float2 p23 = unpack2(acc23[i]);
        float4 v;
        v.x = p01.x + bb0; v.y = p01.y + bb1; v.z = p23.x + bb2; v.w = p23.y + bb3;
        if (relu) { v.x = fmaxf(v.x, 0.f); v.y = fmaxf(v.y, 0.f); v.z = fmaxf(v.z, 0.f); v.w = fmaxf(v.w, 0.f); }
        *(float4*)&C[(size_t)row * N + col] = v;
    }
}

// ---------------- persistent LSTM layer kernel ------------------------------
__global__ void __launch_bounds__(256)
lstm_layer_kernel(const float* __restrict__ xg,     // [B, T, 4H]
                  const float4* __restrict__ WqL,   // layer's packed W
                  float* __restrict__ hA,
                  float* __restrict__ hB,
                  float* __restrict__ h_all)        // [B, T, H] or null
{
    __shared__ __align__(16) float  As[2][32][36];
    __shared__ __align__(16) float4 Wqs[2][KC][32];
    const int bx = blockIdx.x;
    const int grp = blockIdx.y;
    const int m0 = grp * 32;
    const int tid = threadIdx.x;
    const int tx = tid & 31;
    const int ty = tid >> 5;
    const int u  = bx * 32 + tx;

    const int s_r = tid >> 3, s_q = tid & 7;
    const float4* WqT = WqL + (size_t)bx * 512 * 32;

    float creg[4] = {0.f, 0.f, 0.f, 0.f};
    float xv[4][4];

#pragma unroll
    for (int i = 0; i < 4; i++) {
        const float* xr = xg + ((size_t)(m0 + ty + 8 * i) * Tn + 0) * G4H;
        xv[i][0] = __ldcg(xr + u);
        xv[i][1] = __ldcg(xr + 512 + u);
        xv[i][2] = __ldcg(xr + 1024 + u);
        xv[i][3] = __ldcg(xr + 1536 + u);
    }

    for (int t = 0; t < Tn; t++) {
        const float* h_in = (t & 1) ? hB : hA;
        float* h_out      = (t & 1) ? hA : hB;

        ull acc01[4], acc23[4];
#pragma unroll
        for (int i = 0; i < 4; i++) { acc01[i] = 0ull; acc23[i] = 0ull; }

        if (t > 0) {
            for (int c = 0; c < Hn / KC; c++) {
                cp_wait0();
                __syncthreads();
                const int buf = c & 1;
                if (c + 1 < Hn / KC) {
                    int k0n = (c + 1) * KC;
                    cp_async16(&As[buf ^ 1][s_r][4 * s_q], h_in + (m0 + s_r) * Hn + k0n + 4 * s_q);
#pragma unroll
                    for (int i = 0; i < 4; i++) {
                        int idx = tid + i * 256;
                        cp_async16(&Wqs[buf ^ 1][idx >> 5][idx & 31],
                                   WqT + (size_t)(k0n + (idx >> 5)) * 32 + (idx & 31));
                    }
                    cp_commit();
                }
#pragma unroll
                for (int k4 = 0; k4 < KC; k4 += 4) {
                    float4 a4[4];
#pragma unroll
                    for (int i = 0; i < 4; i++) a4[i] = *(const float4*)&As[buf][ty + 8 * i][k4];
#pragma unroll
                    for (int j = 0; j < 4; j++) {
                        float4 w4 = Wqs[buf][k4 + j][tx];
                        ull w01 = *reinterpret_cast<ull*>(&w4.x);
                        ull w23 = *reinterpret_cast<ull*>(&w4.z);
#pragma unroll
                        for (int i = 0; i < 4; i++) {
                            float av = (j == 0) ? a4[i].x : (j == 1) ? a4[i].y : (j == 2) ? a4[i].z : a4[i].w;
                            ull ad = pack2dup(av);
                            ffma2(acc01[i], ad, w01);
                            ffma2(acc23[i], ad, w23);
                        }
                    }
                }
            }
        }

#pragma unroll
        for (int i = 0; i < 4; i++) {
            int row = m0 + ty + 8 * i;
            float2 p01 = unpack2(acc01[i]);
            float2 p23 = unpack2(acc23[i]);
            float gi = p01.x + xv[i][0];
            float gf = p01.y + xv[i][1];
            float gg = p23.x + xv[i][2];
            float go = p23.y + xv[i][3];
            float si = fsig(gi);
            float sf = fsig(gf);
            float so = fsig(go);
            float tg = ftanh(gg);
            float cn = sf * creg[i] + si * tg;
            creg[i] = cn;
            float hn = so * ftanh(cn);
            h_out[row * Hn + u] = hn;
            if (h_all) h_all[((size_t)row * Tn + t) * Hn + u] = hn;
        }

        if (t < Tn - 1) {
#pragma unroll
            for (int i = 0; i < 4; i++) {
                const float* xr = xg + ((size_t)(m0 + ty + 8 * i) * Tn + (t + 1)) * G4H;
                xv[i][0] = __ldcg(xr + u);
                xv[i][1] = __ldcg(xr + 512 + u);
                xv[i][2] = __ldcg(xr + 1024 + u);
                xv[i][3] = __ldcg(xr + 1536 + u);
            }
#pragma unroll
            for (int i = 0; i < 4; i++) {
                int idx = tid + i * 256;
                cp_async16(&Wqs[0][idx >> 5][idx & 31], WqT + (size_t)(idx >> 5) * 32 + (idx & 31));
            }
            cp_commit();

            group_barrier(grp);

            const float* h_next_in = ((t + 1) & 1) ? hB : hA;
            cp_async16(&As[0][s_r][4 * s_q], h_next_in + (m0 + s_r) * Hn + 4 * s_q);
            cp_commit();
        }
    }
}

// ---------------- FC2: out[256,8] = z @ W_fc2^T + b ------------------------
__global__ void fc2_kernel(const float* __restrict__ z,
                           const float* __restrict__ W,
                           const float* __restrict__ b,
                           float* __restrict__ out)
{
    int row = blockIdx.x;
    int o = threadIdx.y;
    int lane = threadIdx.x;
    float s = 0.f;
    const float* zr = z + (size_t)row * FCn;
    const float* wr = W + (size_t)o * FCn;
    for (int k = lane; k < FCn; k += 32) s += zr[k] * wr[k];
#pragma unroll
    for (int off = 16; off; off >>= 1) s += __shfl_down_sync(0xffffffffu, s, off);
    if (lane == 0) out[row * OUTn + o] = s + b[o];
}

// ---------------- host orchestration ---------------------------------------
extern "C" void kernel_launch(void* const* d_in, const int* in_sizes, int n_in,
                              void* d_out, int out_size)
{
    const float* x      = (const float*)d_in[0];
    const float* W_ih0  = (const float*)d_in[1];
    const float* W_hh0  = (const float*)d_in[2];
    const float* b_ih0  = (const float*)d_in[3];
    const float* b_hh0  = (const float*)d_in[4];
    const float* W_ih1  = (const float*)d_in[5];
    const float* W_hh1  = (const float*)d_in[6];
    const float* b_ih1  = (const float*)d_in[7];
    const float* b_hh1  = (const float*)d_in[8];
    const float* W_fc1  = (const float*)d_in[9];
    const float* b_fc1  = (const float*)d_in[10];
    const float* W_fc2  = (const float*)d_in[11];
    const float* b_fc2  = (const float*)d_in[12];
    float* out = (float*)d_out;

    float *xg, *h0all, *hA, *hB, *z;
    float4* Wq;
    uint4 *wb0h, *wb0l, *wb1h, *wb1l;
    cudaGetSymbolAddress((void**)&xg,    g_xg);
    cudaGetSymbolAddress((void**)&h0all, g_h0all);
    cudaGetSymbolAddress((void**)&hA,    g_hA);
    cudaGetSymbolAddress((void**)&hB,    g_hB);
    cudaGetSymbolAddress((void**)&z,     g_z);
    cudaGetSymbolAddress((void**)&Wq,    g_Wq);
    cudaGetSymbolAddress((void**)&wb0h,  g_Wb0hi);
    cudaGetSymbolAddress((void**)&wb0l,  g_Wb0lo);
    cudaGetSymbolAddress((void**)&wb1h,  g_Wb1hi);
    cudaGetSymbolAddress((void**)&wb1l,  g_Wb1lo);

    cudaFuncSetAttribute(mma_gemm_kernel, cudaFuncAttributeMaxDynamicSharedMemorySize, MMAG_SMEM);

    const int MT = Bn * Tn;                 // 131072
    dim3 mmaGrid(G4H / 64, MT / 128);       // (32, 1024)
    dim3 stepGrid(Hn / 32, Bn / 32);        // (16, 8)

    const int NP = 16 * 512 * 32;
    prepack_kernel<<<NP / 256, 256>>>(W_hh0, Wq);
    prepack_kernel<<<NP / 256, 256>>>(W_hh1, Wq + NP);
    prepack_b_kernel<<<(G4H * Dn) / 256, 256>>>(W_ih0, (__nv_bfloat16*)wb0h, (__nv_bfloat16*)wb0l, Dn);
    prepack_b_kernel<<<(G4H * Hn) / 256, 256>>>(W_ih1, (__nv_bfloat16*)wb1h, (__nv_bfloat16*)wb1l, Hn);

    // ---- Layer 0 ----  xg = x @ W_ih0^T + b_ih0 + b_hh0 (K=64)
    mma_gemm_kernel<<<mmaGrid, 256, MMAG_SMEM>>>(x, wb0h, wb0l, b_ih0, b_hh0, xg, Dn, G4H);
    lstm_layer_kernel<<<stepGrid, 256>>>(xg, Wq, hA, hB, h0all);

    // ---- Layer 1 ----  xg = h0all @ W_ih1^T + b_ih1 + b_hh1 (K=512)
    mma_gemm_kernel<<<mmaGrid, 256, MMAG_SMEM>>>(h0all, wb1h, wb1l, b_ih1, b_hh1, xg, Hn, G4H);
    lstm_layer_kernel<<<stepGrid, 256>>>(xg, Wq + NP, hA, hB, (float*)0);
    // T=512 even -> final h lives in hA

    // ---- FC head ----
    dim3 fc1Grid(FCn / 64, Bn / 128);       // (8, 2)
    gemm_bias_kernel<<<fc1Grid, 256>>>(hA, W_fc1, b_fc1, (const float*)0, z, Bn, FCn, Hn, 1);
    fc2_kernel<<<Bn, dim3(32, 8)>>>(z, W_fc2, b_fc2, out);
}

// round 8
// speedup vs baseline: 3.4965x; 1.6149x over previous
#include <cuda_runtime.h>
#include <cuda_bf16.h>
#include <cstddef>
#include <cstdint>

// Problem constants
#define Bn   256
#define Tn   512
#define Dn   64
#define Hn   512
#define G4H  2048   // 4*H
#define FCn  512
#define OUTn 8

#define GKC   16          // k-chunk in fp32 gemm kernel
#define MGRPS 4           // m-groups (Bn/64)
#define GRP_BLOCKS 32     // blocks per m-group (2048 cols / 64)

typedef unsigned long long ull;

#define SWZ128(off) ((off) ^ (((off) >> 3) & 0x70))

// ---------------- scratch (device globals; no runtime allocation) ----------
__device__ float g_xg[(size_t)Bn * Tn * G4H];
__device__ float g_h0all[(size_t)Bn * Tn * Hn];
__device__ float g_hfin[Bn * Hn];
__device__ float g_z[Bn * FCn];
// bf16 h state double buffers (hi/lo split)
__device__ __nv_bfloat16 g_hXhi[Bn * Hn], g_hXlo[Bn * Hn];
__device__ __nv_bfloat16 g_hYhi[Bn * Hn], g_hYlo[Bn * Hn];
// prepacked recurrent weights, bf16 hi/lo, [layer][u_tile(32)][chunk(8)][64n x 64k swizzled]
__device__ __nv_bfloat16 g_Whh_hi[2][(size_t)G4H * Hn];
__device__ __nv_bfloat16 g_Whh_lo[2][(size_t)G4H * Hn];
// bf16 hi/lo pre-swizzled W_ih for mma gemm
__device__ uint4 g_Wb0hi[G4H * Dn / 8],  g_Wb0lo[G4H * Dn / 8];   // layer0: 2048x64
__device__ uint4 g_Wb1hi[G4H * Hn / 8],  g_Wb1lo[G4H * Hn / 8];   // layer1: 2048x512

// ---------------- f32x2 packed helpers (fp32 FC1 gemm) ----------------------
__device__ __forceinline__ void ffma2(ull& d, ull a, ull b) {
    asm("fma.rn.f32x2 %0, %1, %2, %0;" : "+l"(d) : "l"(a), "l"(b));
}
__device__ __forceinline__ ull pack2dup(float x) {
    ull r; asm("mov.b64 %0, {%1, %1};" : "=l"(r) : "f"(x)); return r;
}
__device__ __forceinline__ float2 unpack2(ull v) {
    float2 f; asm("mov.b64 {%0, %1}, %2;" : "=f"(f.x), "=f"(f.y) : "l"(v)); return f;
}

// ---------------- fast activations ------------------------------------------
__device__ __forceinline__ float fsig(float x) {
    return __fdividef(1.f, 1.f + __expf(-x));
}
__device__ __forceinline__ float ftanh(float x) {
    return 1.f - __fdividef(2.f, 1.f + __expf(2.f * x));
}

// ---------------- cp.async helpers -----------------------------------------
__device__ __forceinline__ void cp_async16(void* smem_dst, const void* gmem_src) {
    unsigned saddr = (unsigned)__cvta_generic_to_shared(smem_dst);
    asm volatile("cp.async.cg.shared.global [%0], [%1], 16;" :: "r"(saddr), "l"(gmem_src));
}
__device__ __forceinline__ void cp_async16u(unsigned saddr, const void* gmem_src) {
    asm volatile("cp.async.cg.shared.global [%0], [%1], 16;" :: "r"(saddr), "l"(gmem_src));
}
__device__ __forceinline__ void cp_commit() { asm volatile("cp.async.commit_group;"); }
__device__ __forceinline__ void cp_wait0()  { asm volatile("cp.async.wait_group 0;" ::: "memory"); }
__device__ __forceinline__ void cp_wait1()  { asm volatile("cp.async.wait_group 1;" ::: "memory"); }

__device__ __forceinline__ unsigned smem_u32(const void* p) {
    return (unsigned)__cvta_generic_to_shared(p);
}
__device__ __forceinline__ uint32_t cvt_bf16x2(float hi, float lo) {
    uint32_t r; asm("cvt.rn.bf16x2.f32 %0, %1, %2;" : "=r"(r) : "f"(hi), "f"(lo)); return r;
}

// ---------------- warp-level mma helpers ------------------------------------
__device__ __forceinline__ void ldsm_x4(uint32_t& r0, uint32_t& r1, uint32_t& r2, uint32_t& r3,
                                        uint32_t addr) {
    asm volatile("ldmatrix.sync.aligned.m8n8.x4.shared.b16 {%0,%1,%2,%3}, [%4];"
                 : "=r"(r0), "=r"(r1), "=r"(r2), "=r"(r3) : "r"(addr));
}
__device__ __forceinline__ void mma_bf16(float* d, const uint32_t* a, const uint32_t* b) {
    asm volatile("mma.sync.aligned.m16n8k16.row.col.f32.bf16.bf16.f32 "
                 "{%0,%1,%2,%3}, {%4,%5,%6,%7}, {%8,%9}, {%0,%1,%2,%3};"
                 : "+f"(d[0]), "+f"(d[1]), "+f"(d[2]), "+f"(d[3])
                 : "r"(a[0]), "r"(a[1]), "r"(a[2]), "r"(a[3]), "r"(b[0]), "r"(b[1]));
}

// ---------------- per-m-group barrier (generation based, replay-safe) ------
struct __align__(128) BarSlot { unsigned count; unsigned gen; unsigned pad[30]; };
__device__ BarSlot g_bar[MGRPS];

__device__ __forceinline__ void group_barrier(int grp) {
    __syncthreads();
    __threadfence();
    if (threadIdx.x == 0) {
        unsigned gen = atomicAdd(&g_bar[grp].gen, 0u);
        unsigned arrived = atomicAdd(&g_bar[grp].count, 1u);
        if (arrived == GRP_BLOCKS - 1u) {
            atomicExch(&g_bar[grp].count, 0u);
            __threadfence();
            atomicExch(&g_bar[grp].gen, gen + 1u);
        } else {
            while (atomicAdd(&g_bar[grp].gen, 0u) == gen) { __nanosleep(20); }
        }
    }
    __syncthreads();
}

// ---------------- weight pre-pack kernels -----------------------------------
// Whh [4H, H] -> per u-tile (16 units x 4 gates = 64 n-cols) x 8 k-chunks,
// each chunk a 64n x 64k bf16 tile, SW128 swizzled. hi/lo split.
__global__ void prepack_whh(const float* __restrict__ Whh,
                            __nv_bfloat16* __restrict__ hi,
                            __nv_bfloat16* __restrict__ lo)
{
    int i = blockIdx.x * blockDim.x + threadIdx.x;   // 0 .. 2048*512-1
    int k = i & 511;
    int row = i >> 9;                                 // gate*512 + unit_global
    int gate = row >> 9;
    int ug = row & 511;
    int bu = ug >> 4, un = ug & 15;
    int n = gate * 16 + un;                           // 0..63 within tile
    int c = k >> 6, lk = k & 63;
    size_t off = ((size_t)(bu * 8 + c)) * 4096 + (SWZ128(n * 128 + lk * 2) >> 1);
    float w = Whh[(size_t)row * Hn + k];
    __nv_bfloat16 h = __float2bfloat16(w);
    hi[off] = h;
    lo[off] = __float2bfloat16(w - __bfloat162float(h));
}

// Split W (N=2048 x K) into bf16 hi/lo, per (ntile, kchunk) 64x64 tile, SW128.
__global__ void prepack_b_kernel(const float* __restrict__ W,
                                 __nv_bfloat16* __restrict__ hi,
                                 __nv_bfloat16* __restrict__ lo,
                                 int K)
{
    int i = blockIdx.x * blockDim.x + threadIdx.x;
    int k = i % K;
    int n = i / K;
    int ntile = n >> 6, ln = n & 63;
    int kc = k >> 6, lk = k & 63;
    int nch = K >> 6;
    size_t off = ((size_t)(ntile * nch + kc)) * 4096 + (SWZ128(ln * 128 + lk * 2) >> 1);
    float w = W[(size_t)n * K + k];
    __nv_bfloat16 h = __float2bfloat16(w);
    hi[off] = h;
    lo[off] = __float2bfloat16(w - __bfloat162float(h));
}

// ---------------- HMMA split-bf16 GEMM: C = A @ W^T + b1 (+b2) -------------
#define MMAG_SMEM (49152 + 1024)
__global__ void __launch_bounds__(256, 2)
mma_gemm_kernel(const float* __restrict__ A,
                const uint4* __restrict__ Wbhi,
                const uint4* __restrict__ Wblo,
                const float* __restrict__ b1,
                const float* __restrict__ b2,
                float* __restrict__ C,
                int K, int Ntot)
{
    extern __shared__ char dsm[];
    uint32_t usm = smem_u32(dsm);
    usm = (usm + 1023u) & ~1023u;
    const uint32_t uAhi = usm;
    const uint32_t uAlo = usm + 16384;
    const uint32_t uBhi = usm + 32768;
    const uint32_t uBlo = usm + 40960;

    const int bn = blockIdx.x;
    const int m0 = blockIdx.y * 128;
    const int n0 = bn * 64;
    const int tid = threadIdx.x;
    const int w = tid >> 5;
    const int lane = tid & 31;
    const int mw = (w & 3) * 32;
    const int nw = (w >> 2) * 32;
    const int nch = K >> 6;

    const uint32_t xorv  = (uint32_t)(lane & 7) << 4;
    const uint32_t aRow  = mw + (lane & 15);
    const uint32_t aKsel = (uint32_t)(lane >> 4) << 4;
    const uint32_t bRow  = nw + (lane & 7) + ((lane >> 4) << 3);
    const uint32_t bKsel = (uint32_t)((lane >> 3) & 1) << 4;

    float acc[2][4][4];
#pragma unroll
    for (int mt = 0; mt < 2; mt++)
#pragma unroll
        for (int nt = 0; nt < 4; nt++)
#pragma unroll
            for (int e = 0; e < 4; e++) acc[mt][nt][e] = 0.f;

    for (int c = 0; c < nch; c++) {
        if (c) __syncthreads();

        const uint4* sbh = Wbhi + ((size_t)bn * nch + c) * 512;
        const uint4* sbl = Wblo + ((size_t)bn * nch + c) * 512;
        cp_async16u(uBhi + (uint32_t)tid * 16,         sbh + tid);
        cp_async16u(uBhi + (uint32_t)(tid + 256) * 16, sbh + tid + 256);
        cp_async16u(uBlo + (uint32_t)tid * 16,         sbl + tid);
        cp_async16u(uBlo + (uint32_t)(tid + 256) * 16, sbl + tid + 256);
        cp_commit();

        const int k0 = c * 64;
#pragma unroll
        for (int it = 0; it < 8; it++) {
            int idx = tid + it * 256;
            int r = idx >> 4, f4 = idx & 15;
            float4 v = *(const float4*)(A + (size_t)(m0 + r) * K + k0 + f4 * 4);
            uint32_t h01 = cvt_bf16x2(v.y, v.x);
            uint32_t h23 = cvt_bf16x2(v.w, v.z);
            float f0 = __uint_as_float(h01 << 16);
            float f1 = __uint_as_float(h01 & 0xffff0000u);
            float f2 = __uint_as_float(h23 << 16);
            float f3 = __uint_as_float(h23 & 0xffff0000u);
            uint32_t l01 = cvt_bf16x2(v.y - f1, v.x - f0);
            uint32_t l23 = cvt_bf16x2(v.w - f3, v.z - f2);
            uint32_t sw = (uint32_t)r * 128 + (((uint32_t)f4 * 8) ^ (((uint32_t)r & 7) << 4));
            asm volatile("st.shared.v2.u32 [%0], {%1,%2};" :: "r"(uAhi + sw), "r"(h01), "r"(h23));
            asm volatile("st.shared.v2.u32 [%0], {%1,%2};" :: "r"(uAlo + sw), "r"(l01), "r"(l23));
        }
        cp_wait0();
        __syncthreads();

#pragma unroll
        for (int ks = 0; ks < 4; ks++) {
            const uint32_t kbA = ((uint32_t)(32 * ks) + aKsel) ^ xorv;
            const uint32_t kbB = ((uint32_t)(32 * ks) + bKsel) ^ xorv;
            uint32_t ah0[4], ah1[4], al0[4], al1[4];
            ldsm_x4(ah0[0], ah0[1], ah0[2], ah0[3], uAhi + aRow * 128 + kbA);
            ldsm_x4(ah1[0], ah1[1], ah1[2], ah1[3], uAhi + (aRow + 16) * 128 + kbA);
            ldsm_x4(al0[0], al0[1], al0[2], al0[3], uAlo + aRow * 128 + kbA);
            ldsm_x4(al1[0], al1[1], al1[2], al1[3], uAlo + (aRow + 16) * 128 + kbA);
            uint32_t bh[8], bl[8];
            ldsm_x4(bh[0], bh[1], bh[2], bh[3], uBhi + bRow * 128 + kbB);
            ldsm_x4(bh[4], bh[5], bh[6], bh[7], uBhi + (bRow + 16) * 128 + kbB);
            ldsm_x4(bl[0], bl[1], bl[2], bl[3], uBlo + bRow * 128 + kbB);
            ldsm_x4(bl[4], bl[5], bl[6], bl[7], uBlo + (bRow + 16) * 128 + kbB);
#pragma unroll
            for (int mt = 0; mt < 2; mt++) {
                const uint32_t* Ah = mt ? ah1 : ah0;
                const uint32_t* Al = mt ? al1 : al0;
#pragma unroll
                for (int nt = 0; nt < 4; nt++) {
                    mma_bf16(acc[mt][nt], Ah, bh + nt * 2);
                    mma_bf16(acc[mt][nt], Ah, bl + nt * 2);
                    mma_bf16(acc[mt][nt], Al, bh + nt * 2);
                }
            }
        }
    }

    const int gid = lane >> 2, tig = lane & 3;
    float2 bias[4];
#pragma unroll
    for (int nt = 0; nt < 4; nt++) {
        int col = n0 + nw + nt * 8 + tig * 2;
        bias[nt].x = b1[col]     + (b2 ? b2[col]     : 0.f);
        bias[nt].y = b1[col + 1] + (b2 ? b2[col + 1] : 0.f);
    }
#pragma unroll
    for (int mt = 0; mt < 2; mt++) {
        int row0 = m0 + mw + mt * 16 + gid;
#pragma unroll
        for (int nt = 0; nt < 4; nt++) {
            int col = n0 + nw + nt * 8 + tig * 2;
            float2 v0, v1;
            v0.x = acc[mt][nt][0] + bias[nt].x;
            v0.y = acc[mt][nt][1] + bias[nt].y;
            v1.x = acc[mt][nt][2] + bias[nt].x;
            v1.y = acc[mt][nt][3] + bias[nt].y;
            *(float2*)&C[(size_t)row0 * Ntot + col]       = v0;
            *(float2*)&C[(size_t)(row0 + 8) * Ntot + col] = v1;
        }
    }
}

// ---------------- persistent HMMA LSTM layer kernel -------------------------
// Grid (32, 4): block = 16 units x 4 gates (64 n-cols) x 64 batch rows.
// Whh slice (64n x 512k bf16 hi/lo = 128KB) resident in smem for all steps.
// h kept as bf16 hi/lo global arrays; staged per step via 3-buffer cp.async.
#define STEP_SMEM (181248)
__global__ void __launch_bounds__(256)
lstm_layer_mma(const float* __restrict__ xg,        // [B, T, 4H]
               const uint4* __restrict__ Whi,       // prepacked, this layer
               const uint4* __restrict__ Wlo,
               __nv_bfloat16* __restrict__ hXhi, __nv_bfloat16* __restrict__ hXlo,
               __nv_bfloat16* __restrict__ hYhi, __nv_bfloat16* __restrict__ hYlo,
               float* __restrict__ h_all,           // layer0: [B,T,H]; else null
               float* __restrict__ h_final)         // layer1: [B,H]; else null
{
    __shared__ float sG[64 * 65];                   // gate tile, stride 65
    extern __shared__ char dsm[];
    uint32_t usm = smem_u32(dsm);
    usm = (usm + 1023u) & ~1023u;
    const uint32_t uWhi = usm;                      // 8 chunks x 8KB = 64KB
    const uint32_t uWlo = usm + 65536;              // 64KB
    const uint32_t uAb  = usm + 131072;             // 3 bufs x (8KB hi + 8KB lo)

    const int bu  = blockIdx.x;                     // u-tile 0..31
    const int grp = blockIdx.y;                     // m-group 0..3
    const int m0  = grp * 64;
    const int tid = threadIdx.x;
    const int w   = tid >> 5;
    const int lane = tid & 31;
    const int mw = (w & 1) * 32;
    const int nw = (w >> 1) * 16;

    const uint32_t xorv  = (uint32_t)(lane & 7) << 4;
    const uint32_t aRow  = mw + (lane & 15);
    const uint32_t aKsel = (uint32_t)(lane >> 4) << 4;
    const uint32_t bRow  = nw + (lane & 7) + ((lane >> 4) << 3);
    const uint32_t bKsel = (uint32_t)((lane >> 3) & 1) << 4;
    const int gid = lane >> 2, tig = lane & 3;

    // ---- load resident weights (once) ----
    {
        const uint4* sh = Whi + (size_t)bu * 4096;
        const uint4* sl = Wlo + (size_t)bu * 4096;
#pragma unroll
        for (int j = 0; j < 16; j++) {
            int idx = tid + j * 256;
            cp_async16u(uWhi + (uint32_t)idx * 16, sh + idx);
            cp_async16u(uWlo + (uint32_t)idx * 16, sl + idx);
        }
        cp_commit();
        cp_wait0();
        __syncthreads();
    }

    // ---- per-thread cell mapping: m = tid&63, units ugq*4 .. +3 ----
    const int cm  = tid & 63;
    const int ugq = tid >> 6;                        // 0..3
    const int grow = m0 + cm;                        // global batch row
    const int gcol = bu * 16 + ugq * 4;              // global unit col (x4)

    float creg[4] = {0.f, 0.f, 0.f, 0.f};
    float xvf[4][4];                                 // [gate][j]
    {
        const float* xr = xg + ((size_t)grow * Tn + 0) * G4H + gcol;
#pragma unroll
        for (int g = 0; g < 4; g++)
            *(float4*)&xvf[g][0] = __ldcg((const float4*)(xr + g * 512));
    }

    for (int t = 0; t < Tn; t++) {
        const __nv_bfloat16* hin_hi = (t & 1) ? hXhi : hYhi;
        const __nv_bfloat16* hin_lo = (t & 1) ? hXlo : hYlo;
        __nv_bfloat16* hout_hi      = (t & 1) ? hYhi : hXhi;
        __nv_bfloat16* hout_lo      = (t & 1) ? hYlo : hXlo;

        if (t > 0) {
            float acc[2][2][4];
#pragma unroll
            for (int mt = 0; mt < 2; mt++)
#pragma unroll
                for (int nt = 0; nt < 2; nt++)
#pragma unroll
                    for (int e = 0; e < 4; e++) acc[mt][nt][e] = 0.f;

            // chunk 0 staged at end of previous step (after barrier)
            for (int c = 0; c < 8; c++) {
                if (c < 7) {
                    // stage chunk c+1 into buf (c+1)%3
                    const uint32_t ub = uAb + (uint32_t)((c + 1) % 3) * 16384;
                    const int kb = (c + 1) * 64;
#pragma unroll
                    for (int j = 0; j < 2; j++) {
                        int idx = tid + j * 256;                 // 0..511
                        int r = idx >> 3, q = idx & 7;
                        uint32_t sw = SWZ128((uint32_t)r * 128 + (uint32_t)q * 16);
                        cp_async16u(ub + sw,        hin_hi + (size_t)(m0 + r) * Hn + kb + q * 8);
                        cp_async16u(ub + 8192 + sw, hin_lo + (size_t)(m0 + r) * Hn + kb + q * 8);
                    }
                    cp_commit();
                    cp_wait1();
                } else {
                    cp_wait0();
                }
                __syncthreads();

                const uint32_t uA = uAb + (uint32_t)(c % 3) * 16384;
                const uint32_t wh = uWhi + (uint32_t)c * 8192;
                const uint32_t wl = uWlo + (uint32_t)c * 8192;
#pragma unroll
                for (int ks = 0; ks < 4; ks++) {
                    const uint32_t kbA = ((uint32_t)(32 * ks) + aKsel) ^ xorv;
                    const uint32_t kbB = ((uint32_t)(32 * ks) + bKsel) ^ xorv;
                    uint32_t ah0[4], ah1[4], al0[4], al1[4];
                    ldsm_x4(ah0[0], ah0[1], ah0[2], ah0[3], uA + aRow * 128 + kbA);
                    ldsm_x4(ah1[0], ah1[1], ah1[2], ah1[3], uA + (aRow + 16) * 128 + kbA);
                    ldsm_x4(al0[0], al0[1], al0[2], al0[3], uA + 8192 + aRow * 128 + kbA);
                    ldsm_x4(al1[0], al1[1], al1[2], al1[3], uA + 8192 + (aRow + 16) * 128 + kbA);
                    uint32_t bh[4], bl[4];
                    ldsm_x4(bh[0], bh[1], bh[2], bh[3], wh + bRow * 128 + kbB);
                    ldsm_x4(bl[0], bl[1], bl[2], bl[3], wl + bRow * 128 + kbB);
#pragma unroll
                    for (int mt = 0; mt < 2; mt++) {
                        const uint32_t* Ah = mt ? ah1 : ah0;
                        const uint32_t* Al = mt ? al1 : al0;
#pragma unroll
                        for (int nt = 0; nt < 2; nt++) {
                            mma_bf16(acc[mt][nt], Ah, bh + nt * 2);
                            mma_bf16(acc[mt][nt], Ah, bl + nt * 2);
                            mma_bf16(acc[mt][nt], Al, bh + nt * 2);
                        }
                    }
                }
            }

            // fragments -> sG
            __syncthreads();
#pragma unroll
            for (int mt = 0; mt < 2; mt++) {
                int r0 = mw + mt * 16 + gid;
#pragma unroll
                for (int nt = 0; nt < 2; nt++) {
                    int nc = nw + nt * 8 + tig * 2;
                    sG[r0 * 65 + nc]           = acc[mt][nt][0];
                    sG[r0 * 65 + nc + 1]       = acc[mt][nt][1];
                    sG[(r0 + 8) * 65 + nc]     = acc[mt][nt][2];
                    sG[(r0 + 8) * 65 + nc + 1] = acc[mt][nt][3];
                }
            }
            __syncthreads();
        }

        // ---- cell update: 4 cells per thread ----
        float hn4[4];
#pragma unroll
        for (int j = 0; j < 4; j++) {
            int uloc = ugq * 4 + j;
            float ri = 0.f, rf = 0.f, rg = 0.f, ro = 0.f;
            if (t > 0) {
                ri = sG[cm * 65 + uloc];
                rf = sG[cm * 65 + 16 + uloc];
                rg = sG[cm * 65 + 32 + uloc];
                ro = sG[cm * 65 + 48 + uloc];
            }
            float gi = ri + xvf[0][j];
            float gf = rf + xvf[1][j];
            float gg = rg + xvf[2][j];
            float go = ro + xvf[3][j];
            float cn = fsig(gf) * creg[j] + fsig(gi) * ftanh(gg);
            creg[j] = cn;
            hn4[j] = fsig(go) * ftanh(cn);
        }
        // write h hi/lo (bf16)
        {
            uint32_t hi01 = cvt_bf16x2(hn4[1], hn4[0]);
            uint32_t hi23 = cvt_bf16x2(hn4[3], hn4[2]);
            float r0 = hn4[0] - __uint_as_float(hi01 << 16);
            float r1 = hn4[1] - __uint_as_float(hi01 & 0xffff0000u);
            float r2 = hn4[2] - __uint_as_float(hi23 << 16);
            float r3 = hn4[3] - __uint_as_float(hi23 & 0xffff0000u);
            uint32_t lo01 = cvt_bf16x2(r1, r0);
            uint32_t lo23 = cvt_bf16x2(r3, r2);
            size_t ho = (size_t)grow * Hn + gcol;
            *(uint2*)(hout_hi + ho) = make_uint2(hi01, hi23);
            *(uint2*)(hout_lo + ho) = make_uint2(lo01, lo23);
        }
        if (h_all) {
            float4 v = make_float4(hn4[0], hn4[1], hn4[2], hn4[3]);
            *(float4*)&h_all[((size_t)grow * Tn + t) * Hn + gcol] = v;
        }
        if (h_final && t == Tn - 1) {
            float4 v = make_float4(hn4[0], hn4[1], hn4[2], hn4[3]);
            *(float4*)&h_final[(size_t)grow * Hn + gcol] = v;
        }

        if (t < Tn - 1) {
            // prefetch xg for t+1 (h-independent)
            const float* xr = xg + ((size_t)grow * Tn + (t + 1)) * G4H + gcol;
#pragma unroll
            for (int g = 0; g < 4; g++)
                *(float4*)&xvf[g][0] = __ldcg((const float4*)(xr + g * 512));

            group_barrier(grp);

            // stage chunk 0 of next h_in into buf 0
            const __nv_bfloat16* nhi = (t & 1) ? hYhi : hXhi;   // == hout of this step
            const __nv_bfloat16* nlo = (t & 1) ? hYlo : hXlo;
#pragma unroll
            for (int j = 0; j < 2; j++) {
                int idx = tid + j * 256;
                int r = idx >> 3, q = idx & 7;
                uint32_t sw = SWZ128((uint32_t)r * 128 + (uint32_t)q * 16);
                cp_async16u(uAb + sw,        nhi + (size_t)(m0 + r) * Hn + q * 8);
                cp_async16u(uAb + 8192 + sw, nlo + (size_t)(m0 + r) * Hn + q * 8);
            }
            cp_commit();
        }
    }
}

// ---------------- fp32 tiled GEMM (kept for FC1) ----------------------------
__global__ void __launch_bounds__(256, 2)
gemm_bias_kernel(const float* __restrict__ A,
                 const float* __restrict__ W,
                 const float* __restrict__ b1,
                 const float* __restrict__ b2,
                 float* __restrict__ C,
                 int M, int N, int K, int relu)
{
    __shared__ __align__(16) float As[2][128][GKC];
    __shared__ __align__(16) float Bs[2][GKC][64];
    const int m0 = blockIdx.y * 128;
    const int n0 = blockIdx.x * 64;
    const int tid = threadIdx.x;
    const int cx = tid & 15;
    const int ry = tid >> 4;

    ull acc01[8], acc23[8];
#pragma unroll
    for (int i = 0; i < 8; i++) { acc01[i] = 0ull; acc23[i] = 0ull; }

    const int nch = K / GKC;
    const int bcol = tid & 63, bq = tid >> 6;

#pragma unroll
    for (int i = 0; i < 2; i++) {
        int idx = tid + i * 256;
        cp_async16(&As[0][idx >> 2][(idx & 3) * 4],
                   A + (size_t)(m0 + (idx >> 2)) * K + (idx & 3) * 4);
    }
    cp_commit();
    float4 pW = *(const float4*)(W + (size_t)(n0 + bcol) * K + bq * 4);
    Bs[0][bq * 4 + 0][bcol] = pW.x;
    Bs[0][bq * 4 + 1][bcol] = pW.y;
    Bs[0][bq * 4 + 2][bcol] = pW.z;
    Bs[0][bq * 4 + 3][bcol] = pW.w;

    for (int c = 0; c < nch; c++) {
        cp_wait0();
        __syncthreads();
        const int buf = c & 1;
        const bool more = (c + 1 < nch);
        if (more) {
            int k0 = (c + 1) * GKC;
#pragma unroll
            for (int i = 0; i < 2; i++) {
                int idx = tid + i * 256;
                cp_async16(&As[buf ^ 1][idx >> 2][(idx & 3) * 4],
                           A + (size_t)(m0 + (idx >> 2)) * K + k0 + (idx & 3) * 4);
            }
            cp_commit();
            pW = *(const float4*)(W + (size_t)(n0 + bcol) * K + k0 + bq * 4);
        }
#pragma unroll
        for (int k4 = 0; k4 < GKC; k4 += 4) {
            float4 a4[8];
#pragma unroll
            for (int i = 0; i < 8; i++) a4[i] = *(const float4*)&As[buf][ry + 16 * i][k4];
#pragma unroll
            for (int j = 0; j < 4; j++) {
                float4 w4 = *(const float4*)&Bs[buf][k4 + j][4 * cx];
                ull w01 = *reinterpret_cast<ull*>(&w4.x);
                ull w23 = *reinterpret_cast<ull*>(&w4.z);
#pragma unroll
                for (int i = 0; i < 8; i++) {
                    float av = (j == 0) ? a4[i].x : (j == 1) ? a4[i].y : (j == 2) ? a4[i].z : a4[i].w;
                    ull ad = pack2dup(av);
                    ffma2(acc01[i], ad, w01);
                    ffma2(acc23[i], ad, w23);
                }
            }
        }
        if (more) {
            Bs[buf ^ 1][bq * 4 + 0][bcol] = pW.x;
            Bs[buf ^ 1][bq * 4 + 1][bcol] = pW.y;
            Bs[buf ^ 1][bq * 4 + 2][bcol] = pW.z;
            Bs[buf ^ 1][bq * 4 + 3][bcol] = pW.w;
        }
    }

    const int col = n0 + 4 * cx;
    float bb0 = b1[col + 0], bb1 = b1[col + 1], bb2 = b1[col + 2], bb3 = b1[col + 3];
    if (b2) { bb0 += b2[col + 0]; bb1 += b2[col + 1]; bb2 += b2[col + 2]; bb3 += b2[col + 3]; }
#pragma unroll
    for (int i = 0; i < 8; i++) {
        int row = m0 + ry + 16 * i;
        float2 p01 = unpack2(acc01[i]);
        float2 p23 = unpack2(acc23[i]);
        float4 v;
        v.x = p01.x + bb0; v.y = p01.y + bb1; v.z = p23.x + bb2; v.w = p23.y + bb3;
        if (relu) { v.x = fmaxf(v.x, 0.f); v.y = fmaxf(v.y, 0.f); v.z = fmaxf(v.z, 0.f); v.w = fmaxf(v.w, 0.f); }
        *(float4*)&C[(size_t)row * N + col] = v;
    }
}

// ---------------- FC2: out[256,8] = z @ W_fc2^T + b ------------------------
__global__ void fc2_kernel(const float* __restrict__ z,
                           const float* __restrict__ W,
                           const float* __restrict__ b,
                           float* __restrict__ out)
{
    int row = blockIdx.x;
    int o = threadIdx.y;
    int lane = threadIdx.x;
    float s = 0.f;
    const float* zr = z + (size_t)row * FCn;
    const float* wr = W + (size_t)o * FCn;
    for (int k = lane; k < FCn; k += 32) s += zr[k] * wr[k];
#pragma unroll
    for (int off = 16; off; off >>= 1) s += __shfl_down_sync(0xffffffffu, s, off);
    if (lane == 0) out[row * OUTn + o] = s + b[o];
}

// ---------------- host orchestration ---------------------------------------
extern "C" void kernel_launch(void* const* d_in, const int* in_sizes, int n_in,
                              void* d_out, int out_size)
{
    const float* x      = (const float*)d_in[0];
    const float* W_ih0  = (const float*)d_in[1];
    const float* W_hh0  = (const float*)d_in[2];
    const float* b_ih0  = (const float*)d_in[3];
    const float* b_hh0  = (const float*)d_in[4];
    const float* W_ih1  = (const float*)d_in[5];
    const float* W_hh1  = (const float*)d_in[6];
    const float* b_ih1  = (const float*)d_in[7];
    const float* b_hh1  = (const float*)d_in[8];
    const float* W_fc1  = (const float*)d_in[9];
    const float* b_fc1  = (const float*)d_in[10];
    const float* W_fc2  = (const float*)d_in[11];
    const float* b_fc2  = (const float*)d_in[12];
    float* out = (float*)d_out;

    float *xg, *h0all, *hfin, *z;
    __nv_bfloat16 *hXhi, *hXlo, *hYhi, *hYlo, *whhHi, *whhLo;
    uint4 *wb0h, *wb0l, *wb1h, *wb1l;
    cudaGetSymbolAddress((void**)&xg,    g_xg);
    cudaGetSymbolAddress((void**)&h0all, g_h0all);
    cudaGetSymbolAddress((void**)&hfin,  g_hfin);
    cudaGetSymbolAddress((void**)&z,     g_z);
    cudaGetSymbolAddress((void**)&hXhi,  g_hXhi);
    cudaGetSymbolAddress((void**)&hXlo,  g_hXlo);
    cudaGetSymbolAddress((void**)&hYhi,  g_hYhi);
    cudaGetSymbolAddress((void**)&hYlo,  g_hYlo);
    cudaGetSymbolAddress((void**)&whhHi, g_Whh_hi);
    cudaGetSymbolAddress((void**)&whhLo, g_Whh_lo);
    cudaGetSymbolAddress((void**)&wb0h,  g_Wb0hi);
    cudaGetSymbolAddress((void**)&wb0l,  g_Wb0lo);
    cudaGetSymbolAddress((void**)&wb1h,  g_Wb1hi);
    cudaGetSymbolAddress((void**)&wb1l,  g_Wb1lo);

    cudaFuncSetAttribute(mma_gemm_kernel, cudaFuncAttributeMaxDynamicSharedMemorySize, MMAG_SMEM);
    cudaFuncSetAttribute(lstm_layer_mma,  cudaFuncAttributeMaxDynamicSharedMemorySize, STEP_SMEM);

    const int MT = Bn * Tn;                 // 131072
    dim3 mmaGrid(G4H / 64, MT / 128);       // (32, 1024)
    dim3 stepGrid(32, MGRPS);               // (32, 4) = 128 blocks

    const size_t WHL = (size_t)G4H * Hn;    // per-layer whh elements
    prepack_whh<<<(G4H * Hn) / 256, 256>>>(W_hh0, whhHi, whhLo);
    prepack_whh<<<(G4H * Hn) / 256, 256>>>(W_hh1, whhHi + WHL, whhLo + WHL);
    prepack_b_kernel<<<(G4H * Dn) / 256, 256>>>(W_ih0, (__nv_bfloat16*)wb0h, (__nv_bfloat16*)wb0l, Dn);
    prepack_b_kernel<<<(G4H * Hn) / 256, 256>>>(W_ih1, (__nv_bfloat16*)wb1h, (__nv_bfloat16*)wb1l, Hn);

    // ---- Layer 0 ----
    mma_gemm_kernel<<<mmaGrid, 256, MMAG_SMEM>>>(x, wb0h, wb0l, b_ih0, b_hh0, xg, Dn, G4H);
    lstm_layer_mma<<<stepGrid, 256, STEP_SMEM>>>(xg, (const uint4*)whhHi, (const uint4*)whhLo,
                                                 hXhi, hXlo, hYhi, hYlo, h0all, (float*)0);

    // ---- Layer 1 ----
    mma_gemm_kernel<<<mmaGrid, 256, MMAG_SMEM>>>(h0all, wb1h, wb1l, b_ih1, b_hh1, xg, Hn, G4H);
    lstm_layer_mma<<<stepGrid, 256, STEP_SMEM>>>(xg, (const uint4*)(whhHi + WHL), (const uint4*)(whhLo + WHL),
                                                 hXhi, hXlo, hYhi, hYlo, (float*)0, hfin);

    // ---- FC head ----
    dim3 fc1Grid(FCn / 64, Bn / 128);       // (8, 2)
    gemm_bias_kernel<<<fc1Grid, 256>>>(hfin, W_fc1, b_fc1, (const float*)0, z, Bn, FCn, Hn, 1);
    fc2_kernel<<<Bn, dim3(32, 8)>>>(z, W_fc2, b_fc2, out);
}

// round 9
// speedup vs baseline: 4.5621x; 1.3048x over previous
#include <cuda_runtime.h>
#include <cuda_fp16.h>
#include <cstddef>
#include <cstdint>

// Problem constants
#define Bn   256
#define Tn   512
#define Dn   64
#define Hn   512
#define G4H  2048   // 4*H
#define FCn  512
#define OUTn 8

#define GKC   16          // k-chunk in fp32 gemm kernel
#define MGRPS 4           // m-groups (Bn/64)
#define GRP_BLOCKS 32     // blocks per m-group (2048 cols / 64)

typedef unsigned long long ull;

#define SWZ128(off) ((off) ^ (((off) >> 3) & 0x70))

// ---------------- scratch (device globals; no runtime allocation) ----------
__device__ float g_xg[(size_t)Bn * Tn * G4H];
__device__ __half g_h0h[(size_t)Bn * Tn * Hn];     // layer-0 h, fp16 (feeds layer-1 GEMM)
__device__ float g_hfin[Bn * Hn];
__device__ float g_z[Bn * FCn];
// fp16 h state double buffers (hi only)
__device__ __half g_hX[Bn * Hn], g_hY[Bn * Hn];
// prepacked recurrent weights, fp16 hi/lo, [layer][u_tile(32)][chunk(8)][64n x 64k swizzled]
__device__ __half g_Whh_hi[2][(size_t)G4H * Hn];
__device__ __half g_Whh_lo[2][(size_t)G4H * Hn];
// fp16 hi/lo pre-swizzled W_ih for mma gemm
__device__ uint4 g_Wb0hi[G4H * Dn / 8],  g_Wb0lo[G4H * Dn / 8];   // layer0: 2048x64
__device__ uint4 g_Wb1hi[G4H * Hn / 8],  g_Wb1lo[G4H * Hn / 8];   // layer1: 2048x512

// ---------------- f32x2 packed helpers (fp32 FC1 gemm) ----------------------
__device__ __forceinline__ void ffma2(ull& d, ull a, ull b) {
    asm("fma.rn.f32x2 %0, %1, %2, %0;" : "+l"(d) : "l"(a), "l"(b));
}
__device__ __forceinline__ ull pack2dup(float x) {
    ull r; asm("mov.b64 %0, {%1, %1};" : "=l"(r) : "f"(x)); return r;
}
__device__ __forceinline__ float2 unpack2(ull v) {
    float2 f; asm("mov.b64 {%0, %1}, %2;" : "=f"(f.x), "=f"(f.y) : "l"(v)); return f;
}

// ---------------- fast activations ------------------------------------------
__device__ __forceinline__ float fsig(float x) {
    return __fdividef(1.f, 1.f + __expf(-x));
}
__device__ __forceinline__ float ftanh(float x) {
    return 1.f - __fdividef(2.f, 1.f + __expf(2.f * x));
}

// ---------------- cp.async helpers -----------------------------------------
__device__ __forceinline__ void cp_async16(void* smem_dst, const void* gmem_src) {
    unsigned saddr = (unsigned)__cvta_generic_to_shared(smem_dst);
    asm volatile("cp.async.cg.shared.global [%0], [%1], 16;" :: "r"(saddr), "l"(gmem_src));
}
__device__ __forceinline__ void cp_async16u(unsigned saddr, const void* gmem_src) {
    asm volatile("cp.async.cg.shared.global [%0], [%1], 16;" :: "r"(saddr), "l"(gmem_src));
}
__device__ __forceinline__ void cp_commit() { asm volatile("cp.async.commit_group;"); }
__device__ __forceinline__ void cp_wait0()  { asm volatile("cp.async.wait_group 0;" ::: "memory"); }
__device__ __forceinline__ void cp_wait1()  { asm volatile("cp.async.wait_group 1;" ::: "memory"); }

__device__ __forceinline__ unsigned smem_u32(const void* p) {
    return (unsigned)__cvta_generic_to_shared(p);
}
// pack two fp32 -> f16x2 (hi in upper half, lo in lower half)
__device__ __forceinline__ uint32_t cvt_f16x2(float hi, float lo) {
    uint32_t r; asm("cvt.rn.f16x2.f32 %0, %1, %2;" : "=r"(r) : "f"(hi), "f"(lo)); return r;
}

// ---------------- warp-level mma helpers ------------------------------------
__device__ __forceinline__ void ldsm_x4(uint32_t& r0, uint32_t& r1, uint32_t& r2, uint32_t& r3,
                                        uint32_t addr) {
    asm volatile("ldmatrix.sync.aligned.m8n8.x4.shared.b16 {%0,%1,%2,%3}, [%4];"
                 : "=r"(r0), "=r"(r1), "=r"(r2), "=r"(r3) : "r"(addr));
}
__device__ __forceinline__ void mma_f16(float* d, const uint32_t* a, const uint32_t* b) {
    asm volatile("mma.sync.aligned.m16n8k16.row.col.f32.f16.f16.f32 "
                 "{%0,%1,%2,%3}, {%4,%5,%6,%7}, {%8,%9}, {%0,%1,%2,%3};"
                 : "+f"(d[0]), "+f"(d[1]), "+f"(d[2]), "+f"(d[3])
                 : "r"(a[0]), "r"(a[1]), "r"(a[2]), "r"(a[3]), "r"(b[0]), "r"(b[1]));
}

// ---------------- per-m-group barrier (generation based, replay-safe) ------
struct __align__(128) BarSlot { unsigned count; unsigned gen; unsigned pad[30]; };
__device__ BarSlot g_bar[MGRPS];

__device__ __forceinline__ void group_barrier(int grp) {
    __syncthreads();
    __threadfence();
    if (threadIdx.x == 0) {
        unsigned gen = atomicAdd(&g_bar[grp].gen, 0u);
        unsigned arrived = atomicAdd(&g_bar[grp].count, 1u);
        if (arrived == GRP_BLOCKS - 1u) {
            atomicExch(&g_bar[grp].count, 0u);
            __threadfence();
            atomicExch(&g_bar[grp].gen, gen + 1u);
        } else {
            while (atomicAdd(&g_bar[grp].gen, 0u) == gen) { __nanosleep(20); }
        }
    }
    __syncthreads();
}

// ---------------- weight pre-pack kernels -----------------------------------
// Whh [4H, H] -> per u-tile (16 units x 4 gates = 64 n-cols) x 8 k-chunks,
// each chunk a 64n x 64k fp16 tile, SW128 swizzled. hi/lo split.
__global__ void prepack_whh(const float* __restrict__ Whh,
                            __half* __restrict__ hi,
                            __half* __restrict__ lo)
{
    int i = blockIdx.x * blockDim.x + threadIdx.x;   // 0 .. 2048*512-1
    int k = i & 511;
    int row = i >> 9;                                 // gate*512 + unit_global
    int gate = row >> 9;
    int ug = row & 511;
    int bu = ug >> 4, un = ug & 15;
    int n = gate * 16 + un;                           // 0..63 within tile
    int c = k >> 6, lk = k & 63;
    size_t off = ((size_t)(bu * 8 + c)) * 4096 + (SWZ128(n * 128 + lk * 2) >> 1);
    float w = Whh[(size_t)row * Hn + k];
    __half h = __float2half(w);
    hi[off] = h;
    lo[off] = __float2half(w - __half2float(h));
}

// Split W (N=2048 x K) into fp16 hi/lo, per (ntile, kchunk) 64x64 tile, SW128.
__global__ void prepack_b_kernel(const float* __restrict__ W,
                                 __half* __restrict__ hi,
                                 __half* __restrict__ lo,
                                 int K)
{
    int i = blockIdx.x * blockDim.x + threadIdx.x;
    int k = i % K;
    int n = i / K;
    int ntile = n >> 6, ln = n & 63;
    int kc = k >> 6, lk = k & 63;
    int nch = K >> 6;
    size_t off = ((size_t)(ntile * nch + kc)) * 4096 + (SWZ128(ln * 128 + lk * 2) >> 1);
    float w = W[(size_t)n * K + k];
    __half h = __float2half(w);
    hi[off] = h;
    lo[off] = __float2half(w - __half2float(h));
}

// ---------------- HMMA fp16 2-term GEMM: C = A @ W^T + b1 (+b2) ------------
// A: [M,K] row-major, fp32 (converted to fp16-hi in-kernel) or fp16 (cp.async).
// W prepacked fp16 hi/lo swizzled 64x64 tiles. Terms: Ahi*Whi + Ahi*Wlo.
#define MMAG_SMEM (32768 + 1024)
__global__ void __launch_bounds__(256, 2)
mma_gemm_kernel(const void* __restrict__ Avoid,
                const uint4* __restrict__ Wbhi,
                const uint4* __restrict__ Wblo,
                const float* __restrict__ b1,
                const float* __restrict__ b2,
                float* __restrict__ C,
                int K, int Ntot, int a_f16)
{
    extern __shared__ char dsm[];
    uint32_t usm = smem_u32(dsm);
    usm = (usm + 1023u) & ~1023u;
    const uint32_t uAhi = usm;              // 128 x 64 fp16 = 16KB
    const uint32_t uBhi = usm + 16384;      // 8KB
    const uint32_t uBlo = usm + 24576;      // 8KB

    const int bn = blockIdx.x;
    const int m0 = blockIdx.y * 128;
    const int n0 = bn * 64;
    const int tid = threadIdx.x;
    const int w = tid >> 5;
    const int lane = tid & 31;
    const int mw = (w & 3) * 32;
    const int nw = (w >> 2) * 32;
    const int nch = K >> 6;

    const uint32_t xorv  = (uint32_t)(lane & 7) << 4;
    const uint32_t aRow  = mw + (lane & 15);
    const uint32_t aKsel = (uint32_t)(lane >> 4) << 4;
    const uint32_t bRow  = nw + (lane & 7) + ((lane >> 4) << 3);
    const uint32_t bKsel = (uint32_t)((lane >> 3) & 1) << 4;

    float acc[2][4][4];
#pragma unroll
    for (int mt = 0; mt < 2; mt++)
#pragma unroll
        for (int nt = 0; nt < 4; nt++)
#pragma unroll
            for (int e = 0; e < 4; e++) acc[mt][nt][e] = 0.f;

    for (int c = 0; c < nch; c++) {
        if (c) __syncthreads();

        // ---- stage B (cp.async, pre-swizzled fp16 hi/lo tiles) ----
        const uint4* sbh = Wbhi + ((size_t)bn * nch + c) * 512;
        const uint4* sbl = Wblo + ((size_t)bn * nch + c) * 512;
        cp_async16u(uBhi + (uint32_t)tid * 16,         sbh + tid);
        cp_async16u(uBhi + (uint32_t)(tid + 256) * 16, sbh + tid + 256);
        cp_async16u(uBlo + (uint32_t)tid * 16,         sbl + tid);
        cp_async16u(uBlo + (uint32_t)(tid + 256) * 16, sbl + tid + 256);

        if (a_f16) {
            // A already fp16 row-major: straight cp.async with swizzle
            const uint4* Af = (const uint4*)Avoid;
            const int krow = K >> 3;                 // uint4 per row
#pragma unroll
            for (int j = 0; j < 4; j++) {
                int idx = tid + j * 256;             // 0..1023
                int r = idx >> 3, q = idx & 7;
                cp_async16u(uAhi + SWZ128((uint32_t)r * 128 + (uint32_t)q * 16),
                            Af + (size_t)(m0 + r) * krow + c * 8 + q);
            }
            cp_commit();
            cp_wait0();
            __syncthreads();
        } else {
            cp_commit();
            const float* A = (const float*)Avoid;
            const int k0 = c * 64;
#pragma unroll
            for (int it = 0; it < 8; it++) {
                int idx = tid + it * 256;            // 0..2047
                int r = idx >> 4, f4 = idx & 15;
                float4 v = *(const float4*)(A + (size_t)(m0 + r) * K + k0 + f4 * 4);
                uint32_t h01 = cvt_f16x2(v.y, v.x);
                uint32_t h23 = cvt_f16x2(v.w, v.z);
                uint32_t sw = (uint32_t)r * 128 + (((uint32_t)f4 * 8) ^ (((uint32_t)r & 7) << 4));
                asm volatile("st.shared.v2.u32 [%0], {%1,%2};" :: "r"(uAhi + sw), "r"(h01), "r"(h23));
            }
            cp_wait0();
            __syncthreads();
        }

        // ---- compute: 4 k16 steps, 2 terms ----
#pragma unroll
        for (int ks = 0; ks < 4; ks++) {
            const uint32_t kbA = ((uint32_t)(32 * ks) + aKsel) ^ xorv;
            const uint32_t kbB = ((uint32_t)(32 * ks) + bKsel) ^ xorv;
            uint32_t ah0[4], ah1[4];
            ldsm_x4(ah0[0], ah0[1], ah0[2], ah0[3], uAhi + aRow * 128 + kbA);
            ldsm_x4(ah1[0], ah1[1], ah1[2], ah1[3], uAhi + (aRow + 16) * 128 + kbA);
            uint32_t bh[8], bl[8];
            ldsm_x4(bh[0], bh[1], bh[2], bh[3], uBhi + bRow * 128 + kbB);
            ldsm_x4(bh[4], bh[5], bh[6], bh[7], uBhi + (bRow + 16) * 128 + kbB);
            ldsm_x4(bl[0], bl[1], bl[2], bl[3], uBlo + bRow * 128 + kbB);
            ldsm_x4(bl[4], bl[5], bl[6], bl[7], uBlo + (bRow + 16) * 128 + kbB);
#pragma unroll
            for (int mt = 0; mt < 2; mt++) {
                const uint32_t* Ah = mt ? ah1 : ah0;
#pragma unroll
                for (int nt = 0; nt < 4; nt++) {
                    mma_f16(acc[mt][nt], Ah, bh + nt * 2);
                    mma_f16(acc[mt][nt], Ah, bl + nt * 2);
                }
            }
        }
    }

    const int gid = lane >> 2, tig = lane & 3;
    float2 bias[4];
#pragma unroll
    for (int nt = 0; nt < 4; nt++) {
        int col = n0 + nw + nt * 8 + tig * 2;
        bias[nt].x = b1[col]     + (b2 ? b2[col]     : 0.f);
        bias[nt].y = b1[col + 1] + (b2 ? b2[col + 1] : 0.f);
    }
#pragma unroll
    for (int mt = 0; mt < 2; mt++) {
        int row0 = m0 + mw + mt * 16 + gid;
#pragma unroll
        for (int nt = 0; nt < 4; nt++) {
            int col = n0 + nw + nt * 8 + tig * 2;
            float2 v0, v1;
            v0.x = acc[mt][nt][0] + bias[nt].x;
            v0.y = acc[mt][nt][1] + bias[nt].y;
            v1.x = acc[mt][nt][2] + bias[nt].x;
            v1.y = acc[mt][nt][3] + bias[nt].y;
            *(float2*)&C[(size_t)row0 * Ntot + col]       = v0;
            *(float2*)&C[(size_t)(row0 + 8) * Ntot + col] = v1;
        }
    }
}

// ---------------- persistent HMMA fp16 LSTM layer kernel --------------------
// Grid (32, 4): block = 16 units x 4 gates (64 n-cols) x 64 batch rows.
// W hi/lo fp16 resident in smem (128KB). h fp16 (hi only) staged per step,
// 8 chunks in 2 cp.async groups (second half hidden under first-half MMA).
// Terms: h*Whi + h*Wlo.
#define STEP_SMEM (196608 + 1024)
__global__ void __launch_bounds__(256)
lstm_layer_mma(const float* __restrict__ xg,        // [B, T, 4H]
               const uint4* __restrict__ Whi,       // prepacked, this layer
               const uint4* __restrict__ Wlo,
               __half* __restrict__ hX, __half* __restrict__ hY,
               __half* __restrict__ h_all,          // layer0: [B,T,H] fp16; else null
               float* __restrict__ h_final)         // layer1: [B,H]; else null
{
    __shared__ float sG[64 * 65];                   // gate tile, stride 65
    extern __shared__ char dsm[];
    uint32_t usm = smem_u32(dsm);
    usm = (usm + 1023u) & ~1023u;
    const uint32_t uWhi = usm;                      // 8 chunks x 8KB = 64KB
    const uint32_t uWlo = usm + 65536;              // 64KB
    const uint32_t uH   = usm + 131072;             // 8 chunks x 8KB = 64KB

    const int bu  = blockIdx.x;                     // u-tile 0..31
    const int grp = blockIdx.y;                     // m-group 0..3
    const int m0  = grp * 64;
    const int tid = threadIdx.x;
    const int w   = tid >> 5;
    const int lane = tid & 31;
    const int mw = (w & 1) * 32;
    const int nw = (w >> 1) * 16;

    const uint32_t xorv  = (uint32_t)(lane & 7) << 4;
    const uint32_t aRow  = mw + (lane & 15);
    const uint32_t aKsel = (uint32_t)(lane >> 4) << 4;
    const uint32_t bRow  = nw + (lane & 7) + ((lane >> 4) << 3);
    const uint32_t bKsel = (uint32_t)((lane >> 3) & 1) << 4;
    const int gid = lane >> 2, tig = lane & 3;

    // ---- load resident weights (once) ----
    {
        const uint4* sh = Whi + (size_t)bu * 4096;
        const uint4* sl = Wlo + (size_t)bu * 4096;
#pragma unroll
        for (int j = 0; j < 16; j++) {
            int idx = tid + j * 256;
            cp_async16u(uWhi + (uint32_t)idx * 16, sh + idx);
            cp_async16u(uWlo + (uint32_t)idx * 16, sl + idx);
        }
        cp_commit();
        cp_wait0();
        __syncthreads();
    }

    // ---- per-thread cell mapping: m = tid&63, units ugq*4 .. +3 ----
    const int cm  = tid & 63;
    const int ugq = tid >> 6;                        // 0..3
    const int grow = m0 + cm;                        // global batch row
    const int gcol = bu * 16 + ugq * 4;              // global unit col (x4)

    float creg[4] = {0.f, 0.f, 0.f, 0.f};
    float xvf[4][4];                                 // [gate][j]
    {
        const float* xr = xg + ((size_t)grow * Tn + 0) * G4H + gcol;
#pragma unroll
        for (int g = 0; g < 4; g++)
            *(float4*)&xvf[g][0] = __ldcg((const float4*)(xr + g * 512));
    }

    for (int t = 0; t < Tn; t++) {
        const __half* hin = (t & 1) ? hX : hY;
        __half* hout      = (t & 1) ? hY : hX;

        if (t > 0) {
            // group B: stage chunks 4..7 (group A = chunks 0..3 issued after
            // the previous barrier)
#pragma unroll
            for (int c = 4; c < 8; c++) {
#pragma unroll
                for (int j = 0; j < 2; j++) {
                    int idx = tid + j * 256;                 // 0..511
                    int r = idx >> 3, q = idx & 7;
                    cp_async16u(uH + (uint32_t)c * 8192 + SWZ128((uint32_t)r * 128 + (uint32_t)q * 16),
                                hin + (size_t)(m0 + r) * Hn + c * 64 + q * 8);
                }
            }
            cp_commit();

            float acc[2][2][4];
#pragma unroll
            for (int mt = 0; mt < 2; mt++)
#pragma unroll
                for (int nt = 0; nt < 2; nt++)
#pragma unroll
                    for (int e = 0; e < 4; e++) acc[mt][nt][e] = 0.f;

            cp_wait1();              // group A (chunks 0..3) complete
            __syncthreads();
#pragma unroll
            for (int c = 0; c < 8; c++) {
                if (c == 4) { cp_wait0(); __syncthreads(); }
                const uint32_t uA = uH + (uint32_t)c * 8192;
                const uint32_t wh = uWhi + (uint32_t)c * 8192;
                const uint32_t wl = uWlo + (uint32_t)c * 8192;
#pragma unroll
                for (int ks = 0; ks < 4; ks++) {
                    const uint32_t kbA = ((uint32_t)(32 * ks) + aKsel) ^ xorv;
                    const uint32_t kbB = ((uint32_t)(32 * ks) + bKsel) ^ xorv;
                    uint32_t a0[4], a1[4], bh[4], bl[4];
                    ldsm_x4(a0[0], a0[1], a0[2], a0[3], uA + aRow * 128 + kbA);
                    ldsm_x4(a1[0], a1[1], a1[2], a1[3], uA + (aRow + 16) * 128 + kbA);
                    ldsm_x4(bh[0], bh[1], bh[2], bh[3], wh + bRow * 128 + kbB);
                    ldsm_x4(bl[0], bl[1], bl[2], bl[3], wl + bRow * 128 + kbB);
#pragma unroll
                    for (int mt = 0; mt < 2; mt++) {
                        const uint32_t* Ah = mt ? a1 : a0;
#pragma unroll
                        for (int nt = 0; nt < 2; nt++) {
                            mma_f16(acc[mt][nt], Ah, bh + nt * 2);
                            mma_f16(acc[mt][nt], Ah, bl + nt * 2);
                        }
                    }
                }
            }

            // fragments -> sG
            __syncthreads();
#pragma unroll
            for (int mt = 0; mt < 2; mt++) {
                int r0 = mw + mt * 16 + gid;
#pragma unroll
                for (int nt = 0; nt < 2; nt++) {
                    int nc = nw + nt * 8 + tig * 2;
                    sG[r0 * 65 + nc]           = acc[mt][nt][0];
                    sG[r0 * 65 + nc + 1]       = acc[mt][nt][1];
                    sG[(r0 + 8) * 65 + nc]     = acc[mt][nt][2];
                    sG[(r0 + 8) * 65 + nc + 1] = acc[mt][nt][3];
                }
            }
            __syncthreads();
        }

        // ---- cell update: 4 cells per thread ----
        float hn4[4];
#pragma unroll
        for (int j = 0; j < 4; j++) {
            int uloc = ugq * 4 + j;
            float ri = 0.f, rf = 0.f, rg = 0.f, ro = 0.f;
            if (t > 0) {
                ri = sG[cm * 65 + uloc];
                rf = sG[cm * 65 + 16 + uloc];
                rg = sG[cm * 65 + 32 + uloc];
                ro = sG[cm * 65 + 48 + uloc];
            }
            float gi = ri + xvf[0][j];
            float gf = rf + xvf[1][j];
            float gg = rg + xvf[2][j];
            float go = ro + xvf[3][j];
            float cn = fsig(gf) * creg[j] + fsig(gi) * ftanh(gg);
            creg[j] = cn;
            hn4[j] = fsig(go) * ftanh(cn);
        }
        // write h (fp16)
        {
            uint32_t p01 = cvt_f16x2(hn4[1], hn4[0]);
            uint32_t p23 = cvt_f16x2(hn4[3], hn4[2]);
            size_t ho = (size_t)grow * Hn + gcol;
            *(uint2*)(hout + ho) = make_uint2(p01, p23);
            if (h_all)
                *(uint2*)(h_all + ((size_t)grow * Tn + t) * Hn + gcol) = make_uint2(p01, p23);
        }
        if (h_final && t == Tn - 1) {
            float4 v = make_float4(hn4[0], hn4[1], hn4[2], hn4[3]);
            *(float4*)&h_final[(size_t)grow * Hn + gcol] = v;
        }

        if (t < Tn - 1) {
            // prefetch xg for t+1 (h-independent; completes during barrier)
            const float* xr = xg + ((size_t)grow * Tn + (t + 1)) * G4H + gcol;
#pragma unroll
            for (int g = 0; g < 4; g++)
                *(float4*)&xvf[g][0] = __ldcg((const float4*)(xr + g * 512));

            group_barrier(grp);

            // group A: stage chunks 0..3 of next h_in (= hout just written)
#pragma unroll
            for (int c = 0; c < 4; c++) {
#pragma unroll
                for (int j = 0; j < 2; j++) {
                    int idx = tid + j * 256;
                    int r = idx >> 3, q = idx & 7;
                    cp_async16u(uH + (uint32_t)c * 8192 + SWZ128((uint32_t)r * 128 + (uint32_t)q * 16),
                                hout + (size_t)(m0 + r) * Hn + c * 64 + q * 8);
                }
            }
            cp_commit();
        }
    }
}

// ---------------- fp32 tiled GEMM (kept for FC1) ----------------------------
__global__ void __launch_bounds__(256, 2)
gemm_bias_kernel(const float* __restrict__ A,
                 const float* __restrict__ W,
                 const float* __restrict__ b1,
                 const float* __restrict__ b2,
                 float* __restrict__ C,
                 int M, int N, int K, int relu)
{
    __shared__ __align__(16) float As[2][128][GKC];
    __shared__ __align__(16) float Bs[2][GKC][64];
    const int m0 = blockIdx.y * 128;
    const int n0 = blockIdx.x * 64;
    const int tid = threadIdx.x;
    const int cx = tid & 15;
    const int ry = tid >> 4;

    ull acc01[8], acc23[8];
#pragma unroll
    for (int i = 0; i < 8; i++) { acc01[i] = 0ull; acc23[i] = 0ull; }

    const int nch = K / GKC;
    const int bcol = tid & 63, bq = tid >> 6;

#pragma unroll
    for (int i = 0; i < 2; i++) {
        int idx = tid + i * 256;
        cp_async16(&As[0][idx >> 2][(idx & 3) * 4],
                   A + (size_t)(m0 + (idx >> 2)) * K + (idx & 3) * 4);
    }
    cp_commit();
    float4 pW = *(const float4*)(W + (size_t)(n0 + bcol) * K + bq * 4);
    Bs[0][bq * 4 + 0][bcol] = pW.x;
    Bs[0][bq * 4 + 1][bcol] = pW.y;
    Bs[0][bq * 4 + 2][bcol] = pW.z;
    Bs[0][bq * 4 + 3][bcol] = pW.w;

    for (int c = 0; c < nch; c++) {
        cp_wait0();
        __syncthreads();
        const int buf = c & 1;
        const bool more = (c + 1 < nch);
        if (more) {
            int k0 = (c + 1) * GKC;
#pragma unroll
            for (int i = 0; i < 2; i++) {
                int idx = tid + i * 256;
                cp_async16(&As[buf ^ 1][idx >> 2][(idx & 3) * 4],
                           A + (size_t)(m0 + (idx >> 2)) * K + k0 + (idx & 3) * 4);
            }
            cp_commit();
            pW = *(const float4*)(W + (size_t)(n0 + bcol) * K + k0 + bq * 4);
        }
#pragma unroll
        for (int k4 = 0; k4 < GKC; k4 += 4) {
            float4 a4[8];
#pragma unroll
            for (int i = 0; i < 8; i++) a4[i] = *(const float4*)&As[buf][ry + 16 * i][k4];
#pragma unroll
            for (int j = 0; j < 4; j++) {
                float4 w4 = *(const float4*)&Bs[buf][k4 + j][4 * cx];
                ull w01 = *reinterpret_cast<ull*>(&w4.x);
                ull w23 = *reinterpret_cast<ull*>(&w4.z);
#pragma unroll
                for (int i = 0; i < 8; i++) {
                    float av = (j == 0) ? a4[i].x : (j == 1) ? a4[i].y : (j == 2) ? a4[i].z : a4[i].w;
                    ull ad = pack2dup(av);
                    ffma2(acc01[i], ad, w01);
                    ffma2(acc23[i], ad, w23);
                }
            }
        }
        if (more) {
            Bs[buf ^ 1][bq * 4 + 0][bcol] = pW.x;
            Bs[buf ^ 1][bq * 4 + 1][bcol] = pW.y;
            Bs[buf ^ 1][bq * 4 + 2][bcol] = pW.z;
            Bs[buf ^ 1][bq * 4 + 3][bcol] = pW.w;
        }
    }

    const int col = n0 + 4 * cx;
    float bb0 = b1[col + 0], bb1 = b1[col + 1], bb2 = b1[col + 2], bb3 = b1[col + 3];
    if (b2) { bb0 += b2[col + 0]; bb1 += b2[col + 1]; bb2 += b2[col + 2]; bb3 += b2[col + 3]; }
#pragma unroll
    for (int i = 0; i < 8; i++) {
        int row = m0 + ry + 16 * i;
        float2 p01 = unpack2(acc01[i]);
        float2 p23 = unpack2(acc23[i]);
        float4 v;
        v.x = p01.x + bb0; v.y = p01.y + bb1; v.z = p23.x + bb2; v.w = p23.y + bb3;
        if (relu) { v.x = fmaxf(v.x, 0.f); v.y = fmaxf(v.y, 0.f); v.z = fmaxf(v.z, 0.f); v.w = fmaxf(v.w, 0.f); }
        *(float4*)&C[(size_t)row * N + col] = v;
    }
}

// ---------------- FC2: out[256,8] = z @ W_fc2^T + b ------------------------
__global__ void fc2_kernel(const float* __restrict__ z,
                           const float* __restrict__ W,
                           const float* __restrict__ b,
                           float* __restrict__ out)
{
    int row = blockIdx.x;
    int o = threadIdx.y;
    int lane = threadIdx.x;
    float s = 0.f;
    const float* zr = z + (size_t)row * FCn;
    const float* wr = W + (size_t)o * FCn;
    for (int k = lane; k < FCn; k += 32) s += zr[k] * wr[k];
#pragma unroll
    for (int off = 16; off; off >>= 1) s += __shfl_down_sync(0xffffffffu, s, off);
    if (lane == 0) out[row * OUTn + o] = s + b[o];
}

// ---------------- host orchestration ---------------------------------------
extern "C" void kernel_launch(void* const* d_in, const int* in_sizes, int n_in,
                              void* d_out, int out_size)
{
    const float* x      = (const float*)d_in[0];
    const float* W_ih0  = (const float*)d_in[1];
    const float* W_hh0  = (const float*)d_in[2];
    const float* b_ih0  = (const float*)d_in[3];
    const float* b_hh0  = (const float*)d_in[4];
    const float* W_ih1  = (const float*)d_in[5];
    const float* W_hh1  = (const float*)d_in[6];
    const float* b_ih1  = (const float*)d_in[7];
    const float* b_hh1  = (const float*)d_in[8];
    const float* W_fc1  = (const float*)d_in[9];
    const float* b_fc1  = (const float*)d_in[10];
    const float* W_fc2  = (const float*)d_in[11];
    const float* b_fc2  = (const float*)d_in[12];
    float* out = (float*)d_out;

    float *xg, *hfin, *z;
    __half *h0h, *hX, *hY, *whhHi, *whhLo;
    uint4 *wb0h, *wb0l, *wb1h, *wb1l;
    cudaGetSymbolAddress((void**)&xg,    g_xg);
    cudaGetSymbolAddress((void**)&h0h,   g_h0h);
    cudaGetSymbolAddress((void**)&hfin,  g_hfin);
    cudaGetSymbolAddress((void**)&z,     g_z);
    cudaGetSymbolAddress((void**)&hX,    g_hX);
    cudaGetSymbolAddress((void**)&hY,    g_hY);
    cudaGetSymbolAddress((void**)&whhHi, g_Whh_hi);
    cudaGetSymbolAddress((void**)&whhLo, g_Whh_lo);
    cudaGetSymbolAddress((void**)&wb0h,  g_Wb0hi);
    cudaGetSymbolAddress((void**)&wb0l,  g_Wb0lo);
    cudaGetSymbolAddress((void**)&wb1h,  g_Wb1hi);
    cudaGetSymbolAddress((void**)&wb1l,  g_Wb1lo);

    cudaFuncSetAttribute(mma_gemm_kernel, cudaFuncAttributeMaxDynamicSharedMemorySize, MMAG_SMEM);
    cudaFuncSetAttribute(lstm_layer_mma,  cudaFuncAttributeMaxDynamicSharedMemorySize, STEP_SMEM);

    const int MT = Bn * Tn;                 // 131072
    dim3 mmaGrid(G4H / 64, MT / 128);       // (32, 1024)
    dim3 stepGrid(32, MGRPS);               // (32, 4) = 128 blocks

    const size_t WHL = (size_t)G4H * Hn;    // per-layer whh elements
    prepack_whh<<<(G4H * Hn) / 256, 256>>>(W_hh0, whhHi, whhLo);
    prepack_whh<<<(G4H * Hn) / 256, 256>>>(W_hh1, whhHi + WHL, whhLo + WHL);
    prepack_b_kernel<<<(G4H * Dn) / 256, 256>>>(W_ih0, (__half*)wb0h, (__half*)wb0l, Dn);
    prepack_b_kernel<<<(G4H * Hn) / 256, 256>>>(W_ih1, (__half*)wb1h, (__half*)wb1l, Hn);

    // ---- Layer 0 ----  xg = x @ W_ih0^T + b_ih0 + b_hh0 (K=64, A fp32)
    mma_gemm_kernel<<<mmaGrid, 256, MMAG_SMEM>>>(x, wb0h, wb0l, b_ih0, b_hh0, xg, Dn, G4H, 0);
    lstm_layer_mma<<<stepGrid, 256, STEP_SMEM>>>(xg, (const uint4*)whhHi, (const uint4*)whhLo,
                                                 hX, hY, h0h, (float*)0);

    // ---- Layer 1 ----  xg = h0 @ W_ih1^T + b_ih1 + b_hh1 (K=512, A fp16)
    mma_gemm_kernel<<<mmaGrid, 256, MMAG_SMEM>>>(h0h, wb1h, wb1l, b_ih1, b_hh1, xg, Hn, G4H, 1);
    lstm_layer_mma<<<stepGrid, 256, STEP_SMEM>>>(xg, (const uint4*)(whhHi + WHL), (const uint4*)(whhLo + WHL),
                                                 hX, hY, (__half*)0, hfin);

    // ---- FC head ----
    dim3 fc1Grid(FCn / 64, Bn / 128);       // (8, 2)
    gemm_bias_kernel<<<fc1Grid, 256>>>(hfin, W_fc1, b_fc1, (const float*)0, z, Bn, FCn, Hn, 1);
    fc2_kernel<<<Bn, dim3(32, 8)>>>(z, W_fc2, b_fc2, out);
}

// round 10
// speedup vs baseline: 4.8941x; 1.0728x over previous
#include <cuda_runtime.h>
#include <cuda_fp16.h>
#include <cstddef>
#include <cstdint>

// Problem constants
#define Bn   256
#define Tn   512
#define Dn   64
#define Hn   512
#define G4H  2048   // 4*H
#define FCn  512
#define OUTn 8

#define GKC   16          // k-chunk in fp32 gemm kernel
#define MGRPS 4           // m-groups (Bn/64)
#define GRP_BLOCKS 32     // blocks per m-group (2048 cols / 64)

typedef unsigned long long ull;

#define SWZ128(off) ((off) ^ (((off) >> 3) & 0x70))

// ---------------- scratch (device globals; no runtime allocation) ----------
__device__ float g_xg[(size_t)Bn * Tn * G4H];
__device__ __half g_h0h[(size_t)Bn * Tn * Hn];     // layer-0 h, fp16 (feeds layer-1 GEMM)
__device__ float g_hfin[Bn * Hn];
__device__ float g_z[Bn * FCn];
// fp16 h state double buffers (hi only)
__device__ __half g_hX[Bn * Hn], g_hY[Bn * Hn];
// prepacked recurrent weights, fp16 hi only, [layer][u_tile(32)][chunk(8)][64n x 64k swizzled]
__device__ __half g_Whh_hi[2][(size_t)G4H * Hn];
// fp16 hi/lo pre-swizzled W_ih for mma gemm
__device__ uint4 g_Wb0hi[G4H * Dn / 8],  g_Wb0lo[G4H * Dn / 8];   // layer0: 2048x64
__device__ uint4 g_Wb1hi[G4H * Hn / 8],  g_Wb1lo[G4H * Hn / 8];   // layer1: 2048x512

// ---------------- f32x2 packed helpers (fp32 FC1 gemm) ----------------------
__device__ __forceinline__ void ffma2(ull& d, ull a, ull b) {
    asm("fma.rn.f32x2 %0, %1, %2, %0;" : "+l"(d) : "l"(a), "l"(b));
}
__device__ __forceinline__ ull pack2dup(float x) {
    ull r; asm("mov.b64 %0, {%1, %1};" : "=l"(r) : "f"(x)); return r;
}
__device__ __forceinline__ float2 unpack2(ull v) {
    float2 f; asm("mov.b64 {%0, %1}, %2;" : "=f"(f.x), "=f"(f.y) : "l"(v)); return f;
}

// ---------------- fast activations ------------------------------------------
__device__ __forceinline__ float fsig(float x) {
    return __fdividef(1.f, 1.f + __expf(-x));
}
__device__ __forceinline__ float ftanh(float x) {
    return 1.f - __fdividef(2.f, 1.f + __expf(2.f * x));
}

// ---------------- cp.async helpers -----------------------------------------
__device__ __forceinline__ void cp_async16(void* smem_dst, const void* gmem_src) {
    unsigned saddr = (unsigned)__cvta_generic_to_shared(smem_dst);
    asm volatile("cp.async.cg.shared.global [%0], [%1], 16;" :: "r"(saddr), "l"(gmem_src));
}
__device__ __forceinline__ void cp_async16u(unsigned saddr, const void* gmem_src) {
    asm volatile("cp.async.cg.shared.global [%0], [%1], 16;" :: "r"(saddr), "l"(gmem_src));
}
__device__ __forceinline__ void cp_commit() { asm volatile("cp.async.commit_group;"); }
__device__ __forceinline__ void cp_wait0()  { asm volatile("cp.async.wait_group 0;" ::: "memory"); }
__device__ __forceinline__ void cp_wait1()  { asm volatile("cp.async.wait_group 1;" ::: "memory"); }

__device__ __forceinline__ unsigned smem_u32(const void* p) {
    return (unsigned)__cvta_generic_to_shared(p);
}
// pack two fp32 -> f16x2 (second arg in lower half)
__device__ __forceinline__ uint32_t cvt_f16x2(float hi, float lo) {
    uint32_t r; asm("cvt.rn.f16x2.f32 %0, %1, %2;" : "=r"(r) : "f"(hi), "f"(lo)); return r;
}

// ---------------- warp-level mma helpers ------------------------------------
__device__ __forceinline__ void ldsm_x4(uint32_t& r0, uint32_t& r1, uint32_t& r2, uint32_t& r3,
                                        uint32_t addr) {
    asm volatile("ldmatrix.sync.aligned.m8n8.x4.shared.b16 {%0,%1,%2,%3}, [%4];"
                 : "=r"(r0), "=r"(r1), "=r"(r2), "=r"(r3) : "r"(addr));
}
__device__ __forceinline__ void mma_f16(float* d, const uint32_t* a, const uint32_t* b) {
    asm volatile("mma.sync.aligned.m16n8k16.row.col.f32.f16.f16.f32 "
                 "{%0,%1,%2,%3}, {%4,%5,%6,%7}, {%8,%9}, {%0,%1,%2,%3};"
                 : "+f"(d[0]), "+f"(d[1]), "+f"(d[2]), "+f"(d[3])
                 : "r"(a[0]), "r"(a[1]), "r"(a[2]), "r"(a[3]), "r"(b[0]), "r"(b[1]));
}

// ---------------- per-m-group barrier (generation based, replay-safe) ------
struct __align__(128) BarSlot { unsigned count; unsigned gen; unsigned pad[30]; };
__device__ BarSlot g_bar[MGRPS];

__device__ __forceinline__ void group_barrier(int grp) {
    __syncthreads();
    __threadfence();
    if (threadIdx.x == 0) {
        unsigned gen = atomicAdd(&g_bar[grp].gen, 0u);
        unsigned arrived = atomicAdd(&g_bar[grp].count, 1u);
        if (arrived == GRP_BLOCKS - 1u) {
            atomicExch(&g_bar[grp].count, 0u);
            __threadfence();
            atomicExch(&g_bar[grp].gen, gen + 1u);
        } else {
            while (atomicAdd(&g_bar[grp].gen, 0u) == gen) { __nanosleep(20); }
        }
    }
    __syncthreads();
}

// ---------------- weight pre-pack kernels -----------------------------------
// Whh [4H, H] -> per u-tile (16 units x 4 gates = 64 n-cols) x 8 k-chunks,
// each chunk a 64n x 64k fp16 tile, SW128 swizzled. hi only.
__global__ void prepack_whh(const float* __restrict__ Whh,
                            __half* __restrict__ hi)
{
    int i = blockIdx.x * blockDim.x + threadIdx.x;   // 0 .. 2048*512-1
    int k = i & 511;
    int row = i >> 9;                                 // gate*512 + unit_global
    int gate = row >> 9;
    int ug = row & 511;
    int bu = ug >> 4, un = ug & 15;
    int n = gate * 16 + un;                           // 0..63 within tile
    int c = k >> 6, lk = k & 63;
    size_t off = ((size_t)(bu * 8 + c)) * 4096 + (SWZ128(n * 128 + lk * 2) >> 1);
    hi[off] = __float2half(Whh[(size_t)row * Hn + k]);
}

// Split W (N=2048 x K) into fp16 hi/lo, per (ntile, kchunk) 64x64 tile, SW128.
__global__ void prepack_b_kernel(const float* __restrict__ W,
                                 __half* __restrict__ hi,
                                 __half* __restrict__ lo,
                                 int K)
{
    int i = blockIdx.x * blockDim.x + threadIdx.x;
    int k = i % K;
    int n = i / K;
    int ntile = n >> 6, ln = n & 63;
    int kc = k >> 6, lk = k & 63;
    int nch = K >> 6;
    size_t off = ((size_t)(ntile * nch + kc)) * 4096 + (SWZ128(ln * 128 + lk * 2) >> 1);
    float w = W[(size_t)n * K + k];
    __half h = __float2half(w);
    hi[off] = h;
    lo[off] = __float2half(w - __half2float(h));
}

// ---------------- HMMA fp16 2-term GEMM: C = A @ W^T + b1 (+b2) ------------
// A: [M,K] row-major, fp32 (converted to fp16-hi in-kernel) or fp16 (cp.async).
// W prepacked fp16 hi/lo swizzled 64x64 tiles. Terms: Ahi*Whi + Ahi*Wlo.
#define MMAG_SMEM (32768 + 1024)
__global__ void __launch_bounds__(256, 2)
mma_gemm_kernel(const void* __restrict__ Avoid,
                const uint4* __restrict__ Wbhi,
                const uint4* __restrict__ Wblo,
                const float* __restrict__ b1,
                const float* __restrict__ b2,
                float* __restrict__ C,
                int K, int Ntot, int a_f16)
{
    extern __shared__ char dsm[];
    uint32_t usm = smem_u32(dsm);
    usm = (usm + 1023u) & ~1023u;
    const uint32_t uAhi = usm;              // 128 x 64 fp16 = 16KB
    const uint32_t uBhi = usm + 16384;      // 8KB
    const uint32_t uBlo = usm + 24576;      // 8KB

    const int bn = blockIdx.x;
    const int m0 = blockIdx.y * 128;
    const int n0 = bn * 64;
    const int tid = threadIdx.x;
    const int w = tid >> 5;
    const int lane = tid & 31;
    const int mw = (w & 3) * 32;
    const int nw = (w >> 2) * 32;
    const int nch = K >> 6;

    const uint32_t xorv  = (uint32_t)(lane & 7) << 4;
    const uint32_t aRow  = mw + (lane & 15);
    const uint32_t aKsel = (uint32_t)(lane >> 4) << 4;
    const uint32_t bRow  = nw + (lane & 7) + ((lane >> 4) << 3);
    const uint32_t bKsel = (uint32_t)((lane >> 3) & 1) << 4;

    float acc[2][4][4];
#pragma unroll
    for (int mt = 0; mt < 2; mt++)
#pragma unroll
        for (int nt = 0; nt < 4; nt++)
#pragma unroll
            for (int e = 0; e < 4; e++) acc[mt][nt][e] = 0.f;

    for (int c = 0; c < nch; c++) {
        if (c) __syncthreads();

        // ---- stage B (cp.async, pre-swizzled fp16 hi/lo tiles) ----
        const uint4* sbh = Wbhi + ((size_t)bn * nch + c) * 512;
        const uint4* sbl = Wblo + ((size_t)bn * nch + c) * 512;
        cp_async16u(uBhi + (uint32_t)tid * 16,         sbh + tid);
        cp_async16u(uBhi + (uint32_t)(tid + 256) * 16, sbh + tid + 256);
        cp_async16u(uBlo + (uint32_t)tid * 16,         sbl + tid);
        cp_async16u(uBlo + (uint32_t)(tid + 256) * 16, sbl + tid + 256);

        if (a_f16) {
            // A already fp16 row-major: straight cp.async with swizzle
            const uint4* Af = (const uint4*)Avoid;
            const int krow = K >> 3;                 // uint4 per row
#pragma unroll
            for (int j = 0; j < 4; j++) {
                int idx = tid + j * 256;             // 0..1023
                int r = idx >> 3, q = idx & 7;
                cp_async16u(uAhi + SWZ128((uint32_t)r * 128 + (uint32_t)q * 16),
                            Af + (size_t)(m0 + r) * krow + c * 8 + q);
            }
            cp_commit();
            cp_wait0();
            __syncthreads();
        } else {
            cp_commit();
            const float* A = (const float*)Avoid;
            const int k0 = c * 64;
#pragma unroll
            for (int it = 0; it < 8; it++) {
                int idx = tid + it * 256;            // 0..2047
                int r = idx >> 4, f4 = idx & 15;
                float4 v = *(const float4*)(A + (size_t)(m0 + r) * K + k0 + f4 * 4);
                uint32_t h01 = cvt_f16x2(v.y, v.x);
                uint32_t h23 = cvt_f16x2(v.w, v.z);
                uint32_t sw = (uint32_t)r * 128 + (((uint32_t)f4 * 8) ^ (((uint32_t)r & 7) << 4));
                asm volatile("st.shared.v2.u32 [%0], {%1,%2};" :: "r"(uAhi + sw), "r"(h01), "r"(h23));
            }
            cp_wait0();
            __syncthreads();
        }

        // ---- compute: 4 k16 steps, 2 terms ----
#pragma unroll
        for (int ks = 0; ks < 4; ks++) {
            const uint32_t kbA = ((uint32_t)(32 * ks) + aKsel) ^ xorv;
            const uint32_t kbB = ((uint32_t)(32 * ks) + bKsel) ^ xorv;
            uint32_t ah0[4], ah1[4];
            ldsm_x4(ah0[0], ah0[1], ah0[2], ah0[3], uAhi + aRow * 128 + kbA);
            ldsm_x4(ah1[0], ah1[1], ah1[2], ah1[3], uAhi + (aRow + 16) * 128 + kbA);
            uint32_t bh[8], bl[8];
            ldsm_x4(bh[0], bh[1], bh[2], bh[3], uBhi + bRow * 128 + kbB);
            ldsm_x4(bh[4], bh[5], bh[6], bh[7], uBhi + (bRow + 16) * 128 + kbB);
            ldsm_x4(bl[0], bl[1], bl[2], bl[3], uBlo + bRow * 128 + kbB);
            ldsm_x4(bl[4], bl[5], bl[6], bl[7], uBlo + (bRow + 16) * 128 + kbB);
#pragma unroll
            for (int mt = 0; mt < 2; mt++) {
                const uint32_t* Ah = mt ? ah1 : ah0;
#pragma unroll
                for (int nt = 0; nt < 4; nt++) {
                    mma_f16(acc[mt][nt], Ah, bh + nt * 2);
                    mma_f16(acc[mt][nt], Ah, bl + nt * 2);
                }
            }
        }
    }

    const int gid = lane >> 2, tig = lane & 3;
    float2 bias[4];
#pragma unroll
    for (int nt = 0; nt < 4; nt++) {
        int col = n0 + nw + nt * 8 + tig * 2;
        bias[nt].x = b1[col]     + (b2 ? b2[col]     : 0.f);
        bias[nt].y = b1[col + 1] + (b2 ? b2[col + 1] : 0.f);
    }
#pragma unroll
    for (int mt = 0; mt < 2; mt++) {
        int row0 = m0 + mw + mt * 16 + gid;
#pragma unroll
        for (int nt = 0; nt < 4; nt++) {
            int col = n0 + nw + nt * 8 + tig * 2;
            float2 v0, v1;
            v0.x = acc[mt][nt][0] + bias[nt].x;
            v0.y = acc[mt][nt][1] + bias[nt].y;
            v1.x = acc[mt][nt][2] + bias[nt].x;
            v1.y = acc[mt][nt][3] + bias[nt].y;
            *(float2*)&C[(size_t)row0 * Ntot + col]       = v0;
            *(float2*)&C[(size_t)(row0 + 8) * Ntot + col] = v1;
        }
    }
}

// ---------------- persistent HMMA fp16 LSTM layer kernel --------------------
// Grid (32, 4): block = 16 units x 4 gates (64 n-cols) x 64 batch rows.
// W hi fp16 resident in smem (64KB). h fp16 staged per step, 8 chunks in
// 2 cp.async groups (second half hidden under first-half MMA).
// Single term: h*Whi.
#define STEP_SMEM (131072 + 1024)
__global__ void __launch_bounds__(256)
lstm_layer_mma(const float* __restrict__ xg,        // [B, T, 4H]
               const uint4* __restrict__ Whi,       // prepacked, this layer
               __half* __restrict__ hX, __half* __restrict__ hY,
               __half* __restrict__ h_all,          // layer0: [B,T,H] fp16; else null
               float* __restrict__ h_final)         // layer1: [B,H]; else null
{
    __shared__ float sG[64 * 65];                   // gate tile, stride 65
    extern __shared__ char dsm[];
    uint32_t usm = smem_u32(dsm);
    usm = (usm + 1023u) & ~1023u;
    const uint32_t uWhi = usm;                      // 8 chunks x 8KB = 64KB
    const uint32_t uH   = usm + 65536;              // 8 chunks x 8KB = 64KB

    const int bu  = blockIdx.x;                     // u-tile 0..31
    const int grp = blockIdx.y;                     // m-group 0..3
    const int m0  = grp * 64;
    const int tid = threadIdx.x;
    const int w   = tid >> 5;
    const int lane = tid & 31;
    const int mw = (w & 1) * 32;
    const int nw = (w >> 1) * 16;

    const uint32_t xorv  = (uint32_t)(lane & 7) << 4;
    const uint32_t aRow  = mw + (lane & 15);
    const uint32_t aKsel = (uint32_t)(lane >> 4) << 4;
    const uint32_t bRow  = nw + (lane & 7) + ((lane >> 4) << 3);
    const uint32_t bKsel = (uint32_t)((lane >> 3) & 1) << 4;
    const int gid = lane >> 2, tig = lane & 3;

    // ---- load resident weights (once) ----
    {
        const uint4* sh = Whi + (size_t)bu * 4096;
#pragma unroll
        for (int j = 0; j < 16; j++) {
            int idx = tid + j * 256;
            cp_async16u(uWhi + (uint32_t)idx * 16, sh + idx);
        }
        cp_commit();
        cp_wait0();
        __syncthreads();
    }

    // ---- per-thread cell mapping: m = tid&63, units ugq*4 .. +3 ----
    const int cm  = tid & 63;
    const int ugq = tid >> 6;                        // 0..3
    const int grow = m0 + cm;                        // global batch row
    const int gcol = bu * 16 + ugq * 4;              // global unit col (x4)

    float creg[4] = {0.f, 0.f, 0.f, 0.f};
    float xvf[4][4];                                 // [gate][j]
    {
        const float* xr = xg + ((size_t)grow * Tn + 0) * G4H + gcol;
#pragma unroll
        for (int g = 0; g < 4; g++)
            *(float4*)&xvf[g][0] = __ldcg((const float4*)(xr + g * 512));
    }

    for (int t = 0; t < Tn; t++) {
        const __half* hin = (t & 1) ? hX : hY;
        __half* hout      = (t & 1) ? hY : hX;

        if (t > 0) {
            // group B: stage chunks 4..7 (group A = chunks 0..3 issued after
            // the previous barrier)
#pragma unroll
            for (int c = 4; c < 8; c++) {
#pragma unroll
                for (int j = 0; j < 2; j++) {
                    int idx = tid + j * 256;                 // 0..511
                    int r = idx >> 3, q = idx & 7;
                    cp_async16u(uH + (uint32_t)c * 8192 + SWZ128((uint32_t)r * 128 + (uint32_t)q * 16),
                                hin + (size_t)(m0 + r) * Hn + c * 64 + q * 8);
                }
            }
            cp_commit();

            float acc[2][2][4];
#pragma unroll
            for (int mt = 0; mt < 2; mt++)
#pragma unroll
                for (int nt = 0; nt < 2; nt++)
#pragma unroll
                    for (int e = 0; e < 4; e++) acc[mt][nt][e] = 0.f;

            cp_wait1();              // group A (chunks 0..3) complete
            __syncthreads();
#pragma unroll
            for (int c = 0; c < 8; c++) {
                if (c == 4) { cp_wait0(); __syncthreads(); }
                const uint32_t uA = uH + (uint32_t)c * 8192;
                const uint32_t wh = uWhi + (uint32_t)c * 8192;
#pragma unroll
                for (int ks = 0; ks < 4; ks++) {
                    const uint32_t kbA = ((uint32_t)(32 * ks) + aKsel) ^ xorv;
                    const uint32_t kbB = ((uint32_t)(32 * ks) + bKsel) ^ xorv;
                    uint32_t a0[4], a1[4], bh[4];
                    ldsm_x4(a0[0], a0[1], a0[2], a0[3], uA + aRow * 128 + kbA);
                    ldsm_x4(a1[0], a1[1], a1[2], a1[3], uA + (aRow + 16) * 128 + kbA);
                    ldsm_x4(bh[0], bh[1], bh[2], bh[3], wh + bRow * 128 + kbB);
#pragma unroll
                    for (int mt = 0; mt < 2; mt++) {
                        const uint32_t* Ah = mt ? a1 : a0;
#pragma unroll
                        for (int nt = 0; nt < 2; nt++)
                            mma_f16(acc[mt][nt], Ah, bh + nt * 2);
                    }
                }
            }

            // fragments -> sG
            __syncthreads();
#pragma unroll
            for (int mt = 0; mt < 2; mt++) {
                int r0 = mw + mt * 16 + gid;
#pragma unroll
                for (int nt = 0; nt < 2; nt++) {
                    int nc = nw + nt * 8 + tig * 2;
                    sG[r0 * 65 + nc]           = acc[mt][nt][0];
                    sG[r0 * 65 + nc + 1]       = acc[mt][nt][1];
                    sG[(r0 + 8) * 65 + nc]     = acc[mt][nt][2];
                    sG[(r0 + 8) * 65 + nc + 1] = acc[mt][nt][3];
                }
            }
            __syncthreads();
        }

        // ---- cell update: 4 cells per thread ----
        float hn4[4];
#pragma unroll
        for (int j = 0; j < 4; j++) {
            int uloc = ugq * 4 + j;
            float ri = 0.f, rf = 0.f, rg = 0.f, ro = 0.f;
            if (t > 0) {
                ri = sG[cm * 65 + uloc];
                rf = sG[cm * 65 + 16 + uloc];
                rg = sG[cm * 65 + 32 + uloc];
                ro = sG[cm * 65 + 48 + uloc];
            }
            float gi = ri + xvf[0][j];
            float gf = rf + xvf[1][j];
            float gg = rg + xvf[2][j];
            float go = ro + xvf[3][j];
            float cn = fsig(gf) * creg[j] + fsig(gi) * ftanh(gg);
            creg[j] = cn;
            hn4[j] = fsig(go) * ftanh(cn);
        }
        // write h (fp16)
        {
            uint32_t p01 = cvt_f16x2(hn4[1], hn4[0]);
            uint32_t p23 = cvt_f16x2(hn4[3], hn4[2]);
            size_t ho = (size_t)grow * Hn + gcol;
            *(uint2*)(hout + ho) = make_uint2(p01, p23);
            if (h_all)
                *(uint2*)(h_all + ((size_t)grow * Tn + t) * Hn + gcol) = make_uint2(p01, p23);
        }
        if (h_final && t == Tn - 1) {
            float4 v = make_float4(hn4[0], hn4[1], hn4[2], hn4[3]);
            *(float4*)&h_final[(size_t)grow * Hn + gcol] = v;
        }

        if (t < Tn - 1) {
            // prefetch xg for t+1 (h-independent; completes during barrier)
            const float* xr = xg + ((size_t)grow * Tn + (t + 1)) * G4H + gcol;
#pragma unroll
            for (int g = 0; g < 4; g++)
                *(float4*)&xvf[g][0] = __ldcg((const float4*)(xr + g * 512));

            group_barrier(grp);

            // group A: stage chunks 0..3 of next h_in (= hout just written)
#pragma unroll
            for (int c = 0; c < 4; c++) {
#pragma unroll
                for (int j = 0; j < 2; j++) {
                    int idx = tid + j * 256;
                    int r = idx >> 3, q = idx & 7;
                    cp_async16u(uH + (uint32_t)c * 8192 + SWZ128((uint32_t)r * 128 + (uint32_t)q * 16),
                                hout + (size_t)(m0 + r) * Hn + c * 64 + q * 8);
                }
            }
            cp_commit();
        }
    }
}

// ---------------- fp32 tiled GEMM (kept for FC1) ----------------------------
__global__ void __launch_bounds__(256, 2)
gemm_bias_kernel(const float* __restrict__ A,
                 const float* __restrict__ W,
                 const float* __restrict__ b1,
                 const float* __restrict__ b2,
                 float* __restrict__ C,
                 int M, int N, int K, int relu)
{
    __shared__ __align__(16) float As[2][128][GKC];
    __shared__ __align__(16) float Bs[2][GKC][64];
    const int m0 = blockIdx.y * 128;
    const int n0 = blockIdx.x * 64;
    const int tid = threadIdx.x;
    const int cx = tid & 15;
    const int ry = tid >> 4;

    ull acc01[8], acc23[8];
#pragma unroll
    for (int i = 0; i < 8; i++) { acc01[i] = 0ull; acc23[i] = 0ull; }

    const int nch = K / GKC;
    const int bcol = tid & 63, bq = tid >> 6;

#pragma unroll
    for (int i = 0; i < 2; i++) {
        int idx = tid + i * 256;
        cp_async16(&As[0][idx >> 2][(idx & 3) * 4],
                   A + (size_t)(m0 + (idx >> 2)) * K + (idx & 3) * 4);
    }
    cp_commit();
    float4 pW = *(const float4*)(W + (size_t)(n0 + bcol) * K + bq * 4);
    Bs[0][bq * 4 + 0][bcol] = pW.x;
    Bs[0][bq * 4 + 1][bcol] = pW.y;
    Bs[0][bq * 4 + 2][bcol] = pW.z;
    Bs[0][bq * 4 + 3][bcol] = pW.w;

    for (int c = 0; c < nch; c++) {
        cp_wait0();
        __syncthreads();
        const int buf = c & 1;
        const bool more = (c + 1 < nch);
        if (more) {
            int k0 = (c + 1) * GKC;
#pragma unroll
            for (int i = 0; i < 2; i++) {
                int idx = tid + i * 256;
                cp_async16(&As[buf ^ 1][idx >> 2][(idx & 3) * 4],
                           A + (size_t)(m0 + (idx >> 2)) * K + k0 + (idx & 3) * 4);
            }
            cp_commit();
            pW = *(const float4*)(W + (size_t)(n0 + bcol) * K + k0 + bq * 4);
        }
#pragma unroll
        for (int k4 = 0; k4 < GKC; k4 += 4) {
            float4 a4[8];
#pragma unroll
            for (int i = 0; i < 8; i++) a4[i] = *(const float4*)&As[buf][ry + 16 * i][k4];
#pragma unroll
            for (int j = 0; j < 4; j++) {
                float4 w4 = *(const float4*)&Bs[buf][k4 + j][4 * cx];
                ull w01 = *reinterpret_cast<ull*>(&w4.x);
                ull w23 = *reinterpret_cast<ull*>(&w4.z);
#pragma unroll
                for (int i = 0; i < 8; i++) {
                    float av = (j == 0) ? a4[i].x : (j == 1) ? a4[i].y : (j == 2) ? a4[i].z : a4[i].w;
                    ull ad = pack2dup(av);
                    ffma2(acc01[i], ad, w01);
                    ffma2(acc23[i], ad, w23);
                }
            }
        }
        if (more) {
            Bs[buf ^ 1][bq * 4 + 0][bcol] = pW.x;
            Bs[buf ^ 1][bq * 4 + 1][bcol] = pW.y;
            Bs[buf ^ 1][bq * 4 + 2][bcol] = pW.z;
            Bs[buf ^ 1][bq * 4 + 3][bcol] = pW.w;
        }
    }

    const int col = n0 + 4 * cx;
    float bb0 = b1[col + 0], bb1 = b1[col + 1], bb2 = b1[col + 2], bb3 = b1[col + 3];
    if (b2) { bb0 += b2[col + 0]; bb1 += b2[col + 1]; bb2 += b2[col + 2]; bb3 += b2[col + 3]; }
#pragma unroll
    for (int i = 0; i < 8; i++) {
        int row = m0 + ry + 16 * i;
        float2 p01 = unpack2(acc01[i]);
        float2 p23 = unpack2(acc23[i]);
        float4 v;
        v.x = p01.x + bb0; v.y = p01.y + bb1; v.z = p23.x + bb2; v.w = p23.y + bb3;
        if (relu) { v.x = fmaxf(v.x, 0.f); v.y = fmaxf(v.y, 0.f); v.z = fmaxf(v.z, 0.f); v.w = fmaxf(v.w, 0.f); }
        *(float4*)&C[(size_t)row * N + col] = v;
    }
}

// ---------------- FC2: out[256,8] = z @ W_fc2^T + b ------------------------
__global__ void fc2_kernel(const float* __restrict__ z,
                           const float* __restrict__ W,
                           const float* __restrict__ b,
                           float* __restrict__ out)
{
    int row = blockIdx.x;
    int o = threadIdx.y;
    int lane = threadIdx.x;
    float s = 0.f;
    const float* zr = z + (size_t)row * FCn;
    const float* wr = W + (size_t)o * FCn;
    for (int k = lane; k < FCn; k += 32) s += zr[k] * wr[k];
#pragma unroll
    for (int off = 16; off; off >>= 1) s += __shfl_down_sync(0xffffffffu, s, off);
    if (lane == 0) out[row * OUTn + o] = s + b[o];
}

// ---------------- host orchestration ---------------------------------------
extern "C" void kernel_launch(void* const* d_in, const int* in_sizes, int n_in,
                              void* d_out, int out_size)
{
    const float* x      = (const float*)d_in[0];
    const float* W_ih0  = (const float*)d_in[1];
    const float* W_hh0  = (const float*)d_in[2];
    const float* b_ih0  = (const float*)d_in[3];
    const float* b_hh0  = (const float*)d_in[4];
    const float* W_ih1  = (const float*)d_in[5];
    const float* W_hh1  = (const float*)d_in[6];
    const float* b_ih1  = (const float*)d_in[7];
    const float* b_hh1  = (const float*)d_in[8];
    const float* W_fc1  = (const float*)d_in[9];
    const float* b_fc1  = (const float*)d_in[10];
    const float* W_fc2  = (const float*)d_in[11];
    const float* b_fc2  = (const float*)d_in[12];
    float* out = (float*)d_out;

    float *xg, *hfin, *z;
    __half *h0h, *hX, *hY, *whhHi;
    uint4 *wb0h, *wb0l, *wb1h, *wb1l;
    cudaGetSymbolAddress((void**)&xg,    g_xg);
    cudaGetSymbolAddress((void**)&h0h,   g_h0h);
    cudaGetSymbolAddress((void**)&hfin,  g_hfin);
    cudaGetSymbolAddress((void**)&z,     g_z);
    cudaGetSymbolAddress((void**)&hX,    g_hX);
    cudaGetSymbolAddress((void**)&hY,    g_hY);
    cudaGetSymbolAddress((void**)&whhHi, g_Whh_hi);
    cudaGetSymbolAddress((void**)&wb0h,  g_Wb0hi);
    cudaGetSymbolAddress((void**)&wb0l,  g_Wb0lo);
    cudaGetSymbolAddress((void**)&wb1h,  g_Wb1hi);
    cudaGetSymbolAddress((void**)&wb1l,  g_Wb1lo);

    cudaFuncSetAttribute(mma_gemm_kernel, cudaFuncAttributeMaxDynamicSharedMemorySize, MMAG_SMEM);
    cudaFuncSetAttribute(lstm_layer_mma,  cudaFuncAttributeMaxDynamicSharedMemorySize, STEP_SMEM);

    const int MT = Bn * Tn;                 // 131072
    dim3 mmaGrid(G4H / 64, MT / 128);       // (32, 1024)
    dim3 stepGrid(32, MGRPS);               // (32, 4) = 128 blocks

    const size_t WHL = (size_t)G4H * Hn;    // per-layer whh elements
    prepack_whh<<<(G4H * Hn) / 256, 256>>>(W_hh0, whhHi);
    prepack_whh<<<(G4H * Hn) / 256, 256>>>(W_hh1, whhHi + WHL);
    prepack_b_kernel<<<(G4H * Dn) / 256, 256>>>(W_ih0, (__half*)wb0h, (__half*)wb0l, Dn);
    prepack_b_kernel<<<(G4H * Hn) / 256, 256>>>(W_ih1, (__half*)wb1h, (__half*)wb1l, Hn);

    // ---- Layer 0 ----  xg = x @ W_ih0^T + b_ih0 + b_hh0 (K=64, A fp32)
    mma_gemm_kernel<<<mmaGrid, 256, MMAG_SMEM>>>(x, wb0h, wb0l, b_ih0, b_hh0, xg, Dn, G4H, 0);
    lstm_layer_mma<<<stepGrid, 256, STEP_SMEM>>>(xg, (const uint4*)whhHi,
                                                 hX, hY, h0h, (float*)0);

    // ---- Layer 1 ----  xg = h0 @ W_ih1^T + b_ih1 + b_hh1 (K=512, A fp16)
    mma_gemm_kernel<<<mmaGrid, 256, MMAG_SMEM>>>(h0h, wb1h, wb1l, b_ih1, b_hh1, xg, Hn, G4H, 1);
    lstm_layer_mma<<<stepGrid, 256, STEP_SMEM>>>(xg, (const uint4*)(whhHi + WHL),
                                                 hX, hY, (__half*)0, hfin);

    // ---- FC head ----
    dim3 fc1Grid(FCn / 64, Bn / 128);       // (8, 2)
    gemm_bias_kernel<<<fc1Grid, 256>>>(hfin, W_fc1, b_fc1, (const float*)0, z, Bn, FCn, Hn, 1);
    fc2_kernel<<<Bn, dim3(32, 8)>>>(z, W_fc2, b_fc2, out);
}

// round 11
// speedup vs baseline: 5.8721x; 1.1998x over previous
#include <cuda_runtime.h>
#include <cuda_fp16.h>
#include <cstddef>
#include <cstdint>

// Problem constants
#define Bn   256
#define Tn   512
#define Dn   64
#define Hn   512
#define G4H  2048   // 4*H
#define FCn  512
#define OUTn 8

#define GKC   16          // k-chunk in fp32 gemm kernel
#define MGRPS 8           // m-groups (Bn/32)
#define GRP_BLOCKS 16     // blocks per m-group (2048 cols / 128)

typedef unsigned long long ull;

#define SWZ128(off) ((off) ^ (((off) >> 3) & 0x70))

// ---------------- scratch (device globals; no runtime allocation) ----------
__device__ float g_xg[(size_t)Bn * Tn * G4H];
__device__ __half g_h0h[(size_t)Bn * Tn * Hn];     // layer-0 h, fp16 (feeds layer-1 GEMM)
__device__ float g_hfin[Bn * Hn];
__device__ float g_z[Bn * FCn];
// fp16 h state double buffers
__device__ __half g_hX[Bn * Hn], g_hY[Bn * Hn];
// prepacked recurrent weights, fp16, [layer][u_tile(16)][chunk(8)][128n x 64k swizzled]
__device__ __half g_Whh_hi[2][(size_t)G4H * Hn];
// fp16 hi/lo pre-swizzled W_ih for mma gemm
__device__ uint4 g_Wb0hi[G4H * Dn / 8],  g_Wb0lo[G4H * Dn / 8];   // layer0: 2048x64
__device__ uint4 g_Wb1hi[G4H * Hn / 8],  g_Wb1lo[G4H * Hn / 8];   // layer1: 2048x512

// producer-progress flags (one per m-group, padded to 128B)
__device__ unsigned g_hflag[MGRPS * 32];

// ---------------- f32x2 packed helpers (fp32 FC1 gemm) ----------------------
__device__ __forceinline__ void ffma2(ull& d, ull a, ull b) {
    asm("fma.rn.f32x2 %0, %1, %2, %0;" : "+l"(d) : "l"(a), "l"(b));
}
__device__ __forceinline__ ull pack2dup(float x) {
    ull r; asm("mov.b64 %0, {%1, %1};" : "=l"(r) : "f"(x)); return r;
}
__device__ __forceinline__ float2 unpack2(ull v) {
    float2 f; asm("mov.b64 {%0, %1}, %2;" : "=f"(f.x), "=f"(f.y) : "l"(v)); return f;
}

// ---------------- fast activations ------------------------------------------
__device__ __forceinline__ float fsig(float x) {
    return __fdividef(1.f, 1.f + __expf(-x));
}
__device__ __forceinline__ float ftanh(float x) {
    return 1.f - __fdividef(2.f, 1.f + __expf(2.f * x));
}

// ---------------- cp.async helpers -----------------------------------------
__device__ __forceinline__ void cp_async16(void* smem_dst, const void* gmem_src) {
    unsigned saddr = (unsigned)__cvta_generic_to_shared(smem_dst);
    asm volatile("cp.async.cg.shared.global [%0], [%1], 16;" :: "r"(saddr), "l"(gmem_src));
}
__device__ __forceinline__ void cp_async16u(unsigned saddr, const void* gmem_src) {
    asm volatile("cp.async.cg.shared.global [%0], [%1], 16;" :: "r"(saddr), "l"(gmem_src));
}
__device__ __forceinline__ void cp_commit() { asm volatile("cp.async.commit_group;"); }
__device__ __forceinline__ void cp_wait0()  { asm volatile("cp.async.wait_group 0;" ::: "memory"); }
__device__ __forceinline__ void cp_wait1()  { asm volatile("cp.async.wait_group 1;" ::: "memory"); }

__device__ __forceinline__ unsigned smem_u32(const void* p) {
    return (unsigned)__cvta_generic_to_shared(p);
}
__device__ __forceinline__ uint32_t cvt_f16x2(float hi, float lo) {
    uint32_t r; asm("cvt.rn.f16x2.f32 %0, %1, %2;" : "=r"(r) : "f"(hi), "f"(lo)); return r;
}

// ---------------- release/acquire flag helpers ------------------------------
__device__ __forceinline__ unsigned ld_acq(const unsigned* p) {
    unsigned v;
    asm volatile("ld.acquire.gpu.global.u32 %0, [%1];" : "=r"(v) : "l"(p));
    return v;
}
__device__ __forceinline__ void red_rel_add(unsigned* p, unsigned v) {
    asm volatile("red.release.gpu.global.add.u32 [%0], %1;" :: "l"(p), "r"(v));
}

// ---------------- warp-level mma helpers ------------------------------------
__device__ __forceinline__ void ldsm_x4(uint32_t& r0, uint32_t& r1, uint32_t& r2, uint32_t& r3,
                                        uint32_t addr) {
    asm volatile("ldmatrix.sync.aligned.m8n8.x4.shared.b16 {%0,%1,%2,%3}, [%4];"
                 : "=r"(r0), "=r"(r1), "=r"(r2), "=r"(r3) : "r"(addr));
}
__device__ __forceinline__ void mma_f16(float* d, const uint32_t* a, const uint32_t* b) {
    asm volatile("mma.sync.aligned.m16n8k16.row.col.f32.f16.f16.f32 "
                 "{%0,%1,%2,%3}, {%4,%5,%6,%7}, {%8,%9}, {%0,%1,%2,%3};"
                 : "+f"(d[0]), "+f"(d[1]), "+f"(d[2]), "+f"(d[3])
                 : "r"(a[0]), "r"(a[1]), "r"(a[2]), "r"(a[3]), "r"(b[0]), "r"(b[1]));
}

// ---------------- legacy full group barrier (used once per layer, at end) ---
struct __align__(128) BarSlot { unsigned count; unsigned gen; unsigned pad[30]; };
__device__ BarSlot g_bar[MGRPS];

__device__ __forceinline__ void group_barrier(int grp) {
    __syncthreads();
    __threadfence();
    if (threadIdx.x == 0) {
        unsigned gen = atomicAdd(&g_bar[grp].gen, 0u);
        unsigned arrived = atomicAdd(&g_bar[grp].count, 1u);
        if (arrived == GRP_BLOCKS - 1u) {
            atomicExch(&g_bar[grp].count, 0u);
            __threadfence();
            atomicExch(&g_bar[grp].gen, gen + 1u);
        } else {
            while (atomicAdd(&g_bar[grp].gen, 0u) == gen) { __nanosleep(20); }
        }
    }
    __syncthreads();
}

// ---------------- weight pre-pack kernels -----------------------------------
// Whh [4H, H] -> per u-tile (32 units x 4 gates = 128 n-cols) x 8 k-chunks,
// each chunk a 128n x 64k fp16 tile, SW128 swizzled.
__global__ void prepack_whh(const float* __restrict__ Whh,
                            __half* __restrict__ hi)
{
    int i = blockIdx.x * blockDim.x + threadIdx.x;   // 0 .. 2048*512-1
    int k = i & 511;
    int row = i >> 9;                                 // gate*512 + unit_global
    int gate = row >> 9;
    int ug = row & 511;
    int bu = ug >> 5, un = ug & 31;
    int n = gate * 32 + un;                           // 0..127 within tile
    int c = k >> 6, lk = k & 63;
    size_t off = ((size_t)(bu * 8 + c)) * 8192 + (SWZ128(n * 128 + lk * 2) >> 1);
    hi[off] = __float2half(Whh[(size_t)row * Hn + k]);
}

// Split W (N=2048 x K) into fp16 hi/lo, per (ntile, kchunk) 64x64 tile, SW128.
__global__ void prepack_b_kernel(const float* __restrict__ W,
                                 __half* __restrict__ hi,
                                 __half* __restrict__ lo,
                                 int K)
{
    int i = blockIdx.x * blockDim.x + threadIdx.x;
    int k = i % K;
    int n = i / K;
    int ntile = n >> 6, ln = n & 63;
    int kc = k >> 6, lk = k & 63;
    int nch = K >> 6;
    size_t off = ((size_t)(ntile * nch + kc)) * 4096 + (SWZ128(ln * 128 + lk * 2) >> 1);
    float w = W[(size_t)n * K + k];
    __half h = __float2half(w);
    hi[off] = h;
    lo[off] = __float2half(w - __half2float(h));
}

// ---------------- HMMA fp16 2-term GEMM: C = A @ W^T + b1 (+b2) ------------
#define MMAG_SMEM (32768 + 1024)
__global__ void __launch_bounds__(256, 2)
mma_gemm_kernel(const void* __restrict__ Avoid,
                const uint4* __restrict__ Wbhi,
                const uint4* __restrict__ Wblo,
                const float* __restrict__ b1,
                const float* __restrict__ b2,
                float* __restrict__ C,
                int K, int Ntot, int a_f16)
{
    extern __shared__ char dsm[];
    uint32_t usm = smem_u32(dsm);
    usm = (usm + 1023u) & ~1023u;
    const uint32_t uAhi = usm;              // 128 x 64 fp16 = 16KB
    const uint32_t uBhi = usm + 16384;      // 8KB
    const uint32_t uBlo = usm + 24576;      // 8KB

    const int bn = blockIdx.x;
    const int m0 = blockIdx.y * 128;
    const int n0 = bn * 64;
    const int tid = threadIdx.x;
    const int w = tid >> 5;
    const int lane = tid & 31;
    const int mw = (w & 3) * 32;
    const int nw = (w >> 2) * 32;
    const int nch = K >> 6;

    const uint32_t xorv  = (uint32_t)(lane & 7) << 4;
    const uint32_t aRow  = mw + (lane & 15);
    const uint32_t aKsel = (uint32_t)(lane >> 4) << 4;
    const uint32_t bRow  = nw + (lane & 7) + ((lane >> 4) << 3);
    const uint32_t bKsel = (uint32_t)((lane >> 3) & 1) << 4;

    float acc[2][4][4];
#pragma unroll
    for (int mt = 0; mt < 2; mt++)
#pragma unroll
        for (int nt = 0; nt < 4; nt++)
#pragma unroll
            for (int e = 0; e < 4; e++) acc[mt][nt][e] = 0.f;

    for (int c = 0; c < nch; c++) {
        if (c) __syncthreads();

        const uint4* sbh = Wbhi + ((size_t)bn * nch + c) * 512;
        const uint4* sbl = Wblo + ((size_t)bn * nch + c) * 512;
        cp_async16u(uBhi + (uint32_t)tid * 16,         sbh + tid);
        cp_async16u(uBhi + (uint32_t)(tid + 256) * 16, sbh + tid + 256);
        cp_async16u(uBlo + (uint32_t)tid * 16,         sbl + tid);
        cp_async16u(uBlo + (uint32_t)(tid + 256) * 16, sbl + tid + 256);

        if (a_f16) {
            const uint4* Af = (const uint4*)Avoid;
            const int krow = K >> 3;
#pragma unroll
            for (int j = 0; j < 4; j++) {
                int idx = tid + j * 256;
                int r = idx >> 3, q = idx & 7;
                cp_async16u(uAhi + SWZ128((uint32_t)r * 128 + (uint32_t)q * 16),
                            Af + (size_t)(m0 + r) * krow + c * 8 + q);
            }
            cp_commit();
            cp_wait0();
            __syncthreads();
        } else {
            cp_commit();
            const float* A = (const float*)Avoid;
            const int k0 = c * 64;
#pragma unroll
            for (int it = 0; it < 8; it++) {
                int idx = tid + it * 256;
                int r = idx >> 4, f4 = idx & 15;
                float4 v = *(const float4*)(A + (size_t)(m0 + r) * K + k0 + f4 * 4);
                uint32_t h01 = cvt_f16x2(v.y, v.x);
                uint32_t h23 = cvt_f16x2(v.w, v.z);
                uint32_t sw = (uint32_t)r * 128 + (((uint32_t)f4 * 8) ^ (((uint32_t)r & 7) << 4));
                asm volatile("st.shared.v2.u32 [%0], {%1,%2};" :: "r"(uAhi + sw), "r"(h01), "r"(h23));
            }
            cp_wait0();
            __syncthreads();
        }

#pragma unroll
        for (int ks = 0; ks < 4; ks++) {
            const uint32_t kbA = ((uint32_t)(32 * ks) + aKsel) ^ xorv;
            const uint32_t kbB = ((uint32_t)(32 * ks) + bKsel) ^ xorv;
            uint32_t ah0[4], ah1[4];
            ldsm_x4(ah0[0], ah0[1], ah0[2], ah0[3], uAhi + aRow * 128 + kbA);
            ldsm_x4(ah1[0], ah1[1], ah1[2], ah1[3], uAhi + (aRow + 16) * 128 + kbA);
            uint32_t bh[8], bl[8];
            ldsm_x4(bh[0], bh[1], bh[2], bh[3], uBhi + bRow * 128 + kbB);
            ldsm_x4(bh[4], bh[5], bh[6], bh[7], uBhi + (bRow + 16) * 128 + kbB);
            ldsm_x4(bl[0], bl[1], bl[2], bl[3], uBlo + bRow * 128 + kbB);
            ldsm_x4(bl[4], bl[5], bl[6], bl[7], uBlo + (bRow + 16) * 128 + kbB);
#pragma unroll
            for (int mt = 0; mt < 2; mt++) {
                const uint32_t* Ah = mt ? ah1 : ah0;
#pragma unroll
                for (int nt = 0; nt < 4; nt++) {
                    mma_f16(acc[mt][nt], Ah, bh + nt * 2);
                    mma_f16(acc[mt][nt], Ah, bl + nt * 2);
                }
            }
        }
    }

    const int gid = lane >> 2, tig = lane & 3;
    float2 bias[4];
#pragma unroll
    for (int nt = 0; nt < 4; nt++) {
        int col = n0 + nw + nt * 8 + tig * 2;
        bias[nt].x = b1[col]     + (b2 ? b2[col]     : 0.f);
        bias[nt].y = b1[col + 1] + (b2 ? b2[col + 1] : 0.f);
    }
#pragma unroll
    for (int mt = 0; mt < 2; mt++) {
        int row0 = m0 + mw + mt * 16 + gid;
#pragma unroll
        for (int nt = 0; nt < 4; nt++) {
            int col = n0 + nw + nt * 8 + tig * 2;
            float2 v0, v1;
            v0.x = acc[mt][nt][0] + bias[nt].x;
            v0.y = acc[mt][nt][1] + bias[nt].y;
            v1.x = acc[mt][nt][2] + bias[nt].x;
            v1.y = acc[mt][nt][3] + bias[nt].y;
            *(float2*)&C[(size_t)row0 * Ntot + col]       = v0;
            *(float2*)&C[(size_t)(row0 + 8) * Ntot + col] = v1;
        }
    }
}

// ---------------- persistent HMMA fp16 LSTM layer kernel --------------------
// Grid (16, 8): block = 32 units x 4 gates (128 n-cols) x 32 batch rows.
// W fp16 resident in smem (128KB). h fp16 staged per step (32KB, 2 groups).
// Sync: producer-only release flag; consumers poll acquire-loads.
#define STEP_SMEM (131072 + 32768 + 1024)
__global__ void __launch_bounds__(256)
lstm_layer_mma(const float* __restrict__ xg,        // [B, T, 4H]
               const uint4* __restrict__ Whi,       // prepacked, this layer
               __half* __restrict__ hX, __half* __restrict__ hY,
               __half* __restrict__ h_all,          // layer0: [B,T,H] fp16; else null
               float* __restrict__ h_final)         // layer1: [B,H]; else null
{
    __shared__ float sG[32 * 133];                  // gate tile, stride 133 (odd words)
    extern __shared__ char dsm[];
    uint32_t usm = smem_u32(dsm);
    usm = (usm + 1023u) & ~1023u;
    const uint32_t uWhi = usm;                      // 8 chunks x 16KB = 128KB
    const uint32_t uH   = usm + 131072;             // 8 chunks x 4KB = 32KB

    const int bu  = blockIdx.x;                     // u-tile 0..15
    const int grp = blockIdx.y;                     // m-group 0..7
    const int m0  = grp * 32;
    const int tid = threadIdx.x;
    const int w   = tid >> 5;
    const int lane = tid & 31;
    const int mw = (w & 1) * 16;                    // 16 rows per warp (of 32)
    const int nw = (w >> 1) * 32;                   // 32 cols per warp (of 128)

    const uint32_t xorv  = (uint32_t)(lane & 7) << 4;
    const uint32_t aRow  = mw + (lane & 15);
    const uint32_t aKsel = (uint32_t)(lane >> 4) << 4;
    const uint32_t bRow  = nw + (lane & 7) + ((lane >> 4) << 3);
    const uint32_t bKsel = (uint32_t)((lane >> 3) & 1) << 4;
    const int gid = lane >> 2, tig = lane & 3;

    unsigned* flag = &g_hflag[grp * 32];

    // ---- load resident weights (once): 128KB = 8192 uint4 ----
    {
        const uint4* sh = Whi + (size_t)bu * 8192;
#pragma unroll
        for (int j = 0; j < 32; j++) {
            int idx = tid + j * 256;
            cp_async16u(uWhi + (uint32_t)idx * 16, sh + idx);
        }
        cp_commit();
        cp_wait0();
        __syncthreads();
    }

    // ---- per-thread cell mapping: row = tid&31, units ug*4 .. +3 ----
    const int cm  = tid & 31;
    const int ug  = tid >> 5;                        // 0..7
    const int grow = m0 + cm;                        // global batch row
    const int gcol = bu * 32 + ug * 4;               // global unit col (x4)

    float creg[4] = {0.f, 0.f, 0.f, 0.f};
    float xvf[4][4];                                 // [gate][j]
    {
        const float* xr = xg + ((size_t)grow * Tn + 0) * G4H + gcol;
#pragma unroll
        for (int g = 0; g < 4; g++)
            *(float4*)&xvf[g][0] = __ldcg((const float4*)(xr + g * 512));
    }

    // h staging per chunk: 32 rows x 64 k fp16 = 4KB = 256 cp.async = 1/thread
    const int s_r = tid >> 3, s_q = tid & 7;

    for (int t = 0; t < Tn; t++) {
        const __half* hin = (t & 1) ? hX : hY;
        __half* hout      = (t & 1) ? hY : hX;

        if (t > 0) {
            // wait for all 16 producers of this m-group to publish h_{t-1}
            if (tid == 0) {
                while (ld_acq(flag) < 16u * (unsigned)t) { __nanosleep(20); }
            }
            __syncthreads();

            // stage 8 chunks in 2 commit groups of 4
#pragma unroll
            for (int g2 = 0; g2 < 2; g2++) {
#pragma unroll
                for (int cc = 0; cc < 4; cc++) {
                    int c = g2 * 4 + cc;
                    cp_async16u(uH + (uint32_t)c * 4096 +
                                SWZ128((uint32_t)s_r * 128 + (uint32_t)s_q * 16),
                                hin + (size_t)(m0 + s_r) * Hn + c * 64 + s_q * 8);
                }
                cp_commit();
            }

            float acc[4][4];
#pragma unroll
            for (int nt = 0; nt < 4; nt++)
#pragma unroll
                for (int e = 0; e < 4; e++) acc[nt][e] = 0.f;

#pragma unroll
            for (int c = 0; c < 8; c++) {
                if (c == 0) { cp_wait1(); __syncthreads(); }
                if (c == 4) { cp_wait0(); __syncthreads(); }
                const uint32_t uA = uH + (uint32_t)c * 4096;
                const uint32_t wh = uWhi + (uint32_t)c * 16384;
#pragma unroll
                for (int ks = 0; ks < 4; ks++) {
                    const uint32_t kbA = ((uint32_t)(32 * ks) + aKsel) ^ xorv;
                    const uint32_t kbB = ((uint32_t)(32 * ks) + bKsel) ^ xorv;
                    uint32_t a0[4], bh[8];
                    ldsm_x4(a0[0], a0[1], a0[2], a0[3], uA + aRow * 128 + kbA);
                    ldsm_x4(bh[0], bh[1], bh[2], bh[3], wh + bRow * 128 + kbB);
                    ldsm_x4(bh[4], bh[5], bh[6], bh[7], wh + (bRow + 16) * 128 + kbB);
#pragma unroll
                    for (int nt = 0; nt < 4; nt++)
                        mma_f16(acc[nt], a0, bh + nt * 2);
                }
            }

            // fragments -> sG (no pre-sync needed: prior reads fenced by staging syncs)
            {
                int r0 = mw + gid;
#pragma unroll
                for (int nt = 0; nt < 4; nt++) {
                    int nc = nw + nt * 8 + tig * 2;
                    sG[r0 * 133 + nc]           = acc[nt][0];
                    sG[r0 * 133 + nc + 1]       = acc[nt][1];
                    sG[(r0 + 8) * 133 + nc]     = acc[nt][2];
                    sG[(r0 + 8) * 133 + nc + 1] = acc[nt][3];
                }
            }
            __syncthreads();
        }

        // ---- cell update: 4 cells per thread ----
        float hn4[4];
#pragma unroll
        for (int j = 0; j < 4; j++) {
            int uloc = ug * 4 + j;                   // unit within tile (0..31)
            float ri = 0.f, rf = 0.f, rg = 0.f, ro = 0.f;
            if (t > 0) {
                ri = sG[cm * 133 + uloc];            // gate 0 at cols 0..31
                rf = sG[cm * 133 + 32 + uloc];
                rg = sG[cm * 133 + 64 + uloc];
                ro = sG[cm * 133 + 96 + uloc];
            }
            float gi = ri + xvf[0][j];
            float gf = rf + xvf[1][j];
            float gg = rg + xvf[2][j];
            float go = ro + xvf[3][j];
            float cn = fsig(gf) * creg[j] + fsig(gi) * ftanh(gg);
            creg[j] = cn;
            hn4[j] = fsig(go) * ftanh(cn);
        }
        // write h (fp16)
        {
            uint32_t p01 = cvt_f16x2(hn4[1], hn4[0]);
            uint32_t p23 = cvt_f16x2(hn4[3], hn4[2]);
            size_t ho = (size_t)grow * Hn + gcol;
            *(uint2*)(hout + ho) = make_uint2(p01, p23);
            if (h_all)
                *(uint2*)(h_all + ((size_t)grow * Tn + t) * Hn + gcol) = make_uint2(p01, p23);
        }
        if (h_final && t == Tn - 1) {
            float4 v = make_float4(hn4[0], hn4[1], hn4[2], hn4[3]);
            *(float4*)&h_final[(size_t)grow * Hn + gcol] = v;
        }

        if (t < Tn - 1) {
            // prefetch xg for t+1 (h-independent; completes during next poll)
            const float* xr = xg + ((size_t)grow * Tn + (t + 1)) * G4H + gcol;
#pragma unroll
            for (int g = 0; g < 4; g++)
                *(float4*)&xvf[g][0] = __ldcg((const float4*)(xr + g * 512));

            // publish: all block stores -> bar -> single release-red
            __syncthreads();
            if (tid == 0) red_rel_add(flag, 1u);
        }
    }

    // ---- end of layer: full barrier once, then reset flags (replay-safe) ----
    group_barrier(grp);
    if (bu == 0 && tid == 0) *flag = 0u;
}

// ---------------- fp32 tiled GEMM (kept for FC1) ----------------------------
__global__ void __launch_bounds__(256, 2)
gemm_bias_kernel(const float* __restrict__ A,
                 const float* __restrict__ W,
                 const float* __restrict__ b1,
                 const float* __restrict__ b2,
                 float* __restrict__ C,
                 int M, int N, int K, int relu)
{
    __shared__ __align__(16) float As[2][128][GKC];
    __shared__ __align__(16) float Bs[2][GKC][64];
    const int m0 = blockIdx.y * 128;
    const int n0 = blockIdx.x * 64;
    const int tid = threadIdx.x;
    const int cx = tid & 15;
    const int ry = tid >> 4;

    ull acc01[8], acc23[8];
#pragma unroll
    for (int i = 0; i < 8; i++) { acc01[i] = 0ull; acc23[i] = 0ull; }

    const int nch = K / GKC;
    const int bcol = tid & 63, bq = tid >> 6;

#pragma unroll
    for (int i = 0; i < 2; i++) {
        int idx = tid + i * 256;
        cp_async16(&As[0][idx >> 2][(idx & 3) * 4],
                   A + (size_t)(m0 + (idx >> 2)) * K + (idx & 3) * 4);
    }
    cp_commit();
    float4 pW = *(const float4*)(W + (size_t)(n0 + bcol) * K + bq * 4);
    Bs[0][bq * 4 + 0][bcol] = pW.x;
    Bs[0][bq * 4 + 1][bcol] = pW.y;
    Bs[0][bq * 4 + 2][bcol] = pW.z;
    Bs[0][bq * 4 + 3][bcol] = pW.w;

    for (int c = 0; c < nch; c++) {
        cp_wait0();
        __syncthreads();
        const int buf = c & 1;
        const bool more = (c + 1 < nch);
        if (more) {
            int k0 = (c + 1) * GKC;
#pragma unroll
            for (int i = 0; i < 2; i++) {
                int idx = tid + i * 256;
                cp_async16(&As[buf ^ 1][idx >> 2][(idx & 3) * 4],
                           A + (size_t)(m0 + (idx >> 2)) * K + k0 + (idx & 3) * 4);
            }
            cp_commit();
            pW = *(const float4*)(W + (size_t)(n0 + bcol) * K + k0 + bq * 4);
        }
#pragma unroll
        for (int k4 = 0; k4 < GKC; k4 += 4) {
            float4 a4[8];
#pragma unroll
            for (int i = 0; i < 8; i++) a4[i] = *(const float4*)&As[buf][ry + 16 * i][k4];
#pragma unroll
            for (int j = 0; j < 4; j++) {
                float4 w4 = *(const float4*)&Bs[buf][k4 + j][4 * cx];
                ull w01 = *reinterpret_cast<ull*>(&w4.x);
                ull w23 = *reinterpret_cast<ull*>(&w4.z);
#pragma unroll
                for (int i = 0; i < 8; i++) {
                    float av = (j == 0) ? a4[i].x : (j == 1) ? a4[i].y : (j == 2) ? a4[i].z : a4[i].w;
                    ull ad = pack2dup(av);
                    ffma2(acc01[i], ad, w01);
                    ffma2(acc23[i], ad, w23);
                }
            }
        }
        if (more) {
            Bs[buf ^ 1][bq * 4 + 0][bcol] = pW.x;
            Bs[buf ^ 1][bq * 4 + 1][bcol] = pW.y;
            Bs[buf ^ 1][bq * 4 + 2][bcol] = pW.z;
            Bs[buf ^ 1][bq * 4 + 3][bcol] = pW.w;
        }
    }

    const int col = n0 + 4 * cx;
    float bb0 = b1[col + 0], bb1 = b1[col + 1], bb2 = b1[col + 2], bb3 = b1[col + 3];
    if (b2) { bb0 += b2[col + 0]; bb1 += b2[col + 1]; bb2 += b2[col + 2]; bb3 += b2[col + 3]; }
#pragma unroll
    for (int i = 0; i < 8; i++) {
        int row = m0 + ry + 16 * i;
        float2 p01 = unpack2(acc01[i]);
        float2 p23 = unpack2(acc23[i]);
        float4 v;
        v.x = p01.x + bb0; v.y = p01.y + bb1; v.z = p23.x + bb2; v.w = p23.y + bb3;
        if (relu) { v.x = fmaxf(v.x, 0.f); v.y = fmaxf(v.y, 0.f); v.z = fmaxf(v.z, 0.f); v.w = fmaxf(v.w, 0.f); }
        *(float4*)&C[(size_t)row * N + col] = v;
    }
}

// ---------------- FC2: out[256,8] = z @ W_fc2^T + b ------------------------
__global__ void fc2_kernel(const float* __restrict__ z,
                           const float* __restrict__ W,
                           const float* __restrict__ b,
                           float* __restrict__ out)
{
    int row = blockIdx.x;
    int o = threadIdx.y;
    int lane = threadIdx.x;
    float s = 0.f;
    const float* zr = z + (size_t)row * FCn;
    const float* wr = W + (size_t)o * FCn;
    for (int k = lane; k < FCn; k += 32) s += zr[k] * wr[k];
#pragma unroll
    for (int off = 16; off; off >>= 1) s += __shfl_down_sync(0xffffffffu, s, off);
    if (lane == 0) out[row * OUTn + o] = s + b[o];
}

// ---------------- host orchestration ---------------------------------------
extern "C" void kernel_launch(void* const* d_in, const int* in_sizes, int n_in,
                              void* d_out, int out_size)
{
    const float* x      = (const float*)d_in[0];
    const float* W_ih0  = (const float*)d_in[1];
    const float* W_hh0  = (const float*)d_in[2];
    const float* b_ih0  = (const float*)d_in[3];
    const float* b_hh0  = (const float*)d_in[4];
    const float* W_ih1  = (const float*)d_in[5];
    const float* W_hh1  = (const float*)d_in[6];
    const float* b_ih1  = (const float*)d_in[7];
    const float* b_hh1  = (const float*)d_in[8];
    const float* W_fc1  = (const float*)d_in[9];
    const float* b_fc1  = (const float*)d_in[10];
    const float* W_fc2  = (const float*)d_in[11];
    const float* b_fc2  = (const float*)d_in[12];
    float* out = (float*)d_out;

    float *xg, *hfin, *z;
    __half *h0h, *hX, *hY, *whhHi;
    uint4 *wb0h, *wb0l, *wb1h, *wb1l;
    cudaGetSymbolAddress((void**)&xg,    g_xg);
    cudaGetSymbolAddress((void**)&h0h,   g_h0h);
    cudaGetSymbolAddress((void**)&hfin,  g_hfin);
    cudaGetSymbolAddress((void**)&z,     g_z);
    cudaGetSymbolAddress((void**)&hX,    g_hX);
    cudaGetSymbolAddress((void**)&hY,    g_hY);
    cudaGetSymbolAddress((void**)&whhHi, g_Whh_hi);
    cudaGetSymbolAddress((void**)&wb0h,  g_Wb0hi);
    cudaGetSymbolAddress((void**)&wb0l,  g_Wb0lo);
    cudaGetSymbolAddress((void**)&wb1h,  g_Wb1hi);
    cudaGetSymbolAddress((void**)&wb1l,  g_Wb1lo);

    cudaFuncSetAttribute(mma_gemm_kernel, cudaFuncAttributeMaxDynamicSharedMemorySize, MMAG_SMEM);
    cudaFuncSetAttribute(lstm_layer_mma,  cudaFuncAttributeMaxDynamicSharedMemorySize, STEP_SMEM);

    const int MT = Bn * Tn;                 // 131072
    dim3 mmaGrid(G4H / 64, MT / 128);       // (32, 1024)
    dim3 stepGrid(16, MGRPS);               // (16, 8) = 128 blocks

    const size_t WHL = (size_t)G4H * Hn;    // per-layer whh elements
    prepack_whh<<<(G4H * Hn) / 256, 256>>>(W_hh0, whhHi);
    prepack_whh<<<(G4H * Hn) / 256, 256>>>(W_hh1, whhHi + WHL);
    prepack_b_kernel<<<(G4H * Dn) / 256, 256>>>(W_ih0, (__half*)wb0h, (__half*)wb0l, Dn);
    prepack_b_kernel<<<(G4H * Hn) / 256, 256>>>(W_ih1, (__half*)wb1h, (__half*)wb1l, Hn);

    // ---- Layer 0 ----  xg = x @ W_ih0^T + b_ih0 + b_hh0 (K=64, A fp32)
    mma_gemm_kernel<<<mmaGrid, 256, MMAG_SMEM>>>(x, wb0h, wb0l, b_ih0, b_hh0, xg, Dn, G4H, 0);
    lstm_layer_mma<<<stepGrid, 256, STEP_SMEM>>>(xg, (const uint4*)whhHi,
                                                 hX, hY, h0h, (float*)0);

    // ---- Layer 1 ----  xg = h0 @ W_ih1^T + b_ih1 + b_hh1 (K=512, A fp16)
    mma_gemm_kernel<<<mmaGrid, 256, MMAG_SMEM>>>(h0h, wb1h, wb1l, b_ih1, b_hh1, xg, Hn, G4H, 1);
    lstm_layer_mma<<<stepGrid, 256, STEP_SMEM>>>(xg, (const uint4*)(whhHi + WHL),
                                                 hX, hY, (__half*)0, hfin);

    // ---- FC head ----
    dim3 fc1Grid(FCn / 64, Bn / 128);       // (8, 2)
    gemm_bias_kernel<<<fc1Grid, 256>>>(hfin, W_fc1, b_fc1, (const float*)0, z, Bn, FCn, Hn, 1);
    fc2_kernel<<<Bn, dim3(32, 8)>>>(z, W_fc2, b_fc2, out);
}

// round 12
// speedup vs baseline: 6.8738x; 1.1706x over previous
#include <cuda_runtime.h>
#include <cuda_fp16.h>
#include <cstddef>
#include <cstdint>

// Problem constants
#define Bn   256
#define Tn   512
#define Dn   64
#define Hn   512
#define G4H  2048   // 4*H
#define FCn  512
#define OUTn 8

#define GKC   16          // k-chunk in fp32 gemm kernel
#define MGRPS 8           // m-groups (Bn/32)
#define GRP_BLOCKS 16     // blocks per m-group (2048 cols / 128)

typedef unsigned long long ull;

#define SWZ128(off) ((off) ^ (((off) >> 3) & 0x70))

// ---------------- scratch (device globals; no runtime allocation) ----------
__device__ float g_xg[(size_t)Bn * Tn * G4H];
__device__ __half g_h0h[(size_t)Bn * Tn * Hn];     // layer-0 h, fp16 (feeds layer-1 GEMM)
__device__ float g_hfin[Bn * Hn];
__device__ float g_z[Bn * FCn];
// fp16 h state double buffers
__device__ __half g_hX[Bn * Hn], g_hY[Bn * Hn];
// prepacked recurrent weights, fp16, [layer][u_tile(16)][chunk(8)][128n x 64k swizzled]
__device__ __half g_Whh_hi[2][(size_t)G4H * Hn];
// fp16 pre-swizzled W_ih for mma gemm (hi only)
__device__ uint4 g_Wb0hi[G4H * Dn / 8];            // layer0: 2048x64
__device__ uint4 g_Wb1hi[G4H * Hn / 8];            // layer1: 2048x512

// producer-progress flags (one per m-group, padded to 128B)
__device__ unsigned g_hflag[MGRPS * 32];

// ---------------- f32x2 packed helpers (fp32 FC1 gemm) ----------------------
__device__ __forceinline__ void ffma2(ull& d, ull a, ull b) {
    asm("fma.rn.f32x2 %0, %1, %2, %0;" : "+l"(d) : "l"(a), "l"(b));
}
__device__ __forceinline__ ull pack2dup(float x) {
    ull r; asm("mov.b64 %0, {%1, %1};" : "=l"(r) : "f"(x)); return r;
}
__device__ __forceinline__ float2 unpack2(ull v) {
    float2 f; asm("mov.b64 {%0, %1}, %2;" : "=f"(f.x), "=f"(f.y) : "l"(v)); return f;
}

// ---------------- fast activations ------------------------------------------
__device__ __forceinline__ float fsig(float x) {
    return __fdividef(1.f, 1.f + __expf(-x));
}
__device__ __forceinline__ float ftanh(float x) {
    return 1.f - __fdividef(2.f, 1.f + __expf(2.f * x));
}

// ---------------- cp.async helpers -----------------------------------------
__device__ __forceinline__ void cp_async16(void* smem_dst, const void* gmem_src) {
    unsigned saddr = (unsigned)__cvta_generic_to_shared(smem_dst);
    asm volatile("cp.async.cg.shared.global [%0], [%1], 16;" :: "r"(saddr), "l"(gmem_src));
}
__device__ __forceinline__ void cp_async16u(unsigned saddr, const void* gmem_src) {
    asm volatile("cp.async.cg.shared.global [%0], [%1], 16;" :: "r"(saddr), "l"(gmem_src));
}
__device__ __forceinline__ void cp_commit() { asm volatile("cp.async.commit_group;"); }
__device__ __forceinline__ void cp_wait0()  { asm volatile("cp.async.wait_group 0;" ::: "memory"); }
__device__ __forceinline__ void cp_wait1()  { asm volatile("cp.async.wait_group 1;" ::: "memory"); }
__device__ __forceinline__ void cp_wait2()  { asm volatile("cp.async.wait_group 2;" ::: "memory"); }
__device__ __forceinline__ void cp_wait3()  { asm volatile("cp.async.wait_group 3;" ::: "memory"); }

__device__ __forceinline__ unsigned smem_u32(const void* p) {
    return (unsigned)__cvta_generic_to_shared(p);
}
__device__ __forceinline__ uint32_t cvt_f16x2(float hi, float lo) {
    uint32_t r; asm("cvt.rn.f16x2.f32 %0, %1, %2;" : "=r"(r) : "f"(hi), "f"(lo)); return r;
}

// ---------------- release/acquire flag helpers ------------------------------
__device__ __forceinline__ unsigned ld_acq(const unsigned* p) {
    unsigned v;
    asm volatile("ld.acquire.gpu.global.u32 %0, [%1];" : "=r"(v) : "l"(p));
    return v;
}
__device__ __forceinline__ void red_rel_add(unsigned* p, unsigned v) {
    asm volatile("red.release.gpu.global.add.u32 [%0], %1;" :: "l"(p), "r"(v));
}

// ---------------- warp-level mma helpers ------------------------------------
__device__ __forceinline__ void ldsm_x4(uint32_t& r0, uint32_t& r1, uint32_t& r2, uint32_t& r3,
                                        uint32_t addr) {
    asm volatile("ldmatrix.sync.aligned.m8n8.x4.shared.b16 {%0,%1,%2,%3}, [%4];"
                 : "=r"(r0), "=r"(r1), "=r"(r2), "=r"(r3) : "r"(addr));
}
__device__ __forceinline__ void mma_f16(float* d, const uint32_t* a, const uint32_t* b) {
    asm volatile("mma.sync.aligned.m16n8k16.row.col.f32.f16.f16.f32 "
                 "{%0,%1,%2,%3}, {%4,%5,%6,%7}, {%8,%9}, {%0,%1,%2,%3};"
                 : "+f"(d[0]), "+f"(d[1]), "+f"(d[2]), "+f"(d[3])
                 : "r"(a[0]), "r"(a[1]), "r"(a[2]), "r"(a[3]), "r"(b[0]), "r"(b[1]));
}

// ---------------- legacy full group barrier (used once per layer, at end) ---
struct __align__(128) BarSlot { unsigned count; unsigned gen; unsigned pad[30]; };
__device__ BarSlot g_bar[MGRPS];

__device__ __forceinline__ void group_barrier(int grp) {
    __syncthreads();
    __threadfence();
    if (threadIdx.x == 0) {
        unsigned gen = atomicAdd(&g_bar[grp].gen, 0u);
        unsigned arrived = atomicAdd(&g_bar[grp].count, 1u);
        if (arrived == GRP_BLOCKS - 1u) {
            atomicExch(&g_bar[grp].count, 0u);
            __threadfence();
            atomicExch(&g_bar[grp].gen, gen + 1u);
        } else {
            while (atomicAdd(&g_bar[grp].gen, 0u) == gen) { __nanosleep(20); }
        }
    }
    __syncthreads();
}

// ---------------- weight pre-pack kernels -----------------------------------
// Whh [4H, H] -> per u-tile (32 units x 4 gates = 128 n-cols) x 8 k-chunks,
// each chunk a 128n x 64k fp16 tile, SW128 swizzled.
__global__ void prepack_whh(const float* __restrict__ Whh,
                            __half* __restrict__ hi)
{
    int i = blockIdx.x * blockDim.x + threadIdx.x;   // 0 .. 2048*512-1
    int k = i & 511;
    int row = i >> 9;                                 // gate*512 + unit_global
    int gate = row >> 9;
    int ug = row & 511;
    int bu = ug >> 5, un = ug & 31;
    int n = gate * 32 + un;                           // 0..127 within tile
    int c = k >> 6, lk = k & 63;
    size_t off = ((size_t)(bu * 8 + c)) * 8192 + (SWZ128(n * 128 + lk * 2) >> 1);
    hi[off] = __float2half(Whh[(size_t)row * Hn + k]);
}

// W (N=2048 x K) -> fp16 hi, per (ntile, kchunk) 64x64 tile, SW128.
__global__ void prepack_b_kernel(const float* __restrict__ W,
                                 __half* __restrict__ hi,
                                 int K)
{
    int i = blockIdx.x * blockDim.x + threadIdx.x;
    int k = i % K;
    int n = i / K;
    int ntile = n >> 6, ln = n & 63;
    int kc = k >> 6, lk = k & 63;
    int nch = K >> 6;
    size_t off = ((size_t)(ntile * nch + kc)) * 4096 + (SWZ128(ln * 128 + lk * 2) >> 1);
    hi[off] = __float2half(W[(size_t)n * K + k]);
}

// ---------------- HMMA fp16 1-term GEMM: C = A @ W^T + b1 (+b2) ------------
#define MMAG_SMEM (24576 + 1024)
__global__ void __launch_bounds__(256, 2)
mma_gemm_kernel(const void* __restrict__ Avoid,
                const uint4* __restrict__ Wbhi,
                const float* __restrict__ b1,
                const float* __restrict__ b2,
                float* __restrict__ C,
                int K, int Ntot, int a_f16)
{
    extern __shared__ char dsm[];
    uint32_t usm = smem_u32(dsm);
    usm = (usm + 1023u) & ~1023u;
    const uint32_t uAhi = usm;              // 128 x 64 fp16 = 16KB
    const uint32_t uBhi = usm + 16384;      // 8KB

    const int bn = blockIdx.x;
    const int m0 = blockIdx.y * 128;
    const int n0 = bn * 64;
    const int tid = threadIdx.x;
    const int w = tid >> 5;
    const int lane = tid & 31;
    const int mw = (w & 3) * 32;
    const int nw = (w >> 2) * 32;
    const int nch = K >> 6;

    const uint32_t xorv  = (uint32_t)(lane & 7) << 4;
    const uint32_t aRow  = mw + (lane & 15);
    const uint32_t aKsel = (uint32_t)(lane >> 4) << 4;
    const uint32_t bRow  = nw + (lane & 7) + ((lane >> 4) << 3);
    const uint32_t bKsel = (uint32_t)((lane >> 3) & 1) << 4;

    float acc[2][4][4];
#pragma unroll
    for (int mt = 0; mt < 2; mt++)
#pragma unroll
        for (int nt = 0; nt < 4; nt++)
#pragma unroll
            for (int e = 0; e < 4; e++) acc[mt][nt][e] = 0.f;

    for (int c = 0; c < nch; c++) {
        if (c) __syncthreads();

        const uint4* sbh = Wbhi + ((size_t)bn * nch + c) * 512;
        cp_async16u(uBhi + (uint32_t)tid * 16,         sbh + tid);
        cp_async16u(uBhi + (uint32_t)(tid + 256) * 16, sbh + tid + 256);

        if (a_f16) {
            const uint4* Af = (const uint4*)Avoid;
            const int krow = K >> 3;
#pragma unroll
            for (int j = 0; j < 4; j++) {
                int idx = tid + j * 256;
                int r = idx >> 3, q = idx & 7;
                cp_async16u(uAhi + SWZ128((uint32_t)r * 128 + (uint32_t)q * 16),
                            Af + (size_t)(m0 + r) * krow + c * 8 + q);
            }
            cp_commit();
            cp_wait0();
            __syncthreads();
        } else {
            cp_commit();
            const float* A = (const float*)Avoid;
            const int k0 = c * 64;
#pragma unroll
            for (int it = 0; it < 8; it++) {
                int idx = tid + it * 256;
                int r = idx >> 4, f4 = idx & 15;
                float4 v = *(const float4*)(A + (size_t)(m0 + r) * K + k0 + f4 * 4);
                uint32_t h01 = cvt_f16x2(v.y, v.x);
                uint32_t h23 = cvt_f16x2(v.w, v.z);
                uint32_t sw = (uint32_t)r * 128 + (((uint32_t)f4 * 8) ^ (((uint32_t)r & 7) << 4));
                asm volatile("st.shared.v2.u32 [%0], {%1,%2};" :: "r"(uAhi + sw), "r"(h01), "r"(h23));
            }
            cp_wait0();
            __syncthreads();
        }

#pragma unroll
        for (int ks = 0; ks < 4; ks++) {
            const uint32_t kbA = ((uint32_t)(32 * ks) + aKsel) ^ xorv;
            const uint32_t kbB = ((uint32_t)(32 * ks) + bKsel) ^ xorv;
            uint32_t ah0[4], ah1[4];
            ldsm_x4(ah0[0], ah0[1], ah0[2], ah0[3], uAhi + aRow * 128 + kbA);
            ldsm_x4(ah1[0], ah1[1], ah1[2], ah1[3], uAhi + (aRow + 16) * 128 + kbA);
            uint32_t bh[8];
            ldsm_x4(bh[0], bh[1], bh[2], bh[3], uBhi + bRow * 128 + kbB);
            ldsm_x4(bh[4], bh[5], bh[6], bh[7], uBhi + (bRow + 16) * 128 + kbB);
#pragma unroll
            for (int mt = 0; mt < 2; mt++) {
                const uint32_t* Ah = mt ? ah1 : ah0;
#pragma unroll
                for (int nt = 0; nt < 4; nt++)
                    mma_f16(acc[mt][nt], Ah, bh + nt * 2);
            }
        }
    }

    const int gid = lane >> 2, tig = lane & 3;
    float2 bias[4];
#pragma unroll
    for (int nt = 0; nt < 4; nt++) {
        int col = n0 + nw + nt * 8 + tig * 2;
        bias[nt].x = b1[col]     + (b2 ? b2[col]     : 0.f);
        bias[nt].y = b1[col + 1] + (b2 ? b2[col + 1] : 0.f);
    }
#pragma unroll
    for (int mt = 0; mt < 2; mt++) {
        int row0 = m0 + mw + mt * 16 + gid;
#pragma unroll
        for (int nt = 0; nt < 4; nt++) {
            int col = n0 + nw + nt * 8 + tig * 2;
            float2 v0, v1;
            v0.x = acc[mt][nt][0] + bias[nt].x;
            v0.y = acc[mt][nt][1] + bias[nt].y;
            v1.x = acc[mt][nt][2] + bias[nt].x;
            v1.y = acc[mt][nt][3] + bias[nt].y;
            *(float2*)&C[(size_t)row0 * Ntot + col]       = v0;
            *(float2*)&C[(size_t)(row0 + 8) * Ntot + col] = v1;
        }
    }
}

// ---------------- persistent HMMA fp16 LSTM layer kernel --------------------
// Grid (16, 8): block = 32 units x 4 gates (128 n-cols) x 32 batch rows.
// W fp16 resident in smem (128KB). h fp16 staged per step (32KB, 4 groups of 2
// chunks — first MMA starts after only 8KB lands).
// Sync: producer-only release flag; consumers tight-poll acquire-loads.
#define STEP_SMEM (131072 + 32768 + 1024)
__global__ void __launch_bounds__(256)
lstm_layer_mma(const float* __restrict__ xg,        // [B, T, 4H]
               const uint4* __restrict__ Whi,       // prepacked, this layer
               __half* __restrict__ hX, __half* __restrict__ hY,
               __half* __restrict__ h_all,          // layer0: [B,T,H] fp16; else null
               float* __restrict__ h_final)         // layer1: [B,H]; else null
{
    __shared__ float sG[32 * 133];                  // gate tile, stride 133 (odd words)
    extern __shared__ char dsm[];
    uint32_t usm = smem_u32(dsm);
    usm = (usm + 1023u) & ~1023u;
    const uint32_t uWhi = usm;                      // 8 chunks x 16KB = 128KB
    const uint32_t uH   = usm + 131072;             // 8 chunks x 4KB = 32KB

    const int bu  = blockIdx.x;                     // u-tile 0..15
    const int grp = blockIdx.y;                     // m-group 0..7
    const int m0  = grp * 32;
    const int tid = threadIdx.x;
    const int w   = tid >> 5;
    const int lane = tid & 31;
    const int mw = (w & 1) * 16;                    // 16 rows per warp (of 32)
    const int nw = (w >> 1) * 32;                   // 32 cols per warp (of 128)

    const uint32_t xorv  = (uint32_t)(lane & 7) << 4;
    const uint32_t aRow  = mw + (lane & 15);
    const uint32_t aKsel = (uint32_t)(lane >> 4) << 4;
    const uint32_t bRow  = nw + (lane & 7) + ((lane >> 4) << 3);
    const uint32_t bKsel = (uint32_t)((lane >> 3) & 1) << 4;
    const int gid = lane >> 2, tig = lane & 3;

    unsigned* flag = &g_hflag[grp * 32];

    // ---- load resident weights (once): 128KB = 8192 uint4 ----
    {
        const uint4* sh = Whi + (size_t)bu * 8192;
#pragma unroll
        for (int j = 0; j < 32; j++) {
            int idx = tid + j * 256;
            cp_async16u(uWhi + (uint32_t)idx * 16, sh + idx);
        }
        cp_commit();
        cp_wait0();
        __syncthreads();
    }

    // ---- per-thread cell mapping: row = tid&31, units ug*4 .. +3 ----
    const int cm  = tid & 31;
    const int ug  = tid >> 5;                        // 0..7
    const int grow = m0 + cm;                        // global batch row
    const int gcol = bu * 32 + ug * 4;               // global unit col (x4)

    float creg[4] = {0.f, 0.f, 0.f, 0.f};
    float xvf[4][4];                                 // [gate][j]
    {
        const float* xr = xg + ((size_t)grow * Tn + 0) * G4H + gcol;
#pragma unroll
        for (int g = 0; g < 4; g++)
            *(float4*)&xvf[g][0] = __ldcg((const float4*)(xr + g * 512));
    }

    // h staging per chunk: 32 rows x 64 k fp16 = 4KB = 256 cp.async = 1/thread
    const int s_r = tid >> 3, s_q = tid & 7;

    for (int t = 0; t < Tn; t++) {
        const __half* hin = (t & 1) ? hX : hY;
        __half* hout      = (t & 1) ? hY : hX;

        if (t > 0) {
            // wait for all 16 producers of this m-group to publish h_{t-1}
            if (tid == 0) {
                while (ld_acq(flag) < 16u * (unsigned)t) { }
            }
            __syncthreads();

            // stage 8 chunks in 4 commit groups of 2
#pragma unroll
            for (int g2 = 0; g2 < 4; g2++) {
#pragma unroll
                for (int cc = 0; cc < 2; cc++) {
                    int c = g2 * 2 + cc;
                    cp_async16u(uH + (uint32_t)c * 4096 +
                                SWZ128((uint32_t)s_r * 128 + (uint32_t)s_q * 16),
                                hin + (size_t)(m0 + s_r) * Hn + c * 64 + s_q * 8);
                }
                cp_commit();
            }

            float acc[4][4];
#pragma unroll
            for (int nt = 0; nt < 4; nt++)
#pragma unroll
                for (int e = 0; e < 4; e++) acc[nt][e] = 0.f;

#pragma unroll
            for (int c = 0; c < 8; c++) {
                if (c == 0) { cp_wait3(); __syncthreads(); }
                else if (c == 2) { cp_wait2(); __syncthreads(); }
                else if (c == 4) { cp_wait1(); __syncthreads(); }
                else if (c == 6) { cp_wait0(); __syncthreads(); }
                const uint32_t uA = uH + (uint32_t)c * 4096;
                const uint32_t wh = uWhi + (uint32_t)c * 16384;
#pragma unroll
                for (int ks = 0; ks < 4; ks++) {
                    const uint32_t kbA = ((uint32_t)(32 * ks) + aKsel) ^ xorv;
                    const uint32_t kbB = ((uint32_t)(32 * ks) + bKsel) ^ xorv;
                    uint32_t a0[4], bh[8];
                    ldsm_x4(a0[0], a0[1], a0[2], a0[3], uA + aRow * 128 + kbA);
                    ldsm_x4(bh[0], bh[1], bh[2], bh[3], wh + bRow * 128 + kbB);
                    ldsm_x4(bh[4], bh[5], bh[6], bh[7], wh + (bRow + 16) * 128 + kbB);
#pragma unroll
                    for (int nt = 0; nt < 4; nt++)
                        mma_f16(acc[nt], a0, bh + nt * 2);
                }
            }

            // fragments -> sG
            {
                int r0 = mw + gid;
#pragma unroll
                for (int nt = 0; nt < 4; nt++) {
                    int nc = nw + nt * 8 + tig * 2;
                    sG[r0 * 133 + nc]           = acc[nt][0];
                    sG[r0 * 133 + nc + 1]       = acc[nt][1];
                    sG[(r0 + 8) * 133 + nc]     = acc[nt][2];
                    sG[(r0 + 8) * 133 + nc + 1] = acc[nt][3];
                }
            }
            __syncthreads();
        }

        // ---- cell update: 4 cells per thread ----
        float hn4[4];
#pragma unroll
        for (int j = 0; j < 4; j++) {
            int uloc = ug * 4 + j;                   // unit within tile (0..31)
            float ri = 0.f, rf = 0.f, rg = 0.f, ro = 0.f;
            if (t > 0) {
                ri = sG[cm * 133 + uloc];            // gate 0 at cols 0..31
                rf = sG[cm * 133 + 32 + uloc];
                rg = sG[cm * 133 + 64 + uloc];
                ro = sG[cm * 133 + 96 + uloc];
            }
            float gi = ri + xvf[0][j];
            float gf = rf + xvf[1][j];
            float gg = rg + xvf[2][j];
            float go = ro + xvf[3][j];
            float cn = fsig(gf) * creg[j] + fsig(gi) * ftanh(gg);
            creg[j] = cn;
            hn4[j] = fsig(go) * ftanh(cn);
        }

        // write h (fp16) for consumers, then publish ASAP
        uint32_t p01 = cvt_f16x2(hn4[1], hn4[0]);
        uint32_t p23 = cvt_f16x2(hn4[3], hn4[2]);
        {
            size_t ho = (size_t)grow * Hn + gcol;
            *(uint2*)(hout + ho) = make_uint2(p01, p23);
        }
        if (t < Tn - 1) {
            __syncthreads();                         // all hout stores done
            if (tid == 0) red_rel_add(flag, 1u);     // release (off critical path below)
        }

        // off-critical-path work: h_all / h_final stores, xg prefetch
        if (h_all)
            *(uint2*)(h_all + ((size_t)grow * Tn + t) * Hn + gcol) = make_uint2(p01, p23);
        if (h_final && t == Tn - 1) {
            float4 v = make_float4(hn4[0], hn4[1], hn4[2], hn4[3]);
            *(float4*)&h_final[(size_t)grow * Hn + gcol] = v;
        }
        if (t < Tn - 1) {
            const float* xr = xg + ((size_t)grow * Tn + (t + 1)) * G4H + gcol;
#pragma unroll
            for (int g = 0; g < 4; g++)
                *(float4*)&xvf[g][0] = __ldcg((const float4*)(xr + g * 512));
        }
    }

    // ---- end of layer: full barrier once, then reset flags (replay-safe) ----
    group_barrier(grp);
    if (bu == 0 && tid == 0) *flag = 0u;
}

// ---------------- fp32 tiled GEMM (kept for FC1) ----------------------------
__global__ void __launch_bounds__(256, 2)
gemm_bias_kernel(const float* __restrict__ A,
                 const float* __restrict__ W,
                 const float* __restrict__ b1,
                 const float* __restrict__ b2,
                 float* __restrict__ C,
                 int M, int N, int K, int relu)
{
    __shared__ __align__(16) float As[2][128][GKC];
    __shared__ __align__(16) float Bs[2][GKC][64];
    const int m0 = blockIdx.y * 128;
    const int n0 = blockIdx.x * 64;
    const int tid = threadIdx.x;
    const int cx = tid & 15;
    const int ry = tid >> 4;

    ull acc01[8], acc23[8];
#pragma unroll
    for (int i = 0; i < 8; i++) { acc01[i] = 0ull; acc23[i] = 0ull; }

    const int nch = K / GKC;
    const int bcol = tid & 63, bq = tid >> 6;

#pragma unroll
    for (int i = 0; i < 2; i++) {
        int idx = tid + i * 256;
        cp_async16(&As[0][idx >> 2][(idx & 3) * 4],
                   A + (size_t)(m0 + (idx >> 2)) * K + (idx & 3) * 4);
    }
    cp_commit();
    float4 pW = *(const float4*)(W + (size_t)(n0 + bcol) * K + bq * 4);
    Bs[0][bq * 4 + 0][bcol] = pW.x;
    Bs[0][bq * 4 + 1][bcol] = pW.y;
    Bs[0][bq * 4 + 2][bcol] = pW.z;
    Bs[0][bq * 4 + 3][bcol] = pW.w;

    for (int c = 0; c < nch; c++) {
        cp_wait0();
        __syncthreads();
        const int buf = c & 1;
        const bool more = (c + 1 < nch);
        if (more) {
            int k0 = (c + 1) * GKC;
#pragma unroll
            for (int i = 0; i < 2; i++) {
                int idx = tid + i * 256;
                cp_async16(&As[buf ^ 1][idx >> 2][(idx & 3) * 4],
                           A + (size_t)(m0 + (idx >> 2)) * K + k0 + (idx & 3) * 4);
            }
            cp_commit();
            pW = *(const float4*)(W + (size_t)(n0 + bcol) * K + k0 + bq * 4);
        }
#pragma unroll
        for (int k4 = 0; k4 < GKC; k4 += 4) {
            float4 a4[8];
#pragma unroll
            for (int i = 0; i < 8; i++) a4[i] = *(const float4*)&As[buf][ry + 16 * i][k4];
#pragma unroll
            for (int j = 0; j < 4; j++) {
                float4 w4 = *(const float4*)&Bs[buf][k4 + j][4 * cx];
                ull w01 = *reinterpret_cast<ull*>(&w4.x);
                ull w23 = *reinterpret_cast<ull*>(&w4.z);
#pragma unroll
                for (int i = 0; i < 8; i++) {
                    float av = (j == 0) ? a4[i].x : (j == 1) ? a4[i].y : (j == 2) ? a4[i].z : a4[i].w;
                    ull ad = pack2dup(av);
                    ffma2(acc01[i], ad, w01);
                    ffma2(acc23[i], ad, w23);
                }
            }
        }
        if (more) {
            Bs[buf ^ 1][bq * 4 + 0][bcol] = pW.x;
            Bs[buf ^ 1][bq * 4 + 1][bcol] = pW.y;
            Bs[buf ^ 1][bq * 4 + 2][bcol] = pW.z;
            Bs[buf ^ 1][bq * 4 + 3][bcol] = pW.w;
        }
    }

    const int col = n0 + 4 * cx;
    float bb0 = b1[col + 0], bb1 = b1[col + 1], bb2 = b1[col + 2], bb3 = b1[col + 3];
    if (b2) { bb0 += b2[col + 0]; bb1 += b2[col + 1]; bb2 += b2[col + 2]; bb3 += b2[col + 3]; }
#pragma unroll
    for (int i = 0; i < 8; i++) {
        int row = m0 + ry + 16 * i;
        float2 p01 = unpack2(acc01[i]);
        float2 p23 = unpack2(acc23[i]);
        float4 v;
        v.x = p01.x + bb0; v.y = p01.y + bb1; v.z = p23.x + bb2; v.w = p23.y + bb3;
        if (relu) { v.x = fmaxf(v.x, 0.f); v.y = fmaxf(v.y, 0.f); v.z = fmaxf(v.z, 0.f); v.w = fmaxf(v.w, 0.f); }
        *(float4*)&C[(size_t)row * N + col] = v;
    }
}

// ---------------- FC2: out[256,8] = z @ W_fc2^T + b ------------------------
__global__ void fc2_kernel(const float* __restrict__ z,
                           const float* __restrict__ W,
                           const float* __restrict__ b,
                           float* __restrict__ out)
{
    int row = blockIdx.x;
    int o = threadIdx.y;
    int lane = threadIdx.x;
    float s = 0.f;
    const float* zr = z + (size_t)row * FCn;
    const float* wr = W + (size_t)o * FCn;
    for (int k = lane; k < FCn; k += 32) s += zr[k] * wr[k];
#pragma unroll
    for (int off = 16; off; off >>= 1) s += __shfl_down_sync(0xffffffffu, s, off);
    if (lane == 0) out[row * OUTn + o] = s + b[o];
}

// ---------------- host orchestration ---------------------------------------
extern "C" void kernel_launch(void* const* d_in, const int* in_sizes, int n_in,
                              void* d_out, int out_size)
{
    const float* x      = (const float*)d_in[0];
    const float* W_ih0  = (const float*)d_in[1];
    const float* W_hh0  = (const float*)d_in[2];
    const float* b_ih0  = (const float*)d_in[3];
    const float* b_hh0  = (const float*)d_in[4];
    const float* W_ih1  = (const float*)d_in[5];
    const float* W_hh1  = (const float*)d_in[6];
    const float* b_ih1  = (const float*)d_in[7];
    const float* b_hh1  = (const float*)d_in[8];
    const float* W_fc1  = (const float*)d_in[9];
    const float* b_fc1  = (const float*)d_in[10];
    const float* W_fc2  = (const float*)d_in[11];
    const float* b_fc2  = (const float*)d_in[12];
    float* out = (float*)d_out;

    float *xg, *hfin, *z;
    __half *h0h, *hX, *hY, *whhHi;
    uint4 *wb0h, *wb1h;
    cudaGetSymbolAddress((void**)&xg,    g_xg);
    cudaGetSymbolAddress((void**)&h0h,   g_h0h);
    cudaGetSymbolAddress((void**)&hfin,  g_hfin);
    cudaGetSymbolAddress((void**)&z,     g_z);
    cudaGetSymbolAddress((void**)&hX,    g_hX);
    cudaGetSymbolAddress((void**)&hY,    g_hY);
    cudaGetSymbolAddress((void**)&whhHi, g_Whh_hi);
    cudaGetSymbolAddress((void**)&wb0h,  g_Wb0hi);
    cudaGetSymbolAddress((void**)&wb1h,  g_Wb1hi);

    cudaFuncSetAttribute(mma_gemm_kernel, cudaFuncAttributeMaxDynamicSharedMemorySize, MMAG_SMEM);
    cudaFuncSetAttribute(lstm_layer_mma,  cudaFuncAttributeMaxDynamicSharedMemorySize, STEP_SMEM);

    const int MT = Bn * Tn;                 // 131072
    dim3 mmaGrid(G4H / 64, MT / 128);       // (32, 1024)
    dim3 stepGrid(16, MGRPS);               // (16, 8) = 128 blocks

    const size_t WHL = (size_t)G4H * Hn;    // per-layer whh elements
    prepack_whh<<<(G4H * Hn) / 256, 256>>>(W_hh0, whhHi);
    prepack_whh<<<(G4H * Hn) / 256, 256>>>(W_hh1, whhHi + WHL);
    prepack_b_kernel<<<(G4H * Dn) / 256, 256>>>(W_ih0, (__half*)wb0h, Dn);
    prepack_b_kernel<<<(G4H * Hn) / 256, 256>>>(W_ih1, (__half*)wb1h, Hn);

    // ---- Layer 0 ----  xg = x @ W_ih0^T + b_ih0 + b_hh0 (K=64, A fp32)
    mma_gemm_kernel<<<mmaGrid, 256, MMAG_SMEM>>>(x, wb0h, b_ih0, b_hh0, xg, Dn, G4H, 0);
    lstm_layer_mma<<<stepGrid, 256, STEP_SMEM>>>(xg, (const uint4*)whhHi,
                                                 hX, hY, h0h, (float*)0);

    // ---- Layer 1 ----  xg = h0 @ W_ih1^T + b_ih1 + b_hh1 (K=512, A fp16)
    mma_gemm_kernel<<<mmaGrid, 256, MMAG_SMEM>>>(h0h, wb1h, b_ih1, b_hh1, xg, Hn, G4H, 1);
    lstm_layer_mma<<<stepGrid, 256, STEP_SMEM>>>(xg, (const uint4*)(whhHi + WHL),
                                                 hX, hY, (__half*)0, hfin);

    // ---- FC head ----
    dim3 fc1Grid(FCn / 64, Bn / 128);       // (8, 2)
    gemm_bias_kernel<<<fc1Grid, 256>>>(hfin, W_fc1, b_fc1, (const float*)0, z, Bn, FCn, Hn, 1);
    fc2_kernel<<<Bn, dim3(32, 8)>>>(z, W_fc2, b_fc2, out);
}

// round 13
// speedup vs baseline: 7.4485x; 1.0836x over previous
#include <cuda_runtime.h>
#include <cuda_fp16.h>
#include <cstddef>
#include <cstdint>

// Problem constants
#define Bn   256
#define Tn   512
#define Dn   64
#define Hn   512
#define G4H  2048   // 4*H
#define FCn  512
#define OUTn 8

#define GKC   16          // k-chunk in fp32 gemm kernel
#define MGRPS 8           // m-groups (Bn/32)
#define GRP_BLOCKS 16     // blocks per m-group (2048 cols / 128)

typedef unsigned long long ull;

#define SWZ128(off) ((off) ^ (((off) >> 3) & 0x70))

// ---------------- scratch (device globals; no runtime allocation) ----------
// xg in fp16, gate-interleaved layout: xg[m, t, u*4 + g]
__device__ __half g_xg[(size_t)Bn * Tn * G4H];
__device__ __half g_h0h[(size_t)Bn * Tn * Hn];     // layer-0 h, fp16 (feeds layer-1 GEMM)
__device__ float g_hfin[Bn * Hn];
__device__ float g_z[Bn * FCn];
// fp16 h state double buffers
__device__ __half g_hX[Bn * Hn], g_hY[Bn * Hn];
// prepacked recurrent weights, fp16, [layer][u_tile(16)][chunk(8)][128n x 64k swizzled]
// n within tile = unit_local*4 + gate  (gate-interleaved)
__device__ __half g_Whh_hi[2][(size_t)G4H * Hn];
// fp16 pre-swizzled W_ih for mma gemm (gate-interleaved n)
__device__ uint4 g_Wb0hi[G4H * Dn / 8];            // layer0: 2048x64
__device__ uint4 g_Wb1hi[G4H * Hn / 8];            // layer1: 2048x512

// producer-progress flags (one per m-group, padded to 128B)
__device__ unsigned g_hflag[MGRPS * 32];

// ---------------- f32x2 packed helpers (fp32 FC1 gemm) ----------------------
__device__ __forceinline__ void ffma2(ull& d, ull a, ull b) {
    asm("fma.rn.f32x2 %0, %1, %2, %0;" : "+l"(d) : "l"(a), "l"(b));
}
__device__ __forceinline__ ull pack2dup(float x) {
    ull r; asm("mov.b64 %0, {%1, %1};" : "=l"(r) : "f"(x)); return r;
}
__device__ __forceinline__ float2 unpack2(ull v) {
    float2 f; asm("mov.b64 {%0, %1}, %2;" : "=f"(f.x), "=f"(f.y) : "l"(v)); return f;
}

// ---------------- fast activations ------------------------------------------
__device__ __forceinline__ float fsig(float x) {
    return __fdividef(1.f, 1.f + __expf(-x));
}
__device__ __forceinline__ float ftanh(float x) {
    return 1.f - __fdividef(2.f, 1.f + __expf(2.f * x));
}

// ---------------- cp.async helpers -----------------------------------------
__device__ __forceinline__ void cp_async16(void* smem_dst, const void* gmem_src) {
    unsigned saddr = (unsigned)__cvta_generic_to_shared(smem_dst);
    asm volatile("cp.async.cg.shared.global [%0], [%1], 16;" :: "r"(saddr), "l"(gmem_src));
}
__device__ __forceinline__ void cp_async16u(unsigned saddr, const void* gmem_src) {
    asm volatile("cp.async.cg.shared.global [%0], [%1], 16;" :: "r"(saddr), "l"(gmem_src));
}
__device__ __forceinline__ void cp_commit() { asm volatile("cp.async.commit_group;"); }
__device__ __forceinline__ void cp_wait0()  { asm volatile("cp.async.wait_group 0;" ::: "memory"); }
__device__ __forceinline__ void cp_wait1()  { asm volatile("cp.async.wait_group 1;" ::: "memory"); }
__device__ __forceinline__ void cp_wait2()  { asm volatile("cp.async.wait_group 2;" ::: "memory"); }
__device__ __forceinline__ void cp_wait3()  { asm volatile("cp.async.wait_group 3;" ::: "memory"); }

__device__ __forceinline__ unsigned smem_u32(const void* p) {
    return (unsigned)__cvta_generic_to_shared(p);
}
__device__ __forceinline__ uint32_t cvt_f16x2(float hi, float lo) {
    uint32_t r; asm("cvt.rn.f16x2.f32 %0, %1, %2;" : "=r"(r) : "f"(hi), "f"(lo)); return r;
}

// ---------------- release/acquire flag helpers ------------------------------
__device__ __forceinline__ unsigned ld_acq(const unsigned* p) {
    unsigned v;
    asm volatile("ld.acquire.gpu.global.u32 %0, [%1];" : "=r"(v) : "l"(p));
    return v;
}
__device__ __forceinline__ void red_rel_add(unsigned* p, unsigned v) {
    asm volatile("red.release.gpu.global.add.u32 [%0], %1;" :: "l"(p), "r"(v));
}

// ---------------- warp-level mma helpers ------------------------------------
__device__ __forceinline__ void ldsm_x4(uint32_t& r0, uint32_t& r1, uint32_t& r2, uint32_t& r3,
                                        uint32_t addr) {
    asm volatile("ldmatrix.sync.aligned.m8n8.x4.shared.b16 {%0,%1,%2,%3}, [%4];"
                 : "=r"(r0), "=r"(r1), "=r"(r2), "=r"(r3) : "r"(addr));
}
__device__ __forceinline__ void mma_f16(float* d, const uint32_t* a, const uint32_t* b) {
    asm volatile("mma.sync.aligned.m16n8k16.row.col.f32.f16.f16.f32 "
                 "{%0,%1,%2,%3}, {%4,%5,%6,%7}, {%8,%9}, {%0,%1,%2,%3};"
                 : "+f"(d[0]), "+f"(d[1]), "+f"(d[2]), "+f"(d[3])
                 : "r"(a[0]), "r"(a[1]), "r"(a[2]), "r"(a[3]), "r"(b[0]), "r"(b[1]));
}

// ---------------- legacy full group barrier (used once per layer, at end) ---
struct __align__(128) BarSlot { unsigned count; unsigned gen; unsigned pad[30]; };
__device__ BarSlot g_bar[MGRPS];

__device__ __forceinline__ void group_barrier(int grp) {
    __syncthreads();
    __threadfence();
    if (threadIdx.x == 0) {
        unsigned gen = atomicAdd(&g_bar[grp].gen, 0u);
        unsigned arrived = atomicAdd(&g_bar[grp].count, 1u);
        if (arrived == GRP_BLOCKS - 1u) {
            atomicExch(&g_bar[grp].count, 0u);
            __threadfence();
            atomicExch(&g_bar[grp].gen, gen + 1u);
        } else {
            while (atomicAdd(&g_bar[grp].gen, 0u) == gen) { __nanosleep(20); }
        }
    }
    __syncthreads();
}

// ---------------- weight pre-pack kernels -----------------------------------
// Whh [4H, H] -> per u-tile (32 units x 4 gates = 128 n-cols, n = un*4+gate)
// x 8 k-chunks, each chunk a 128n x 64k fp16 tile, SW128 swizzled.
__global__ void prepack_whh(const float* __restrict__ Whh,
                            __half* __restrict__ hi)
{
    int i = blockIdx.x * blockDim.x + threadIdx.x;   // 0 .. 2048*512-1
    int k = i & 511;
    int row = i >> 9;                                 // gate*512 + unit_global
    int gate = row >> 9;
    int ug = row & 511;
    int bu = ug >> 5, un = ug & 31;
    int n = un * 4 + gate;                            // gate-interleaved
    int c = k >> 6, lk = k & 63;
    size_t off = ((size_t)(bu * 8 + c)) * 8192 + (SWZ128(n * 128 + lk * 2) >> 1);
    hi[off] = __float2half(Whh[(size_t)row * Hn + k]);
}

// W (2048 x K) -> fp16, per (ntile, kchunk) 64x64 tile, SW128.
// n' = u*4 + gate (gate-interleaved output columns).
__global__ void prepack_b_kernel(const float* __restrict__ W,
                                 __half* __restrict__ hi,
                                 int K)
{
    int i = blockIdx.x * blockDim.x + threadIdx.x;
    int k = i % K;
    int n_orig = i / K;                               // gate*512 + u
    int np = (n_orig & 511) * 4 + (n_orig >> 9);
    int ntile = np >> 6, ln = np & 63;
    int kc = k >> 6, lk = k & 63;
    int nch = K >> 6;
    size_t off = ((size_t)(ntile * nch + kc)) * 4096 + (SWZ128(ln * 128 + lk * 2) >> 1);
    hi[off] = __float2half(W[(size_t)n_orig * K + k]);
}

// inverse column permutation: n' -> orig row index in bias arrays
__device__ __forceinline__ int borig(int np) { return (np & 3) * 512 + (np >> 2); }

// ---------------- HMMA fp16 GEMM: C(half) = A @ W^T + b1 (+b2) -------------
#define MMAG_SMEM (24576 + 1024)
__global__ void __launch_bounds__(256, 2)
mma_gemm_kernel(const void* __restrict__ Avoid,
                const uint4* __restrict__ Wbhi,
                const float* __restrict__ b1,
                const float* __restrict__ b2,
                __half* __restrict__ C,
                int K, int Ntot, int a_f16)
{
    extern __shared__ char dsm[];
    uint32_t usm = smem_u32(dsm);
    usm = (usm + 1023u) & ~1023u;
    const uint32_t uAhi = usm;              // 128 x 64 fp16 = 16KB
    const uint32_t uBhi = usm + 16384;      // 8KB

    const int bn = blockIdx.x;
    const int m0 = blockIdx.y * 128;
    const int n0 = bn * 64;
    const int tid = threadIdx.x;
    const int w = tid >> 5;
    const int lane = tid & 31;
    const int mw = (w & 3) * 32;
    const int nw = (w >> 2) * 32;
    const int nch = K >> 6;

    const uint32_t xorv  = (uint32_t)(lane & 7) << 4;
    const uint32_t aRow  = mw + (lane & 15);
    const uint32_t aKsel = (uint32_t)(lane >> 4) << 4;
    const uint32_t bRow  = nw + (lane & 7) + ((lane >> 4) << 3);
    const uint32_t bKsel = (uint32_t)((lane >> 3) & 1) << 4;

    float acc[2][4][4];
#pragma unroll
    for (int mt = 0; mt < 2; mt++)
#pragma unroll
        for (int nt = 0; nt < 4; nt++)
#pragma unroll
            for (int e = 0; e < 4; e++) acc[mt][nt][e] = 0.f;

    for (int c = 0; c < nch; c++) {
        if (c) __syncthreads();

        const uint4* sbh = Wbhi + ((size_t)bn * nch + c) * 512;
        cp_async16u(uBhi + (uint32_t)tid * 16,         sbh + tid);
        cp_async16u(uBhi + (uint32_t)(tid + 256) * 16, sbh + tid + 256);

        if (a_f16) {
            const uint4* Af = (const uint4*)Avoid;
            const int krow = K >> 3;
#pragma unroll
            for (int j = 0; j < 4; j++) {
                int idx = tid + j * 256;
                int r = idx >> 3, q = idx & 7;
                cp_async16u(uAhi + SWZ128((uint32_t)r * 128 + (uint32_t)q * 16),
                            Af + (size_t)(m0 + r) * krow + c * 8 + q);
            }
            cp_commit();
            cp_wait0();
            __syncthreads();
        } else {
            cp_commit();
            const float* A = (const float*)Avoid;
            const int k0 = c * 64;
#pragma unroll
            for (int it = 0; it < 8; it++) {
                int idx = tid + it * 256;
                int r = idx >> 4, f4 = idx & 15;
                float4 v = *(const float4*)(A + (size_t)(m0 + r) * K + k0 + f4 * 4);
                uint32_t h01 = cvt_f16x2(v.y, v.x);
                uint32_t h23 = cvt_f16x2(v.w, v.z);
                uint32_t sw = (uint32_t)r * 128 + (((uint32_t)f4 * 8) ^ (((uint32_t)r & 7) << 4));
                asm volatile("st.shared.v2.u32 [%0], {%1,%2};" :: "r"(uAhi + sw), "r"(h01), "r"(h23));
            }
            cp_wait0();
            __syncthreads();
        }

#pragma unroll
        for (int ks = 0; ks < 4; ks++) {
            const uint32_t kbA = ((uint32_t)(32 * ks) + aKsel) ^ xorv;
            const uint32_t kbB = ((uint32_t)(32 * ks) + bKsel) ^ xorv;
            uint32_t ah0[4], ah1[4];
            ldsm_x4(ah0[0], ah0[1], ah0[2], ah0[3], uAhi + aRow * 128 + kbA);
            ldsm_x4(ah1[0], ah1[1], ah1[2], ah1[3], uAhi + (aRow + 16) * 128 + kbA);
            uint32_t bh[8];
            ldsm_x4(bh[0], bh[1], bh[2], bh[3], uBhi + bRow * 128 + kbB);
            ldsm_x4(bh[4], bh[5], bh[6], bh[7], uBhi + (bRow + 16) * 128 + kbB);
#pragma unroll
            for (int mt = 0; mt < 2; mt++) {
                const uint32_t* Ah = mt ? ah1 : ah0;
#pragma unroll
                for (int nt = 0; nt < 4; nt++)
                    mma_f16(acc[mt][nt], Ah, bh + nt * 2);
            }
        }
    }

    const int gid = lane >> 2, tig = lane & 3;
    float2 bias[4];
#pragma unroll
    for (int nt = 0; nt < 4; nt++) {
        int col = n0 + nw + nt * 8 + tig * 2;
        int o0 = borig(col), o1 = borig(col + 1);
        bias[nt].x = b1[o0] + (b2 ? b2[o0] : 0.f);
        bias[nt].y = b1[o1] + (b2 ? b2[o1] : 0.f);
    }
#pragma unroll
    for (int mt = 0; mt < 2; mt++) {
        int row0 = m0 + mw + mt * 16 + gid;
#pragma unroll
        for (int nt = 0; nt < 4; nt++) {
            int col = n0 + nw + nt * 8 + tig * 2;
            uint32_t v0 = cvt_f16x2(acc[mt][nt][1] + bias[nt].y, acc[mt][nt][0] + bias[nt].x);
            uint32_t v1 = cvt_f16x2(acc[mt][nt][3] + bias[nt].y, acc[mt][nt][2] + bias[nt].x);
            *(uint32_t*)&C[(size_t)row0 * Ntot + col]       = v0;
            *(uint32_t*)&C[(size_t)(row0 + 8) * Ntot + col] = v1;
        }
    }
}

// ---------------- persistent HMMA fp16 LSTM layer kernel --------------------
// Grid (16, 8): block = 32 units x 4 gates (128 gate-interleaved n-cols)
// x 32 batch rows. W fp16 resident in smem (128KB). h fp16 staged per step
// (32KB, 4 commit groups of 2 chunks).
// Sync: per-warp release flag (threshold 128*t); per-warp acquire poll.
// Epilogue: gate exchange via one shfl.xor(1) pair — no smem round trip.
#define STEP_SMEM (131072 + 32768 + 1024)
__global__ void __launch_bounds__(256)
lstm_layer_mma(const __half* __restrict__ xg,       // [B, T, 4H] gate-interleaved
               const uint4* __restrict__ Whi,       // prepacked, this layer
               __half* __restrict__ hX, __half* __restrict__ hY,
               __half* __restrict__ h_all,          // layer0: [B,T,H] fp16; else null
               float* __restrict__ h_final)         // layer1: [B,H]; else null
{
    extern __shared__ char dsm[];
    uint32_t usm = smem_u32(dsm);
    usm = (usm + 1023u) & ~1023u;
    const uint32_t uWhi = usm;                      // 8 chunks x 16KB = 128KB
    const uint32_t uH   = usm + 131072;             // 8 chunks x 4KB = 32KB

    const int bu  = blockIdx.x;                     // u-tile 0..15
    const int grp = blockIdx.y;                     // m-group 0..7
    const int m0  = grp * 32;
    const int tid = threadIdx.x;
    const int w   = tid >> 5;
    const int lane = tid & 31;
    const int mw = (w & 1) * 16;                    // 16 rows per warp (of 32)
    const int nw = (w >> 1) * 32;                   // 32 cols per warp (of 128)

    const uint32_t xorv  = (uint32_t)(lane & 7) << 4;
    const uint32_t aRow  = mw + (lane & 15);
    const uint32_t aKsel = (uint32_t)(lane >> 4) << 4;
    const uint32_t bRow  = nw + (lane & 7) + ((lane >> 4) << 3);
    const uint32_t bKsel = (uint32_t)((lane >> 3) & 1) << 4;
    const int gid = lane >> 2, tig = lane & 3;
    const bool oddt = (tig & 1);

    unsigned* flag = &g_hflag[grp * 32];

    // ---- load resident weights (once): 128KB = 8192 uint4 ----
    {
        const uint4* sh = Whi + (size_t)bu * 8192;
#pragma unroll
        for (int j = 0; j < 32; j++) {
            int idx = tid + j * 256;
            cp_async16u(uWhi + (uint32_t)idx * 16, sh + idx);
        }
        cp_commit();
        cp_wait0();
        __syncthreads();
    }

    // ---- per-thread cell mapping (from MMA fragment + shfl exchange) ----
    // cell row = m0 + mw + gid + 8*(tig&1); unit(nt) = bu*32 + (w>>1)*8 + (tig>>1) + nt*2
    const int crow  = m0 + mw + gid + 8 * (tig & 1);
    const int ubase = bu * 32 + (w >> 1) * 8 + (tig >> 1);

    float creg[4] = {0.f, 0.f, 0.f, 0.f};
    float xvf[4][4];                                 // [nt][gate]
    {
        const __half* xr = xg + ((size_t)crow * Tn + 0) * G4H;
#pragma unroll
        for (int nt = 0; nt < 4; nt++) {
            uint2 p = __ldcg((const uint2*)(xr + (size_t)(ubase + nt * 2) * 4));
            float2 a = __half22float2(*(__half2*)&p.x);
            float2 b = __half22float2(*(__half2*)&p.y);
            xvf[nt][0] = a.x; xvf[nt][1] = a.y; xvf[nt][2] = b.x; xvf[nt][3] = b.y;
        }
    }

    // h staging per chunk: 32 rows x 64 k fp16 = 4KB = 256 cp.async = 1/thread
    const int s_r = tid >> 3, s_q = tid & 7;

    for (int t = 0; t < Tn; t++) {
        const __half* hin = (t & 1) ? hX : hY;
        __half* hout      = (t & 1) ? hY : hX;

        float g4[4][4];                              // [nt][gate], recurrent part
#pragma unroll
        for (int nt = 0; nt < 4; nt++)
#pragma unroll
            for (int g = 0; g < 4; g++) g4[nt][g] = 0.f;

        if (t > 0) {
            // per-warp poll: all 128 producer-warps of this group published h_{t-1}
            if (lane == 0) {
                while (ld_acq(flag) < 128u * (unsigned)t) { }
            }
            __syncwarp();

            // stage 8 chunks in 4 commit groups of 2
#pragma unroll
            for (int g2 = 0; g2 < 4; g2++) {
#pragma unroll
                for (int cc = 0; cc < 2; cc++) {
                    int c = g2 * 2 + cc;
                    cp_async16u(uH + (uint32_t)c * 4096 +
                                SWZ128((uint32_t)s_r * 128 + (uint32_t)s_q * 16),
                                hin + (size_t)(m0 + s_r) * Hn + c * 64 + s_q * 8);
                }
                cp_commit();
            }

            float acc[4][4];
#pragma unroll
            for (int nt = 0; nt < 4; nt++)
#pragma unroll
                for (int e = 0; e < 4; e++) acc[nt][e] = 0.f;

#pragma unroll
            for (int c = 0; c < 8; c++) {
                if (c == 0) { cp_wait3(); __syncthreads(); }
                else if (c == 2) { cp_wait2(); __syncthreads(); }
                else if (c == 4) { cp_wait1(); __syncthreads(); }
                else if (c == 6) { cp_wait0(); __syncthreads(); }
                const uint32_t uA = uH + (uint32_t)c * 4096;
                const uint32_t wh = uWhi + (uint32_t)c * 16384;
#pragma unroll
                for (int ks = 0; ks < 4; ks++) {
                    const uint32_t kbA = ((uint32_t)(32 * ks) + aKsel) ^ xorv;
                    const uint32_t kbB = ((uint32_t)(32 * ks) + bKsel) ^ xorv;
                    uint32_t a0[4], bh[8];
                    ldsm_x4(a0[0], a0[1], a0[2], a0[3], uA + aRow * 128 + kbA);
                    ldsm_x4(bh[0], bh[1], bh[2], bh[3], wh + bRow * 128 + kbB);
                    ldsm_x4(bh[4], bh[5], bh[6], bh[7], wh + (bRow + 16) * 128 + kbB);
#pragma unroll
                    for (int nt = 0; nt < 4; nt++)
                        mma_f16(acc[nt], a0, bh + nt * 2);
                }
            }

            // gate exchange: pair (tig, tig^1) swaps so each thread gets all
            // 4 gates of one (row, unit) per nt.
#pragma unroll
            for (int nt = 0; nt < 4; nt++) {
                float s0 = __shfl_xor_sync(0xffffffffu, oddt ? acc[nt][0] : acc[nt][2], 1);
                float s1 = __shfl_xor_sync(0xffffffffu, oddt ? acc[nt][1] : acc[nt][3], 1);
                g4[nt][0] = oddt ? s0 : acc[nt][0];
                g4[nt][1] = oddt ? s1 : acc[nt][1];
                g4[nt][2] = oddt ? acc[nt][2] : s0;
                g4[nt][3] = oddt ? acc[nt][3] : s1;
            }
        }

        // ---- cell update: 4 cells per thread (1 per nt) ----
        float hn4[4];
#pragma unroll
        for (int nt = 0; nt < 4; nt++) {
            float gi = g4[nt][0] + xvf[nt][0];
            float gf = g4[nt][1] + xvf[nt][1];
            float gg = g4[nt][2] + xvf[nt][2];
            float go = g4[nt][3] + xvf[nt][3];
            float cn = fsig(gf) * creg[nt] + fsig(gi) * ftanh(gg);
            creg[nt] = cn;
            hn4[nt] = fsig(go) * ftanh(cn);
        }

        // write h (fp16) then per-warp release ASAP
#pragma unroll
        for (int nt = 0; nt < 4; nt++)
            hout[(size_t)crow * Hn + (ubase + nt * 2)] = __float2half(hn4[nt]);
        if (t < Tn - 1) {
            __syncwarp();
            if (lane == 0) red_rel_add(flag, 1u);
        }

        // off-critical-path: h_all / h_final, xg prefetch for t+1
        if (h_all) {
#pragma unroll
            for (int nt = 0; nt < 4; nt++)
                h_all[((size_t)crow * Tn + t) * Hn + (ubase + nt * 2)] = __float2half(hn4[nt]);
        }
        if (h_final && t == Tn - 1) {
#pragma unroll
            for (int nt = 0; nt < 4; nt++)
                h_final[(size_t)crow * Hn + (ubase + nt * 2)] = hn4[nt];
        }
        if (t < Tn - 1) {
            const __half* xr = xg + ((size_t)crow * Tn + (t + 1)) * G4H;
#pragma unroll
            for (int nt = 0; nt < 4; nt++) {
                uint2 p = __ldcg((const uint2*)(xr + (size_t)(ubase + nt * 2) * 4));
                float2 a = __half22float2(*(__half2*)&p.x);
                float2 b = __half22float2(*(__half2*)&p.y);
                xvf[nt][0] = a.x; xvf[nt][1] = a.y; xvf[nt][2] = b.x; xvf[nt][3] = b.y;
            }
        }
    }

    // ---- end of layer: full barrier once, then reset flags (replay-safe) ----
    group_barrier(grp);
    if (bu == 0 && tid == 0) *flag = 0u;
}

// ---------------- fp32 tiled GEMM (kept for FC1) ----------------------------
__global__ void __launch_bounds__(256, 2)
gemm_bias_kernel(const float* __restrict__ A,
                 const float* __restrict__ W,
                 const float* __restrict__ b1,
                 const float* __restrict__ b2,
                 float* __restrict__ C,
                 int M, int N, int K, int relu)
{
    __shared__ __align__(16) float As[2][128][GKC];
    __shared__ __align__(16) float Bs[2][GKC][64];
    const int m0 = blockIdx.y * 128;
    const int n0 = blockIdx.x * 64;
    const int tid = threadIdx.x;
    const int cx = tid & 15;
    const int ry = tid >> 4;

    ull acc01[8], acc23[8];
#pragma unroll
    for (int i = 0; i < 8; i++) { acc01[i] = 0ull; acc23[i] = 0ull; }

    const int nch = K / GKC;
    const int bcol = tid & 63, bq = tid >> 6;

#pragma unroll
    for (int i = 0; i < 2; i++) {
        int idx = tid + i * 256;
        cp_async16(&As[0][idx >> 2][(idx & 3) * 4],
                   A + (size_t)(m0 + (idx >> 2)) * K + (idx & 3) * 4);
    }
    cp_commit();
    float4 pW = *(const float4*)(W + (size_t)(n0 + bcol) * K + bq * 4);
    Bs[0][bq * 4 + 0][bcol] = pW.x;
    Bs[0][bq * 4 + 1][bcol] = pW.y;
    Bs[0][bq * 4 + 2][bcol] = pW.z;
    Bs[0][bq * 4 + 3][bcol] = pW.w;

    for (int c = 0; c < nch; c++) {
        cp_wait0();
        __syncthreads();
        const int buf = c & 1;
        const bool more = (c + 1 < nch);
        if (more) {
            int k0 = (c + 1) * GKC;
#pragma unroll
            for (int i = 0; i < 2; i++) {
                int idx = tid + i * 256;
                cp_async16(&As[buf ^ 1][idx >> 2][(idx & 3) * 4],
                           A + (size_t)(m0 + (idx >> 2)) * K + k0 + (idx & 3) * 4);
            }
            cp_commit();
            pW = *(const float4*)(W + (size_t)(n0 + bcol) * K + k0 + bq * 4);
        }
#pragma unroll
        for (int k4 = 0; k4 < GKC; k4 += 4) {
            float4 a4[8];
#pragma unroll
            for (int i = 0; i < 8; i++) a4[i] = *(const float4*)&As[buf][ry + 16 * i][k4];
#pragma unroll
            for (int j = 0; j < 4; j++) {
                float4 w4 = *(const float4*)&Bs[buf][k4 + j][4 * cx];
                ull w01 = *reinterpret_cast<ull*>(&w4.x);
                ull w23 = *reinterpret_cast<ull*>(&w4.z);
#pragma unroll
                for (int i = 0; i < 8; i++) {
                    float av = (j == 0) ? a4[i].x : (j == 1) ? a4[i].y : (j == 2) ? a4[i].z : a4[i].w;
                    ull ad = pack2dup(av);
                    ffma2(acc01[i], ad, w01);
                    ffma2(acc23[i], ad, w23);
                }
            }
        }
        if (more) {
            Bs[buf ^ 1][bq * 4 + 0][bcol] = pW.x;
            Bs[buf ^ 1][bq * 4 + 1][bcol] = pW.y;
            Bs[buf ^ 1][bq * 4 + 2][bcol] = pW.z;
            Bs[buf ^ 1][bq * 4 + 3][bcol] = pW.w;
        }
    }

    const int col = n0 + 4 * cx;
    float bb0 = b1[col + 0], bb1 = b1[col + 1], bb2 = b1[col + 2], bb3 = b1[col + 3];
    if (b2) { bb0 += b2[col + 0]; bb1 += b2[col + 1]; bb2 += b2[col + 2]; bb3 += b2[col + 3]; }
#pragma unroll
    for (int i = 0; i < 8; i++) {
        int row = m0 + ry + 16 * i;
        float2 p01 = unpack2(acc01[i]);
        float2 p23 = unpack2(acc23[i]);
        float4 v;
        v.x = p01.x + bb0; v.y = p01.y + bb1; v.z = p23.x + bb2; v.w = p23.y + bb3;
        if (relu) { v.x = fmaxf(v.x, 0.f); v.y = fmaxf(v.y, 0.f); v.z = fmaxf(v.z, 0.f); v.w = fmaxf(v.w, 0.f); }
        *(float4*)&C[(size_t)row * N + col] = v;
    }
}

// ---------------- FC2: out[256,8] = z @ W_fc2^T + b ------------------------
__global__ void fc2_kernel(const float* __restrict__ z,
                           const float* __restrict__ W,
                           const float* __restrict__ b,
                           float* __restrict__ out)
{
    int row = blockIdx.x;
    int o = threadIdx.y;
    int lane = threadIdx.x;
    float s = 0.f;
    const float* zr = z + (size_t)row * FCn;
    const float* wr = W + (size_t)o * FCn;
    for (int k = lane; k < FCn; k += 32) s += zr[k] * wr[k];
#pragma unroll
    for (int off = 16; off; off >>= 1) s += __shfl_down_sync(0xffffffffu, s, off);
    if (lane == 0) out[row * OUTn + o] = s + b[o];
}

// ---------------- host orchestration ---------------------------------------
extern "C" void kernel_launch(void* const* d_in, const int* in_sizes, int n_in,
                              void* d_out, int out_size)
{
    const float* x      = (const float*)d_in[0];
    const float* W_ih0  = (const float*)d_in[1];
    const float* W_hh0  = (const float*)d_in[2];
    const float* b_ih0  = (const float*)d_in[3];
    const float* b_hh0  = (const float*)d_in[4];
    const float* W_ih1  = (const float*)d_in[5];
    const float* W_hh1  = (const float*)d_in[6];
    const float* b_ih1  = (const float*)d_in[7];
    const float* b_hh1  = (const float*)d_in[8];
    const float* W_fc1  = (const float*)d_in[9];
    const float* b_fc1  = (const float*)d_in[10];
    const float* W_fc2  = (const float*)d_in[11];
    const float* b_fc2  = (const float*)d_in[12];
    float* out = (float*)d_out;

    float *hfin, *z;
    __half *xg, *h0h, *hX, *hY, *whhHi;
    uint4 *wb0h, *wb1h;
    cudaGetSymbolAddress((void**)&xg,    g_xg);
    cudaGetSymbolAddress((void**)&h0h,   g_h0h);
    cudaGetSymbolAddress((void**)&hfin,  g_hfin);
    cudaGetSymbolAddress((void**)&z,     g_z);
    cudaGetSymbolAddress((void**)&hX,    g_hX);
    cudaGetSymbolAddress((void**)&hY,    g_hY);
    cudaGetSymbolAddress((void**)&whhHi, g_Whh_hi);
    cudaGetSymbolAddress((void**)&wb0h,  g_Wb0hi);
    cudaGetSymbolAddress((void**)&wb1h,  g_Wb1hi);

    cudaFuncSetAttribute(mma_gemm_kernel, cudaFuncAttributeMaxDynamicSharedMemorySize, MMAG_SMEM);
    cudaFuncSetAttribute(lstm_layer_mma,  cudaFuncAttributeMaxDynamicSharedMemorySize, STEP_SMEM);

    const int MT = Bn * Tn;                 // 131072
    dim3 mmaGrid(G4H / 64, MT / 128);       // (32, 1024)
    dim3 stepGrid(16, MGRPS);               // (16, 8) = 128 blocks

    const size_t WHL = (size_t)G4H * Hn;    // per-layer whh elements
    prepack_whh<<<(G4H * Hn) / 256, 256>>>(W_hh0, whhHi);
    prepack_whh<<<(G4H * Hn) / 256, 256>>>(W_hh1, whhHi + WHL);
    prepack_b_kernel<<<(G4H * Dn) / 256, 256>>>(W_ih0, (__half*)wb0h, Dn);
    prepack_b_kernel<<<(G4H * Hn) / 256, 256>>>(W_ih1, (__half*)wb1h, Hn);

    // ---- Layer 0 ----  xg = x @ W_ih0^T + b_ih0 + b_hh0 (K=64, A fp32)
    mma_gemm_kernel<<<mmaGrid, 256, MMAG_SMEM>>>(x, wb0h, b_ih0, b_hh0, xg, Dn, G4H, 0);
    lstm_layer_mma<<<stepGrid, 256, STEP_SMEM>>>(xg, (const uint4*)whhHi,
                                                 hX, hY, h0h, (float*)0);

    // ---- Layer 1 ----  xg = h0 @ W_ih1^T + b_ih1 + b_hh1 (K=512, A fp16)
    mma_gemm_kernel<<<mmaGrid, 256, MMAG_SMEM>>>(h0h, wb1h, b_ih1, b_hh1, xg, Hn, G4H, 1);
    lstm_layer_mma<<<stepGrid, 256, STEP_SMEM>>>(xg, (const uint4*)(whhHi + WHL),
                                                 hX, hY, (__half*)0, hfin);

    // ---- FC head ----
    dim3 fc1Grid(FCn / 64, Bn / 128);       // (8, 2)
    gemm_bias_kernel<<<fc1Grid, 256>>>(hfin, W_fc1, b_fc1, (const float*)0, z, Bn, FCn, Hn, 1);
    fc2_kernel<<<Bn, dim3(32, 8)>>>(z, W_fc2, b_fc2, out);
}